// round 2
// baseline (speedup 1.0000x reference)
#include <cuda_runtime.h>

#define B_  4
#define T_  2048
#define C_  1024
#define H_  16
#define HD_ 64
#define M_  (B_*T_)   // 8192

// scratch (static __device__ allocation is allowed)
__device__ float g_q[(size_t)B_*H_*T_*HD_];
__device__ float g_k[(size_t)B_*H_*T_*HD_];
__device__ float g_v[(size_t)B_*H_*T_*HD_];
__device__ float g_y[(size_t)B_*T_*C_];

// ---------------------------------------------------------------------------
// GEMM: out = X[M,K] @ W[N,K]^T + bias[N]   (nn.Linear semantics)
// 64x64 tile, BK=16, 256 threads, 4x4 microtile per thread.
// DST: 0 -> g_q, 1 -> g_k, 2 -> g_v  (written in [B,H,T,hd] layout)
//      3 -> out pointer arg          (written in [M,C] row-major)
// ---------------------------------------------------------------------------
template <int DST>
__global__ __launch_bounds__(256) void proj_kernel(
    const float* __restrict__ X, const float* __restrict__ W,
    const float* __restrict__ bias, float* __restrict__ out, int K)
{
    __shared__ float As[16][65];   // As[k][m]
    __shared__ float Bs[16][65];   // Bs[k][n]
    const int tid = threadIdx.x;
    const int bm = blockIdx.y * 64;
    const int bn = blockIdx.x * 64;
    const int tx = tid & 15, ty = tid >> 4;
    const int lr = tid >> 2;           // 0..63 tile row
    const int lc = (tid & 3) * 4;      // k offset 0,4,8,12

    const float* Ag = X + (size_t)(bm + lr) * K + lc;
    const float* Bg = W + (size_t)(bn + lr) * K + lc;

    float acc[4][4] = {};

    for (int k0 = 0; k0 < K; k0 += 16) {
        float4 a4 = *(const float4*)(Ag + k0);
        float4 b4 = *(const float4*)(Bg + k0);
        __syncthreads();
        As[lc+0][lr]=a4.x; As[lc+1][lr]=a4.y; As[lc+2][lr]=a4.z; As[lc+3][lr]=a4.w;
        Bs[lc+0][lr]=b4.x; Bs[lc+1][lr]=b4.y; Bs[lc+2][lr]=b4.z; Bs[lc+3][lr]=b4.w;
        __syncthreads();
        #pragma unroll
        for (int k = 0; k < 16; ++k) {
            float a[4], b[4];
            #pragma unroll
            for (int i = 0; i < 4; ++i) a[i] = As[k][ty*4+i];
            #pragma unroll
            for (int j = 0; j < 4; ++j) b[j] = Bs[k][tx*4+j];
            #pragma unroll
            for (int i = 0; i < 4; ++i)
                #pragma unroll
                for (int j = 0; j < 4; ++j)
                    acc[i][j] = fmaf(a[i], b[j], acc[i][j]);
        }
    }

    float* dst;
    if      (DST == 0) dst = g_q;
    else if (DST == 1) dst = g_k;
    else if (DST == 2) dst = g_v;
    else               dst = out;

    #pragma unroll
    for (int i = 0; i < 4; ++i) {
        const int row = bm + ty*4 + i;
        #pragma unroll
        for (int j = 0; j < 4; ++j) {
            const int col = bn + tx*4 + j;
            const float val = acc[i][j] + bias[col];
            if (DST < 3) {
                const int b = row >> 11, t = row & 2047;   // T=2048
                const int h = col >> 6,  d = col & 63;     // hd=64
                dst[(((size_t)(b*H_ + h))*T_ + t)*HD_ + d] = val;
            } else {
                dst[(size_t)row*C_ + col] = val;
            }
        }
    }
}

// ---------------------------------------------------------------------------
// Causal flash attention, fp32. One block = 64 query rows of one (b,h).
// 256 threads: thread owns rows {2rp, 2rp+1} x cols [8cs, 8cs+8).
// smem: Qs[64][65], Ks[64][65] (reused as Ps), Vs[64][65] -> 49,920 B dynamic.
// ---------------------------------------------------------------------------
__global__ __launch_bounds__(256) void attn_kernel()
{
    extern __shared__ float sm[];
    float (*Qs)[65] = (float(*)[65])(sm);
    float (*Ks)[65] = (float(*)[65])(sm + 64*65);
    float (*Vs)[65] = (float(*)[65])(sm + 2*64*65);
    float (*Ps)[65] = Ks;   // reuse: K dead after S is computed

    const int tid   = threadIdx.x;
    const int qtile = blockIdx.x;        // 0..31
    const int bh    = blockIdx.y;        // 0..63  (= b*H + h)
    const int qbase = qtile * 64;

    const float* Qg = g_q + (size_t)bh * T_ * HD_;
    const float* Kg = g_k + (size_t)bh * T_ * HD_;
    const float* Vg = g_v + (size_t)bh * T_ * HD_;

    // load Q tile (64 x 64), float4 coalesced
    #pragma unroll
    for (int it = 0; it < 4; ++it) {
        const int idx = tid + it*256;
        const int row = idx >> 4;
        const int c4  = (idx & 15) * 4;
        float4 q4 = *(const float4*)(Qg + (size_t)(qbase+row)*HD_ + c4);
        Qs[row][c4+0]=q4.x; Qs[row][c4+1]=q4.y; Qs[row][c4+2]=q4.z; Qs[row][c4+3]=q4.w;
    }

    const int rp = tid >> 3;       // 0..31
    const int cs = tid & 7;        // 0..7
    const int r0 = rp*2, r1 = r0 + 1;
    const int cb = cs*8;

    float m0 = -1e30f, m1 = -1e30f, l0 = 0.f, l1 = 0.f;
    float acc0[8] = {}, acc1[8] = {};
    const float scale = 0.125f;    // 1/sqrt(64)

    for (int jt = 0; jt <= qtile; ++jt) {
        const int jbase = jt * 64;
        __syncthreads();   // prev iteration done with Ks(=Ps)/Vs

        #pragma unroll
        for (int it = 0; it < 4; ++it) {
            const int idx = tid + it*256;
            const int row = idx >> 4;
            const int c4  = (idx & 15) * 4;
            float4 k4 = *(const float4*)(Kg + (size_t)(jbase+row)*HD_ + c4);
            Ks[row][c4+0]=k4.x; Ks[row][c4+1]=k4.y; Ks[row][c4+2]=k4.z; Ks[row][c4+3]=k4.w;
            float4 v4 = *(const float4*)(Vg + (size_t)(jbase+row)*HD_ + c4);
            Vs[row][c4+0]=v4.x; Vs[row][c4+1]=v4.y; Vs[row][c4+2]=v4.z; Vs[row][c4+3]=v4.w;
        }
        __syncthreads();

        // S = Q K^T
        float s0[8] = {}, s1[8] = {};
        #pragma unroll 4
        for (int k = 0; k < 64; ++k) {
            const float qa = Qs[r0][k];
            const float qb = Qs[r1][k];
            #pragma unroll
            for (int c = 0; c < 8; ++c) {
                const float kv = Ks[cb+c][k];
                s0[c] = fmaf(qa, kv, s0[c]);
                s1[c] = fmaf(qb, kv, s1[c]);
            }
        }

        const bool diag = (jt == qtile);
        #pragma unroll
        for (int c = 0; c < 8; ++c) {
            s0[c] *= scale; s1[c] *= scale;
            if (diag) {
                if (cb + c > r0) s0[c] = -1e30f;
                if (cb + c > r1) s1[c] = -1e30f;
            }
        }

        // row max (8 lanes per row, lane groups aligned -> xor shuffles)
        float rm0 = s0[0], rm1 = s1[0];
        #pragma unroll
        for (int c = 1; c < 8; ++c) { rm0 = fmaxf(rm0, s0[c]); rm1 = fmaxf(rm1, s1[c]); }
        #pragma unroll
        for (int off = 1; off < 8; off <<= 1) {
            rm0 = fmaxf(rm0, __shfl_xor_sync(0xffffffffu, rm0, off));
            rm1 = fmaxf(rm1, __shfl_xor_sync(0xffffffffu, rm1, off));
        }

        const float mn0 = fmaxf(m0, rm0), mn1 = fmaxf(m1, rm1);
        const float al0 = __expf(m0 - mn0), al1 = __expf(m1 - mn1);
        float rs0 = 0.f, rs1 = 0.f;
        #pragma unroll
        for (int c = 0; c < 8; ++c) {
            s0[c] = __expf(s0[c] - mn0); rs0 += s0[c];
            s1[c] = __expf(s1[c] - mn1); rs1 += s1[c];
        }
        #pragma unroll
        for (int off = 1; off < 8; off <<= 1) {
            rs0 += __shfl_xor_sync(0xffffffffu, rs0, off);
            rs1 += __shfl_xor_sync(0xffffffffu, rs1, off);
        }
        l0 = al0*l0 + rs0;  l1 = al1*l1 + rs1;
        m0 = mn0;  m1 = mn1;
        #pragma unroll
        for (int d = 0; d < 8; ++d) { acc0[d] *= al0; acc1[d] *= al1; }

        __syncthreads();   // all threads done reading Ks before overwriting as Ps
        #pragma unroll
        for (int c = 0; c < 8; ++c) { Ps[r0][cb+c] = s0[c]; Ps[r1][cb+c] = s1[c]; }
        __syncthreads();

        // O += P V
        #pragma unroll 4
        for (int c = 0; c < 64; ++c) {
            const float p0 = Ps[r0][c];
            const float p1 = Ps[r1][c];
            #pragma unroll
            for (int d = 0; d < 8; ++d) {
                const float vv = Vs[c][cb+d];
                acc0[d] = fmaf(p0, vv, acc0[d]);
                acc1[d] = fmaf(p1, vv, acc1[d]);
            }
        }
    }

    // epilogue: y[b, t, h*64 + d] = O / l
    const int b = bh >> 4, h = bh & 15;
    const float inv0 = 1.f / l0, inv1 = 1.f / l1;
    const size_t base0 = ((size_t)(b*T_ + qbase + r0))*C_ + h*HD_ + cb;
    const size_t base1 = ((size_t)(b*T_ + qbase + r1))*C_ + h*HD_ + cb;
    #pragma unroll
    for (int d = 0; d < 8; ++d) {
        g_y[base0 + d] = acc0[d] * inv0;
        g_y[base1 + d] = acc1[d] * inv1;
    }
}

// ---------------------------------------------------------------------------
extern "C" void kernel_launch(void* const* d_in, const int* in_sizes, int n_in,
                              void* d_out, int out_size)
{
    const float* query = (const float*)d_in[0];
    const float* Wq = (const float*)d_in[1];  const float* bq = (const float*)d_in[2];
    const float* Wk = (const float*)d_in[3];  const float* bk = (const float*)d_in[4];
    const float* Wv = (const float*)d_in[5];  const float* bv = (const float*)d_in[6];
    const float* Wp = (const float*)d_in[7];  const float* bp = (const float*)d_in[8];

    const dim3 gg(C_/64, M_/64);   // (16, 128)

    proj_kernel<0><<<gg, 256>>>(query, Wq, bq, nullptr, C_);
    proj_kernel<1><<<gg, 256>>>(query, Wk, bk, nullptr, C_);
    proj_kernel<2><<<gg, 256>>>(query, Wv, bv, nullptr, C_);

    const int attn_smem = 3*64*65*sizeof(float);   // 49,920 B
    cudaFuncSetAttribute(attn_kernel, cudaFuncAttributeMaxDynamicSharedMemorySize, attn_smem);
    attn_kernel<<<dim3(T_/64, B_*H_), 256, attn_smem>>>();

    // final projection reads g_y directly (device symbol visible in device code)
    float* yp = nullptr;  // unused for DST<3; g_y referenced via symbol below
    (void)yp;
    // need g_y as input pointer: reference via a tiny helper kernel-free trick is
    // not possible host-side without cudaGetSymbolAddress, so use it here (legal,
    // non-stream API):
    float* y_dev;
    cudaGetSymbolAddress((void**)&y_dev, g_y);
    proj_kernel<3><<<gg, 256>>>(y_dev, Wp, bp, (float*)d_out, C_);
}

// round 6
// speedup vs baseline: 1.4672x; 1.4672x over previous
#include <cuda_runtime.h>
#include <cuda_bf16.h>
#include <cstdint>

#define B_  4
#define T_  2048
#define C_  1024
#define H_  16
#define HD_ 64
#define M_  (B_*T_)   // 8192

// ---------------------------------------------------------------------------
// device scratch
// ---------------------------------------------------------------------------
__device__ float g_q[(size_t)B_*H_*T_*HD_];
__device__ float g_k[(size_t)B_*H_*T_*HD_];
__device__ float g_v[(size_t)B_*H_*T_*HD_];
__device__ float g_y[(size_t)B_*T_*C_];

__device__ __nv_bfloat16 g_xhi[(size_t)M_*C_];
__device__ __nv_bfloat16 g_xlo[(size_t)M_*C_];
__device__ __nv_bfloat16 g_yhi[(size_t)M_*C_];
__device__ __nv_bfloat16 g_ylo[(size_t)M_*C_];
__device__ __nv_bfloat16 g_wqhi[(size_t)C_*C_], g_wqlo[(size_t)C_*C_];
__device__ __nv_bfloat16 g_wkhi[(size_t)C_*C_], g_wklo[(size_t)C_*C_];
__device__ __nv_bfloat16 g_wvhi[(size_t)C_*C_], g_wvlo[(size_t)C_*C_];
__device__ __nv_bfloat16 g_wphi[(size_t)C_*C_], g_wplo[(size_t)C_*C_];

// ---------------------------------------------------------------------------
// helpers
// ---------------------------------------------------------------------------
__device__ __forceinline__ unsigned smem_u32(const void* p) {
    unsigned a;
    asm("{ .reg .u64 t; cvta.to.shared.u64 t, %1; cvt.u32.u64 %0, t; }"
        : "=r"(a) : "l"(p));
    return a;
}

__device__ __forceinline__ void cpa16(unsigned s, const void* g) {
    asm volatile("cp.async.cg.shared.global [%0], [%1], 16;" :: "r"(s), "l"(g));
}
__device__ __forceinline__ void cpa_commit() {
    asm volatile("cp.async.commit_group;" ::: "memory");
}
__device__ __forceinline__ void cpa_wait1() {
    asm volatile("cp.async.wait_group 1;" ::: "memory");
}
__device__ __forceinline__ void cpa_wait0() {
    asm volatile("cp.async.wait_group 0;" ::: "memory");
}

// mma.sync m16n8k16 row.col f32.bf16.bf16.f32 (sm_80+ baseline PTX)
__device__ __forceinline__ void mma16816(float* d, const unsigned* a, const unsigned* b) {
    asm volatile(
        "mma.sync.aligned.m16n8k16.row.col.f32.bf16.bf16.f32 "
        "{%0,%1,%2,%3}, {%4,%5,%6,%7}, {%8,%9}, {%0,%1,%2,%3};"
        : "+f"(d[0]), "+f"(d[1]), "+f"(d[2]), "+f"(d[3])
        : "r"(a[0]), "r"(a[1]), "r"(a[2]), "r"(a[3]), "r"(b[0]), "r"(b[1]));
}

// ---------------------------------------------------------------------------
// split: fp32 -> (hi bf16, lo bf16)
// ---------------------------------------------------------------------------
__global__ __launch_bounds__(256) void split_kernel(
    const float* __restrict__ src, __nv_bfloat16* __restrict__ hi,
    __nv_bfloat16* __restrict__ lo, int n)
{
    int i = blockIdx.x * blockDim.x + threadIdx.x;
    const int stride = gridDim.x * blockDim.x;
    for (; i < n; i += stride) {
        const float x = src[i];
        const __nv_bfloat16 h = __float2bfloat16(x);
        hi[i] = h;
        lo[i] = __float2bfloat16(x - __bfloat162float(h));
    }
}

// ---------------------------------------------------------------------------
// mma.sync projection GEMM: out = X[M,1024] @ W[Nblk,1024]^T + bias
// split-bf16 3-pass: Xhi*Whi + Xhi*Wlo + Xlo*Whi, fp32 accum in registers.
// Tiles: CTA 128x128x(BK=32), 8 warps (4m x 2n), warp 32x64, mma m16n8k16.
// smem rows padded to 40 bf16 (conflict-free frag loads). cp.async dbl-buffer.
// DST: 0->g_q 1->g_k 2->g_v (bhtd layout), 3->outp ([M,C] row-major)
// ---------------------------------------------------------------------------
#define RS    40                       // smem row stride (bf16)
#define ABYTES (128*RS*2)              // 10240 B per array
#define BUFB  (4*ABYTES)               // 40960 B per buffer
#define PROJ_SMEM (2*BUFB)             // 81920 B

template <int DST>
__global__ __launch_bounds__(256, 1) void proj_mma(
    const __nv_bfloat16* __restrict__ Ahi, const __nv_bfloat16* __restrict__ Alo,
    const __nv_bfloat16* __restrict__ Bhi, const __nv_bfloat16* __restrict__ Blo,
    const float* __restrict__ bias, float* __restrict__ outp)
{
    extern __shared__ char smc[];
    const int tid  = threadIdx.x;
    const int wid  = tid >> 5, lane = tid & 31;
    const int g    = lane >> 2, q = lane & 3;      // frag row group / quad col
    const int wm   = wid >> 1, wn = wid & 1;       // warp grid 4x2
    const int bm   = blockIdx.y * 128;
    const int bn   = blockIdx.x * 128;
    const unsigned sb = smem_u32(smc);

    const __nv_bfloat16* srcs[4] = {Ahi, Alo, Bhi, Blo};

    // issue cp.async for one 32-wide K chunk into buffer `buf`
    auto load_chunk = [&](int k0, int buf) {
        const unsigned boff = (unsigned)buf * BUFB;
        #pragma unroll
        for (int it = 0; it < 8; ++it) {
            const int u   = it * 256 + tid;        // 0..2047
            const int arr = u >> 9;                // 0..3
            const int r   = (u >> 2) & 127;
            const int seg = u & 3;                 // 16B segment
            const int rowg = ((arr < 2) ? bm : bn) + r;
            const void* gp = (const char*)srcs[arr] + ((size_t)rowg * C_ + k0 + seg * 8) * 2;
            const unsigned sp = sb + boff + (unsigned)arr * ABYTES
                              + (unsigned)(r * RS + seg * 8) * 2;
            cpa16(sp, gp);
        }
        cpa_commit();
    };

    float acc[2][8][4] = {};   // [mtile][ntile][frag]

    load_chunk(0, 0);

    for (int c = 0; c < 32; ++c) {
        if (c < 31) load_chunk((c + 1) * 32, (c + 1) & 1);
        if (c < 31) cpa_wait1(); else cpa_wait0();
        __syncthreads();

        const __nv_bfloat16* base = (const __nv_bfloat16*)(smc + (c & 1) * BUFB);
        const __nv_bfloat16* As_h = base;
        const __nv_bfloat16* As_l = base +     128*RS;
        const __nv_bfloat16* Bs_h = base + 2 * 128*RS;
        const __nv_bfloat16* Bs_l = base + 3 * 128*RS;

        #pragma unroll
        for (int ks = 0; ks < 2; ++ks) {
            const int ko = ks * 16;
            unsigned bh[8][2], bl[8][2];
            #pragma unroll
            for (int nt = 0; nt < 8; ++nt) {
                const int nrow = wn * 64 + nt * 8 + g;
                bh[nt][0] = *(const unsigned*)(Bs_h + nrow * RS + ko + q * 2);
                bh[nt][1] = *(const unsigned*)(Bs_h + nrow * RS + ko + 8 + q * 2);
                bl[nt][0] = *(const unsigned*)(Bs_l + nrow * RS + ko + q * 2);
                bl[nt][1] = *(const unsigned*)(Bs_l + nrow * RS + ko + 8 + q * 2);
            }
            #pragma unroll
            for (int mt = 0; mt < 2; ++mt) {
                const int r0 = wm * 32 + mt * 16 + g;
                unsigned ah[4], al[4];
                ah[0] = *(const unsigned*)(As_h + (r0    ) * RS + ko     + q * 2);
                ah[1] = *(const unsigned*)(As_h + (r0 + 8) * RS + ko     + q * 2);
                ah[2] = *(const unsigned*)(As_h + (r0    ) * RS + ko + 8 + q * 2);
                ah[3] = *(const unsigned*)(As_h + (r0 + 8) * RS + ko + 8 + q * 2);
                al[0] = *(const unsigned*)(As_l + (r0    ) * RS + ko     + q * 2);
                al[1] = *(const unsigned*)(As_l + (r0 + 8) * RS + ko     + q * 2);
                al[2] = *(const unsigned*)(As_l + (r0    ) * RS + ko + 8 + q * 2);
                al[3] = *(const unsigned*)(As_l + (r0 + 8) * RS + ko + 8 + q * 2);
                #pragma unroll
                for (int nt = 0; nt < 8; ++nt) {
                    mma16816(acc[mt][nt], ah, bh[nt]);   // hi*hi
                    mma16816(acc[mt][nt], ah, bl[nt]);   // hi*lo
                    mma16816(acc[mt][nt], al, bh[nt]);   // lo*hi
                }
            }
        }
        __syncthreads();
    }

    // epilogue: fragment regs -> gmem (+bias)
    #pragma unroll
    for (int mt = 0; mt < 2; ++mt) {
        #pragma unroll
        for (int nt = 0; nt < 8; ++nt) {
            const int col = bn + wn * 64 + nt * 8 + q * 2;
            const float b0 = bias[col], b1 = bias[col + 1];
            #pragma unroll
            for (int hrow = 0; hrow < 2; ++hrow) {
                const int row = bm + wm * 32 + mt * 16 + g + hrow * 8;
                const float v0 = acc[mt][nt][hrow * 2 + 0] + b0;
                const float v1 = acc[mt][nt][hrow * 2 + 1] + b1;
                if (DST == 3) {
                    outp[(size_t)row * C_ + col]     = v0;
                    outp[(size_t)row * C_ + col + 1] = v1;
                } else {
                    const int bb = row >> 11, t = row & 2047;
                    const int h  = col >> 6,  d = col & 63;
                    float* dst = (DST == 0) ? g_q : (DST == 1) ? g_k : g_v;
                    float* p = &dst[(((size_t)(bb * H_ + h)) * T_ + t) * HD_ + d];
                    p[0] = v0; p[1] = v1;
                }
            }
        }
    }
}

// ---------------------------------------------------------------------------
// Causal flash attention, fp32 (unchanged, known correct)
// ---------------------------------------------------------------------------
__global__ __launch_bounds__(256) void attn_kernel()
{
    extern __shared__ float sm[];
    float (*Qs)[65] = (float(*)[65])(sm);
    float (*Ks)[65] = (float(*)[65])(sm + 64*65);
    float (*Vs)[65] = (float(*)[65])(sm + 2*64*65);
    float (*Ps)[65] = Ks;

    const int tid   = threadIdx.x;
    const int qtile = blockIdx.x;
    const int bh    = blockIdx.y;
    const int qbase = qtile * 64;

    const float* Qg = g_q + (size_t)bh * T_ * HD_;
    const float* Kg = g_k + (size_t)bh * T_ * HD_;
    const float* Vg = g_v + (size_t)bh * T_ * HD_;

    #pragma unroll
    for (int it = 0; it < 4; ++it) {
        const int idx = tid + it*256;
        const int row = idx >> 4;
        const int c4  = (idx & 15) * 4;
        float4 q4 = *(const float4*)(Qg + (size_t)(qbase+row)*HD_ + c4);
        Qs[row][c4+0]=q4.x; Qs[row][c4+1]=q4.y; Qs[row][c4+2]=q4.z; Qs[row][c4+3]=q4.w;
    }

    const int rp = tid >> 3;
    const int cs = tid & 7;
    const int r0 = rp*2, r1 = r0 + 1;
    const int cb = cs*8;

    float m0 = -1e30f, m1 = -1e30f, l0 = 0.f, l1 = 0.f;
    float acc0[8] = {}, acc1[8] = {};
    const float scale = 0.125f;

    for (int jt = 0; jt <= qtile; ++jt) {
        const int jbase = jt * 64;
        __syncthreads();

        #pragma unroll
        for (int it = 0; it < 4; ++it) {
            const int idx = tid + it*256;
            const int row = idx >> 4;
            const int c4  = (idx & 15) * 4;
            float4 k4 = *(const float4*)(Kg + (size_t)(jbase+row)*HD_ + c4);
            Ks[row][c4+0]=k4.x; Ks[row][c4+1]=k4.y; Ks[row][c4+2]=k4.z; Ks[row][c4+3]=k4.w;
            float4 v4 = *(const float4*)(Vg + (size_t)(jbase+row)*HD_ + c4);
            Vs[row][c4+0]=v4.x; Vs[row][c4+1]=v4.y; Vs[row][c4+2]=v4.z; Vs[row][c4+3]=v4.w;
        }
        __syncthreads();

        float s0[8] = {}, s1[8] = {};
        #pragma unroll 4
        for (int k = 0; k < 64; ++k) {
            const float qa = Qs[r0][k];
            const float qb = Qs[r1][k];
            #pragma unroll
            for (int c = 0; c < 8; ++c) {
                const float kv = Ks[cb+c][k];
                s0[c] = fmaf(qa, kv, s0[c]);
                s1[c] = fmaf(qb, kv, s1[c]);
            }
        }

        const bool diag = (jt == qtile);
        #pragma unroll
        for (int c = 0; c < 8; ++c) {
            s0[c] *= scale; s1[c] *= scale;
            if (diag) {
                if (cb + c > r0) s0[c] = -1e30f;
                if (cb + c > r1) s1[c] = -1e30f;
            }
        }

        float rm0 = s0[0], rm1 = s1[0];
        #pragma unroll
        for (int c = 1; c < 8; ++c) { rm0 = fmaxf(rm0, s0[c]); rm1 = fmaxf(rm1, s1[c]); }
        #pragma unroll
        for (int off = 1; off < 8; off <<= 1) {
            rm0 = fmaxf(rm0, __shfl_xor_sync(0xffffffffu, rm0, off));
            rm1 = fmaxf(rm1, __shfl_xor_sync(0xffffffffu, rm1, off));
        }

        const float mn0 = fmaxf(m0, rm0), mn1 = fmaxf(m1, rm1);
        const float al0 = __expf(m0 - mn0), al1 = __expf(m1 - mn1);
        float rs0 = 0.f, rs1 = 0.f;
        #pragma unroll
        for (int c = 0; c < 8; ++c) {
            s0[c] = __expf(s0[c] - mn0); rs0 += s0[c];
            s1[c] = __expf(s1[c] - mn1); rs1 += s1[c];
        }
        #pragma unroll
        for (int off = 1; off < 8; off <<= 1) {
            rs0 += __shfl_xor_sync(0xffffffffu, rs0, off);
            rs1 += __shfl_xor_sync(0xffffffffu, rs1, off);
        }
        l0 = al0*l0 + rs0;  l1 = al1*l1 + rs1;
        m0 = mn0;  m1 = mn1;
        #pragma unroll
        for (int d = 0; d < 8; ++d) { acc0[d] *= al0; acc1[d] *= al1; }

        __syncthreads();
        #pragma unroll
        for (int c = 0; c < 8; ++c) { Ps[r0][cb+c] = s0[c]; Ps[r1][cb+c] = s1[c]; }
        __syncthreads();

        #pragma unroll 4
        for (int c = 0; c < 64; ++c) {
            const float p0 = Ps[r0][c];
            const float p1 = Ps[r1][c];
            #pragma unroll
            for (int d = 0; d < 8; ++d) {
                const float vv = Vs[c][cb+d];
                acc0[d] = fmaf(p0, vv, acc0[d]);
                acc1[d] = fmaf(p1, vv, acc1[d]);
            }
        }
    }

    const int b = bh >> 4, h = bh & 15;
    const float inv0 = 1.f / l0, inv1 = 1.f / l1;
    const size_t base0 = ((size_t)(b*T_ + qbase + r0))*C_ + h*HD_ + cb;
    const size_t base1 = ((size_t)(b*T_ + qbase + r1))*C_ + h*HD_ + cb;
    #pragma unroll
    for (int d = 0; d < 8; ++d) {
        g_y[base0 + d] = acc0[d] * inv0;
        g_y[base1 + d] = acc1[d] * inv1;
    }
}

// ---------------------------------------------------------------------------
extern "C" void kernel_launch(void* const* d_in, const int* in_sizes, int n_in,
                              void* d_out, int out_size)
{
    const float* query = (const float*)d_in[0];
    const float* Wq = (const float*)d_in[1];  const float* bq = (const float*)d_in[2];
    const float* Wk = (const float*)d_in[3];  const float* bk = (const float*)d_in[4];
    const float* Wv = (const float*)d_in[5];  const float* bv = (const float*)d_in[6];
    const float* Wp = (const float*)d_in[7];  const float* bp = (const float*)d_in[8];

    __nv_bfloat16 *xhi, *xlo, *yhi, *ylo;
    __nv_bfloat16 *wqh, *wql, *wkh, *wkl, *wvh, *wvl, *wph, *wpl;
    float* yp;
    cudaGetSymbolAddress((void**)&xhi, g_xhi); cudaGetSymbolAddress((void**)&xlo, g_xlo);
    cudaGetSymbolAddress((void**)&yhi, g_yhi); cudaGetSymbolAddress((void**)&ylo, g_ylo);
    cudaGetSymbolAddress((void**)&wqh, g_wqhi); cudaGetSymbolAddress((void**)&wql, g_wqlo);
    cudaGetSymbolAddress((void**)&wkh, g_wkhi); cudaGetSymbolAddress((void**)&wkl, g_wklo);
    cudaGetSymbolAddress((void**)&wvh, g_wvhi); cudaGetSymbolAddress((void**)&wvl, g_wvlo);
    cudaGetSymbolAddress((void**)&wph, g_wphi); cudaGetSymbolAddress((void**)&wpl, g_wplo);
    cudaGetSymbolAddress((void**)&yp,  g_y);

    cudaFuncSetAttribute(proj_mma<0>, cudaFuncAttributeMaxDynamicSharedMemorySize, PROJ_SMEM);
    cudaFuncSetAttribute(proj_mma<1>, cudaFuncAttributeMaxDynamicSharedMemorySize, PROJ_SMEM);
    cudaFuncSetAttribute(proj_mma<2>, cudaFuncAttributeMaxDynamicSharedMemorySize, PROJ_SMEM);
    cudaFuncSetAttribute(proj_mma<3>, cudaFuncAttributeMaxDynamicSharedMemorySize, PROJ_SMEM);

    // splits
    split_kernel<<<2048, 256>>>(query, xhi, xlo, M_*C_);
    split_kernel<<<512, 256>>>(Wq, wqh, wql, C_*C_);
    split_kernel<<<512, 256>>>(Wk, wkh, wkl, C_*C_);
    split_kernel<<<512, 256>>>(Wv, wvh, wvl, C_*C_);
    split_kernel<<<512, 256>>>(Wp, wph, wpl, C_*C_);

    // q/k/v projections on mma.sync
    const dim3 pg(C_/128, M_/128);   // (8, 64)
    proj_mma<0><<<pg, 256, PROJ_SMEM>>>(xhi, xlo, wqh, wql, bq, nullptr);
    proj_mma<1><<<pg, 256, PROJ_SMEM>>>(xhi, xlo, wkh, wkl, bk, nullptr);
    proj_mma<2><<<pg, 256, PROJ_SMEM>>>(xhi, xlo, wvh, wvl, bv, nullptr);

    // attention (fp32 flash)
    const int attn_smem = 3*64*65*sizeof(float);
    cudaFuncSetAttribute(attn_kernel, cudaFuncAttributeMaxDynamicSharedMemorySize, attn_smem);
    attn_kernel<<<dim3(T_/64, B_*H_), 256, attn_smem>>>();

    // output projection
    split_kernel<<<2048, 256>>>(yp, yhi, ylo, M_*C_);
    proj_mma<3><<<pg, 256, PROJ_SMEM>>>(yhi, ylo, wph, wpl, bp, (float*)d_out);
}

// round 7
// speedup vs baseline: 2.5239x; 1.7203x over previous
#include <cuda_runtime.h>
#include <cuda_bf16.h>
#include <cstdint>

#define B_  4
#define T_  2048
#define C_  1024
#define H_  16
#define HD_ 64
#define M_  (B_*T_)   // 8192

// ---------------------------------------------------------------------------
// device scratch
// ---------------------------------------------------------------------------
__device__ float g_q[(size_t)B_*H_*T_*HD_];
__device__ float g_k[(size_t)B_*H_*T_*HD_];
__device__ float g_v[(size_t)B_*H_*T_*HD_];
__device__ float g_y[(size_t)B_*T_*C_];

__device__ __nv_bfloat16 g_xhi[(size_t)M_*C_];
__device__ __nv_bfloat16 g_xlo[(size_t)M_*C_];
__device__ __nv_bfloat16 g_yhi[(size_t)M_*C_];
__device__ __nv_bfloat16 g_ylo[(size_t)M_*C_];
__device__ __nv_bfloat16 g_wqhi[(size_t)C_*C_], g_wqlo[(size_t)C_*C_];
__device__ __nv_bfloat16 g_wkhi[(size_t)C_*C_], g_wklo[(size_t)C_*C_];
__device__ __nv_bfloat16 g_wvhi[(size_t)C_*C_], g_wvlo[(size_t)C_*C_];
__device__ __nv_bfloat16 g_wphi[(size_t)C_*C_], g_wplo[(size_t)C_*C_];

// ---------------------------------------------------------------------------
// helpers
// ---------------------------------------------------------------------------
__device__ __forceinline__ unsigned smem_u32(const void* p) {
    unsigned a;
    asm("{ .reg .u64 t; cvta.to.shared.u64 t, %1; cvt.u32.u64 %0, t; }"
        : "=r"(a) : "l"(p));
    return a;
}

__device__ __forceinline__ void cpa16(unsigned s, const void* g) {
    asm volatile("cp.async.cg.shared.global [%0], [%1], 16;" :: "r"(s), "l"(g));
}
__device__ __forceinline__ void cpa_commit() {
    asm volatile("cp.async.commit_group;" ::: "memory");
}
__device__ __forceinline__ void cpa_wait1() {
    asm volatile("cp.async.wait_group 1;" ::: "memory");
}
__device__ __forceinline__ void cpa_wait0() {
    asm volatile("cp.async.wait_group 0;" ::: "memory");
}

// mma.sync m16n8k16 row.col f32.bf16.bf16.f32
__device__ __forceinline__ void mma16816(float* d, const unsigned* a, const unsigned* b) {
    asm volatile(
        "mma.sync.aligned.m16n8k16.row.col.f32.bf16.bf16.f32 "
        "{%0,%1,%2,%3}, {%4,%5,%6,%7}, {%8,%9}, {%0,%1,%2,%3};"
        : "+f"(d[0]), "+f"(d[1]), "+f"(d[2]), "+f"(d[3])
        : "r"(a[0]), "r"(a[1]), "r"(a[2]), "r"(a[3]), "r"(b[0]), "r"(b[1]));
}

// ---------------------------------------------------------------------------
// split: fp32 -> (hi bf16, lo bf16)
// ---------------------------------------------------------------------------
__global__ __launch_bounds__(256) void split_kernel(
    const float* __restrict__ src, __nv_bfloat16* __restrict__ hi,
    __nv_bfloat16* __restrict__ lo, int n)
{
    int i = blockIdx.x * blockDim.x + threadIdx.x;
    const int stride = gridDim.x * blockDim.x;
    for (; i < n; i += stride) {
        const float x = src[i];
        const __nv_bfloat16 h = __float2bfloat16(x);
        hi[i] = h;
        lo[i] = __float2bfloat16(x - __bfloat162float(h));
    }
}

// ---------------------------------------------------------------------------
// mma.sync projection GEMM (pass-reordered to break acc RAW chains)
// ---------------------------------------------------------------------------
#define RS    40
#define ABYTES (128*RS*2)
#define BUFB  (4*ABYTES)
#define PROJ_SMEM (2*BUFB)             // 81920 B

template <int DST>
__global__ __launch_bounds__(256, 1) void proj_mma(
    const __nv_bfloat16* __restrict__ Ahi, const __nv_bfloat16* __restrict__ Alo,
    const __nv_bfloat16* __restrict__ Bhi, const __nv_bfloat16* __restrict__ Blo,
    const float* __restrict__ bias, float* __restrict__ outp)
{
    extern __shared__ char smc[];
    const int tid  = threadIdx.x;
    const int wid  = tid >> 5, lane = tid & 31;
    const int g    = lane >> 2, q = lane & 3;
    const int wm   = wid >> 1, wn = wid & 1;
    const int bm   = blockIdx.y * 128;
    const int bn   = blockIdx.x * 128;
    const unsigned sb = smem_u32(smc);

    const __nv_bfloat16* srcs[4] = {Ahi, Alo, Bhi, Blo};

    auto load_chunk = [&](int k0, int buf) {
        const unsigned boff = (unsigned)buf * BUFB;
        #pragma unroll
        for (int it = 0; it < 8; ++it) {
            const int u   = it * 256 + tid;
            const int arr = u >> 9;
            const int r   = (u >> 2) & 127;
            const int seg = u & 3;
            const int rowg = ((arr < 2) ? bm : bn) + r;
            const void* gp = (const char*)srcs[arr] + ((size_t)rowg * C_ + k0 + seg * 8) * 2;
            const unsigned sp = sb + boff + (unsigned)arr * ABYTES
                              + (unsigned)(r * RS + seg * 8) * 2;
            cpa16(sp, gp);
        }
        cpa_commit();
    };

    float acc[2][8][4] = {};

    load_chunk(0, 0);

    for (int c = 0; c < 32; ++c) {
        if (c < 31) load_chunk((c + 1) * 32, (c + 1) & 1);
        if (c < 31) cpa_wait1(); else cpa_wait0();
        __syncthreads();

        const __nv_bfloat16* base = (const __nv_bfloat16*)(smc + (c & 1) * BUFB);
        const __nv_bfloat16* As_h = base;
        const __nv_bfloat16* As_l = base +     128*RS;
        const __nv_bfloat16* Bs_h = base + 2 * 128*RS;
        const __nv_bfloat16* Bs_l = base + 3 * 128*RS;

        #pragma unroll
        for (int ks = 0; ks < 2; ++ks) {
            const int ko = ks * 16;
            unsigned bh[8][2], bl[8][2];
            #pragma unroll
            for (int nt = 0; nt < 8; ++nt) {
                const int nrow = wn * 64 + nt * 8 + g;
                bh[nt][0] = *(const unsigned*)(Bs_h + nrow * RS + ko + q * 2);
                bh[nt][1] = *(const unsigned*)(Bs_h + nrow * RS + ko + 8 + q * 2);
                bl[nt][0] = *(const unsigned*)(Bs_l + nrow * RS + ko + q * 2);
                bl[nt][1] = *(const unsigned*)(Bs_l + nrow * RS + ko + 8 + q * 2);
            }
            #pragma unroll
            for (int mt = 0; mt < 2; ++mt) {
                const int r0 = wm * 32 + mt * 16 + g;
                unsigned ah[4], al[4];
                ah[0] = *(const unsigned*)(As_h + (r0    ) * RS + ko     + q * 2);
                ah[1] = *(const unsigned*)(As_h + (r0 + 8) * RS + ko     + q * 2);
                ah[2] = *(const unsigned*)(As_h + (r0    ) * RS + ko + 8 + q * 2);
                ah[3] = *(const unsigned*)(As_h + (r0 + 8) * RS + ko + 8 + q * 2);
                al[0] = *(const unsigned*)(As_l + (r0    ) * RS + ko     + q * 2);
                al[1] = *(const unsigned*)(As_l + (r0 + 8) * RS + ko     + q * 2);
                al[2] = *(const unsigned*)(As_l + (r0    ) * RS + ko + 8 + q * 2);
                al[3] = *(const unsigned*)(As_l + (r0 + 8) * RS + ko + 8 + q * 2);
                // pass-major order: 8 independent accs between reuses
                #pragma unroll
                for (int nt = 0; nt < 8; ++nt) mma16816(acc[mt][nt], ah, bh[nt]);
                #pragma unroll
                for (int nt = 0; nt < 8; ++nt) mma16816(acc[mt][nt], ah, bl[nt]);
                #pragma unroll
                for (int nt = 0; nt < 8; ++nt) mma16816(acc[mt][nt], al, bh[nt]);
            }
        }
        __syncthreads();
    }

    #pragma unroll
    for (int mt = 0; mt < 2; ++mt) {
        #pragma unroll
        for (int nt = 0; nt < 8; ++nt) {
            const int col = bn + wn * 64 + nt * 8 + q * 2;
            const float b0 = bias[col], b1 = bias[col + 1];
            #pragma unroll
            for (int hrow = 0; hrow < 2; ++hrow) {
                const int row = bm + wm * 32 + mt * 16 + g + hrow * 8;
                const float v0 = acc[mt][nt][hrow * 2 + 0] + b0;
                const float v1 = acc[mt][nt][hrow * 2 + 1] + b1;
                if (DST == 3) {
                    outp[(size_t)row * C_ + col]     = v0;
                    outp[(size_t)row * C_ + col + 1] = v1;
                } else {
                    const int bb = row >> 11, t = row & 2047;
                    const int h  = col >> 6,  d = col & 63;
                    float* dst = (DST == 0) ? g_q : (DST == 1) ? g_k : g_v;
                    float* p = &dst[(((size_t)(bb * H_ + h)) * T_ + t) * HD_ + d];
                    p[0] = v0; p[1] = v1;
                }
            }
        }
    }
}

// ---------------------------------------------------------------------------
// Causal flash attention, fp32. BR=128, BC=64, 256 threads.
// Thread tile: 4 rows (rbase..rbase+3) x 8 interleaved cols (cs + 8c).
// Bank-conflict-free fragment loads. Separate P buffer (no K reuse).
// smem: Qs[128][65] Ks[64][65] Vs[64][65] Ps[128][65] = 99,840 B
// ---------------------------------------------------------------------------
#define ATTN_SMEM (384*65*4)

__global__ __launch_bounds__(256) void attn_kernel()
{
    extern __shared__ float sm[];
    float (*Qs)[65] = (float(*)[65])(sm);
    float (*Ks)[65] = (float(*)[65])(sm + 128*65);
    float (*Vs)[65] = (float(*)[65])(sm + 192*65);
    float (*Ps)[65] = (float(*)[65])(sm + 256*65);

    const int tid   = threadIdx.x;
    const int blk   = blockIdx.x;        // 0..15
    const int bh    = blockIdx.y;        // 0..63
    const int qbase = blk * 128;

    const float* Qg = g_q + (size_t)bh * T_ * HD_;
    const float* Kg = g_k + (size_t)bh * T_ * HD_;
    const float* Vg = g_v + (size_t)bh * T_ * HD_;

    // load Q tile (128 x 64), float4 coalesced
    #pragma unroll
    for (int it = 0; it < 8; ++it) {
        const int idx = it * 256 + tid;
        const int row = idx >> 4;
        const int c4  = (idx & 15) * 4;
        float4 q4 = *(const float4*)(Qg + (size_t)(qbase + row) * HD_ + c4);
        Qs[row][c4+0]=q4.x; Qs[row][c4+1]=q4.y; Qs[row][c4+2]=q4.z; Qs[row][c4+3]=q4.w;
    }

    const int rp = tid >> 3;             // 0..31
    const int cs = tid & 7;              // 0..7
    const int rbase = rp * 4;            // rows rbase..rbase+3

    float m[4], l[4] = {0.f, 0.f, 0.f, 0.f};
    float acc[4][8] = {};
    #pragma unroll
    for (int i = 0; i < 4; ++i) m[i] = -1e30f;
    const float scale = 0.125f;          // 1/sqrt(64)

    const int ntiles = 2 * blk + 2;
    for (int jt = 0; jt < ntiles; ++jt) {
        const int jbase = jt * 64;
        __syncthreads();                 // prev iter done with Ks/Vs/Ps

        #pragma unroll
        for (int it = 0; it < 4; ++it) {
            const int idx = it * 256 + tid;
            const int row = idx >> 4;
            const int c4  = (idx & 15) * 4;
            float4 k4 = *(const float4*)(Kg + (size_t)(jbase + row) * HD_ + c4);
            Ks[row][c4+0]=k4.x; Ks[row][c4+1]=k4.y; Ks[row][c4+2]=k4.z; Ks[row][c4+3]=k4.w;
            float4 v4 = *(const float4*)(Vg + (size_t)(jbase + row) * HD_ + c4);
            Vs[row][c4+0]=v4.x; Vs[row][c4+1]=v4.y; Vs[row][c4+2]=v4.z; Vs[row][c4+3]=v4.w;
        }
        __syncthreads();

        // threads whose 4 rows are all above this tile's cols contribute nothing
        const bool active = (jbase <= qbase + rbase + 3);

        if (active) {
            // S = Q K^T  (cols interleaved: col = cs + 8c)
            float s[4][8] = {};
            #pragma unroll 4
            for (int k = 0; k < 64; ++k) {
                float qa[4];
                #pragma unroll
                for (int i = 0; i < 4; ++i) qa[i] = Qs[rbase + i][k];
                #pragma unroll
                for (int c = 0; c < 8; ++c) {
                    const float kv = Ks[cs + 8*c][k];
                    #pragma unroll
                    for (int i = 0; i < 4; ++i)
                        s[i][c] = fmaf(qa[i], kv, s[i][c]);
                }
            }

            const bool maymask = (jbase + 63 > qbase + rbase);
            #pragma unroll
            for (int i = 0; i < 4; ++i) {
                const int grow = qbase + rbase + i;
                #pragma unroll
                for (int c = 0; c < 8; ++c) {
                    s[i][c] *= scale;
                    if (maymask && (jbase + cs + 8*c > grow)) s[i][c] = -1e30f;
                }
            }

            // online softmax (reduce over 8 regs + 8 aligned lanes)
            #pragma unroll
            for (int i = 0; i < 4; ++i) {
                float rm = s[i][0];
                #pragma unroll
                for (int c = 1; c < 8; ++c) rm = fmaxf(rm, s[i][c]);
                #pragma unroll
                for (int off = 1; off < 8; off <<= 1)
                    rm = fmaxf(rm, __shfl_xor_sync(0xffffffffu, rm, off));
                const float mn = fmaxf(m[i], rm);
                const float al = __expf(m[i] - mn);
                float rs = 0.f;
                #pragma unroll
                for (int c = 0; c < 8; ++c) { s[i][c] = __expf(s[i][c] - mn); rs += s[i][c]; }
                #pragma unroll
                for (int off = 1; off < 8; off <<= 1)
                    rs += __shfl_xor_sync(0xffffffffu, rs, off);
                l[i] = al * l[i] + rs;
                m[i] = mn;
                #pragma unroll
                for (int d = 0; d < 8; ++d) acc[i][d] *= al;
            }

            // write P
            #pragma unroll
            for (int i = 0; i < 4; ++i)
                #pragma unroll
                for (int c = 0; c < 8; ++c)
                    Ps[rbase + i][cs + 8*c] = s[i][c];
        } else {
            // still must zero P rows? no: inactive threads' rows are fully
            // masked only for THIS tile; their rows are below jbase start...
            // inactive means all cols > all rows -> P rows would be all zero.
            #pragma unroll
            for (int i = 0; i < 4; ++i)
                #pragma unroll
                for (int c = 0; c < 8; ++c)
                    Ps[rbase + i][cs + 8*c] = 0.f;
        }
        __syncthreads();

        // O += P V  (cols interleaved: col = cs + 8d)
        if (active) {
            #pragma unroll 4
            for (int c = 0; c < 64; ++c) {
                float p[4];
                #pragma unroll
                for (int i = 0; i < 4; ++i) p[i] = Ps[rbase + i][c];
                #pragma unroll
                for (int d = 0; d < 8; ++d) {
                    const float vv = Vs[c][cs + 8*d];
                    #pragma unroll
                    for (int i = 0; i < 4; ++i)
                        acc[i][d] = fmaf(p[i], vv, acc[i][d]);
                }
            }
        }
    }

    // epilogue: y[b, t, h*64 + col] = O / l,  col = cs + 8d
    const int b = bh >> 4, h = bh & 15;
    #pragma unroll
    for (int i = 0; i < 4; ++i) {
        const int row = qbase + rbase + i;
        const float inv = 1.f / l[i];
        const size_t base = ((size_t)(b * T_ + row)) * C_ + h * HD_ + cs;
        #pragma unroll
        for (int d = 0; d < 8; ++d)
            g_y[base + 8*d] = acc[i][d] * inv;
    }
}

// ---------------------------------------------------------------------------
extern "C" void kernel_launch(void* const* d_in, const int* in_sizes, int n_in,
                              void* d_out, int out_size)
{
    const float* query = (const float*)d_in[0];
    const float* Wq = (const float*)d_in[1];  const float* bq = (const float*)d_in[2];
    const float* Wk = (const float*)d_in[3];  const float* bk = (const float*)d_in[4];
    const float* Wv = (const float*)d_in[5];  const float* bv = (const float*)d_in[6];
    const float* Wp = (const float*)d_in[7];  const float* bp = (const float*)d_in[8];

    __nv_bfloat16 *xhi, *xlo, *yhi, *ylo;
    __nv_bfloat16 *wqh, *wql, *wkh, *wkl, *wvh, *wvl, *wph, *wpl;
    float* yp;
    cudaGetSymbolAddress((void**)&xhi, g_xhi); cudaGetSymbolAddress((void**)&xlo, g_xlo);
    cudaGetSymbolAddress((void**)&yhi, g_yhi); cudaGetSymbolAddress((void**)&ylo, g_ylo);
    cudaGetSymbolAddress((void**)&wqh, g_wqhi); cudaGetSymbolAddress((void**)&wql, g_wqlo);
    cudaGetSymbolAddress((void**)&wkh, g_wkhi); cudaGetSymbolAddress((void**)&wkl, g_wklo);
    cudaGetSymbolAddress((void**)&wvh, g_wvhi); cudaGetSymbolAddress((void**)&wvl, g_wvlo);
    cudaGetSymbolAddress((void**)&wph, g_wphi); cudaGetSymbolAddress((void**)&wpl, g_wplo);
    cudaGetSymbolAddress((void**)&yp,  g_y);

    cudaFuncSetAttribute(proj_mma<0>, cudaFuncAttributeMaxDynamicSharedMemorySize, PROJ_SMEM);
    cudaFuncSetAttribute(proj_mma<1>, cudaFuncAttributeMaxDynamicSharedMemorySize, PROJ_SMEM);
    cudaFuncSetAttribute(proj_mma<2>, cudaFuncAttributeMaxDynamicSharedMemorySize, PROJ_SMEM);
    cudaFuncSetAttribute(proj_mma<3>, cudaFuncAttributeMaxDynamicSharedMemorySize, PROJ_SMEM);
    cudaFuncSetAttribute(attn_kernel, cudaFuncAttributeMaxDynamicSharedMemorySize, ATTN_SMEM);

    // splits
    split_kernel<<<2048, 256>>>(query, xhi, xlo, M_*C_);
    split_kernel<<<512, 256>>>(Wq, wqh, wql, C_*C_);
    split_kernel<<<512, 256>>>(Wk, wkh, wkl, C_*C_);
    split_kernel<<<512, 256>>>(Wv, wvh, wvl, C_*C_);
    split_kernel<<<512, 256>>>(Wp, wph, wpl, C_*C_);

    // q/k/v projections on mma.sync
    const dim3 pg(C_/128, M_/128);   // (8, 64)
    proj_mma<0><<<pg, 256, PROJ_SMEM>>>(xhi, xlo, wqh, wql, bq, nullptr);
    proj_mma<1><<<pg, 256, PROJ_SMEM>>>(xhi, xlo, wkh, wkl, bk, nullptr);
    proj_mma<2><<<pg, 256, PROJ_SMEM>>>(xhi, xlo, wvh, wvl, bv, nullptr);

    // attention (fp32 flash, BR=128)
    attn_kernel<<<dim3(T_/128, B_*H_), 256, ATTN_SMEM>>>();

    // output projection
    split_kernel<<<2048, 256>>>(yp, yhi, ylo, M_*C_);
    proj_mma<3><<<pg, 256, PROJ_SMEM>>>(yhi, ylo, wph, wpl, bp, (float*)d_out);
}

// round 8
// speedup vs baseline: 4.2073x; 1.6670x over previous
#include <cuda_runtime.h>
#include <cuda_bf16.h>
#include <cstdint>

#define B_  4
#define T_  2048
#define C_  1024
#define H_  16
#define HD_ 64
#define M_  (B_*T_)   // 8192

// ---------------------------------------------------------------------------
// device scratch (bf16 split everywhere)
// ---------------------------------------------------------------------------
__device__ __nv_bfloat16 g_xhi[(size_t)M_*C_];
__device__ __nv_bfloat16 g_xlo[(size_t)M_*C_];
__device__ __nv_bfloat16 g_yhi[(size_t)M_*C_];
__device__ __nv_bfloat16 g_ylo[(size_t)M_*C_];
__device__ __nv_bfloat16 g_qhi[(size_t)B_*H_*T_*HD_], g_qlo[(size_t)B_*H_*T_*HD_];
__device__ __nv_bfloat16 g_khi[(size_t)B_*H_*T_*HD_], g_klo[(size_t)B_*H_*T_*HD_];
__device__ __nv_bfloat16 g_vthi[(size_t)B_*H_*HD_*T_], g_vtlo[(size_t)B_*H_*HD_*T_]; // [B,H,hd,T]
__device__ __nv_bfloat16 g_wqhi[(size_t)C_*C_], g_wqlo[(size_t)C_*C_];
__device__ __nv_bfloat16 g_wkhi[(size_t)C_*C_], g_wklo[(size_t)C_*C_];
__device__ __nv_bfloat16 g_wvhi[(size_t)C_*C_], g_wvlo[(size_t)C_*C_];
__device__ __nv_bfloat16 g_wphi[(size_t)C_*C_], g_wplo[(size_t)C_*C_];

// ---------------------------------------------------------------------------
// helpers
// ---------------------------------------------------------------------------
__device__ __forceinline__ unsigned smem_u32(const void* p) {
    unsigned a;
    asm("{ .reg .u64 t; cvta.to.shared.u64 t, %1; cvt.u32.u64 %0, t; }"
        : "=r"(a) : "l"(p));
    return a;
}
__device__ __forceinline__ void cpa16(unsigned s, const void* g) {
    asm volatile("cp.async.cg.shared.global [%0], [%1], 16;" :: "r"(s), "l"(g));
}
__device__ __forceinline__ void cpa_commit() {
    asm volatile("cp.async.commit_group;" ::: "memory");
}
__device__ __forceinline__ void cpa_wait1() {
    asm volatile("cp.async.wait_group 1;" ::: "memory");
}
__device__ __forceinline__ void cpa_wait0() {
    asm volatile("cp.async.wait_group 0;" ::: "memory");
}
__device__ __forceinline__ void mma16816(float* d, const unsigned* a, const unsigned* b) {
    asm volatile(
        "mma.sync.aligned.m16n8k16.row.col.f32.bf16.bf16.f32 "
        "{%0,%1,%2,%3}, {%4,%5,%6,%7}, {%8,%9}, {%0,%1,%2,%3};"
        : "+f"(d[0]), "+f"(d[1]), "+f"(d[2]), "+f"(d[3])
        : "r"(a[0]), "r"(a[1]), "r"(a[2]), "r"(a[3]), "r"(b[0]), "r"(b[1]));
}
// pack two f32 -> bf16x2 (lo = first arg)
__device__ __forceinline__ unsigned pack_bf(float lo, float hi) {
    unsigned d;
    asm("cvt.rn.bf16x2.f32 %0, %1, %2;" : "=r"(d) : "f"(hi), "f"(lo));
    return d;
}
__device__ __forceinline__ void split_pack(float p0, float p1, unsigned& hi, unsigned& lo) {
    hi = pack_bf(p0, p1);
    __nv_bfloat162 h2 = *reinterpret_cast<__nv_bfloat162*>(&hi);
    lo = pack_bf(p0 - __bfloat162float(h2.x), p1 - __bfloat162float(h2.y));
}

// ---------------------------------------------------------------------------
// split: fp32 -> (hi bf16, lo bf16)
// ---------------------------------------------------------------------------
__global__ __launch_bounds__(256) void split_kernel(
    const float* __restrict__ src, __nv_bfloat16* __restrict__ hi,
    __nv_bfloat16* __restrict__ lo, int n)
{
    int i = blockIdx.x * blockDim.x + threadIdx.x;
    const int stride = gridDim.x * blockDim.x;
    for (; i < n; i += stride) {
        const float x = src[i];
        const __nv_bfloat16 h = __float2bfloat16(x);
        hi[i] = h;
        lo[i] = __float2bfloat16(x - __bfloat162float(h));
    }
}

// ---------------------------------------------------------------------------
// mma.sync projection GEMM (proven R7 mainloop; epilogue emits split bf16)
// DST: 0->q hi/lo [B,H,T,64], 1->k hi/lo, 2->v hi/lo TRANSPOSED [B,H,64,T],
//      3->f32 outp [M,C]
// ---------------------------------------------------------------------------
#define RS    40
#define ABYTES (128*RS*2)
#define BUFB  (4*ABYTES)
#define PROJ_SMEM (2*BUFB)             // 81920 B

template <int DST>
__global__ __launch_bounds__(256, 1) void proj_mma(
    const __nv_bfloat16* __restrict__ Ahi, const __nv_bfloat16* __restrict__ Alo,
    const __nv_bfloat16* __restrict__ Bhi, const __nv_bfloat16* __restrict__ Blo,
    const float* __restrict__ bias, float* __restrict__ outp)
{
    extern __shared__ char smc[];
    const int tid  = threadIdx.x;
    const int wid  = tid >> 5, lane = tid & 31;
    const int g    = lane >> 2, q = lane & 3;
    const int wm   = wid >> 1, wn = wid & 1;
    const int bm   = blockIdx.y * 128;
    const int bn   = blockIdx.x * 128;
    const unsigned sb = smem_u32(smc);

    const __nv_bfloat16* srcs[4] = {Ahi, Alo, Bhi, Blo};

    auto load_chunk = [&](int k0, int buf) {
        const unsigned boff = (unsigned)buf * BUFB;
        #pragma unroll
        for (int it = 0; it < 8; ++it) {
            const int u   = it * 256 + tid;
            const int arr = u >> 9;
            const int r   = (u >> 2) & 127;
            const int seg = u & 3;
            const int rowg = ((arr < 2) ? bm : bn) + r;
            const void* gp = (const char*)srcs[arr] + ((size_t)rowg * C_ + k0 + seg * 8) * 2;
            const unsigned sp = sb + boff + (unsigned)arr * ABYTES
                              + (unsigned)(r * RS + seg * 8) * 2;
            cpa16(sp, gp);
        }
        cpa_commit();
    };

    float acc[2][8][4] = {};

    load_chunk(0, 0);

    for (int c = 0; c < 32; ++c) {
        if (c < 31) load_chunk((c + 1) * 32, (c + 1) & 1);
        if (c < 31) cpa_wait1(); else cpa_wait0();
        __syncthreads();

        const __nv_bfloat16* base = (const __nv_bfloat16*)(smc + (c & 1) * BUFB);
        const __nv_bfloat16* As_h = base;
        const __nv_bfloat16* As_l = base +     128*RS;
        const __nv_bfloat16* Bs_h = base + 2 * 128*RS;
        const __nv_bfloat16* Bs_l = base + 3 * 128*RS;

        #pragma unroll
        for (int ks = 0; ks < 2; ++ks) {
            const int ko = ks * 16;
            unsigned bh[8][2], bl[8][2];
            #pragma unroll
            for (int nt = 0; nt < 8; ++nt) {
                const int nrow = wn * 64 + nt * 8 + g;
                bh[nt][0] = *(const unsigned*)(Bs_h + nrow * RS + ko + q * 2);
                bh[nt][1] = *(const unsigned*)(Bs_h + nrow * RS + ko + 8 + q * 2);
                bl[nt][0] = *(const unsigned*)(Bs_l + nrow * RS + ko + q * 2);
                bl[nt][1] = *(const unsigned*)(Bs_l + nrow * RS + ko + 8 + q * 2);
            }
            #pragma unroll
            for (int mt = 0; mt < 2; ++mt) {
                const int r0 = wm * 32 + mt * 16 + g;
                unsigned ah[4], al[4];
                ah[0] = *(const unsigned*)(As_h + (r0    ) * RS + ko     + q * 2);
                ah[1] = *(const unsigned*)(As_h + (r0 + 8) * RS + ko     + q * 2);
                ah[2] = *(const unsigned*)(As_h + (r0    ) * RS + ko + 8 + q * 2);
                ah[3] = *(const unsigned*)(As_h + (r0 + 8) * RS + ko + 8 + q * 2);
                al[0] = *(const unsigned*)(As_l + (r0    ) * RS + ko     + q * 2);
                al[1] = *(const unsigned*)(As_l + (r0 + 8) * RS + ko     + q * 2);
                al[2] = *(const unsigned*)(As_l + (r0    ) * RS + ko + 8 + q * 2);
                al[3] = *(const unsigned*)(As_l + (r0 + 8) * RS + ko + 8 + q * 2);
                #pragma unroll
                for (int nt = 0; nt < 8; ++nt) mma16816(acc[mt][nt], ah, bh[nt]);
                #pragma unroll
                for (int nt = 0; nt < 8; ++nt) mma16816(acc[mt][nt], ah, bl[nt]);
                #pragma unroll
                for (int nt = 0; nt < 8; ++nt) mma16816(acc[mt][nt], al, bh[nt]);
            }
        }
        __syncthreads();
    }

    #pragma unroll
    for (int mt = 0; mt < 2; ++mt) {
        #pragma unroll
        for (int nt = 0; nt < 8; ++nt) {
            const int col = bn + wn * 64 + nt * 8 + q * 2;
            const float b0 = bias[col], b1 = bias[col + 1];
            #pragma unroll
            for (int hrow = 0; hrow < 2; ++hrow) {
                const int row = bm + wm * 32 + mt * 16 + g + hrow * 8;
                const float v0 = acc[mt][nt][hrow * 2 + 0] + b0;
                const float v1 = acc[mt][nt][hrow * 2 + 1] + b1;
                if (DST == 3) {
                    outp[(size_t)row * C_ + col]     = v0;
                    outp[(size_t)row * C_ + col + 1] = v1;
                } else {
                    const __nv_bfloat16 h0 = __float2bfloat16(v0);
                    const __nv_bfloat16 h1 = __float2bfloat16(v1);
                    const __nv_bfloat16 l0 = __float2bfloat16(v0 - __bfloat162float(h0));
                    const __nv_bfloat16 l1 = __float2bfloat16(v1 - __bfloat162float(h1));
                    const int bb = row >> 11, t = row & 2047;
                    const int hh = col >> 6,  d = col & 63;
                    if (DST == 0 || DST == 1) {
                        const size_t idx = (((size_t)(bb * H_ + hh)) * T_ + t) * HD_ + d;
                        __nv_bfloat16* dh = (DST == 0) ? g_qhi : g_khi;
                        __nv_bfloat16* dl = (DST == 0) ? g_qlo : g_klo;
                        *(__nv_bfloat162*)(dh + idx) = __halves2bfloat162(h0, h1);
                        *(__nv_bfloat162*)(dl + idx) = __halves2bfloat162(l0, l1);
                    } else {  // DST==2: transposed V
                        const size_t idx = (((size_t)(bb * H_ + hh)) * HD_ + d) * T_ + t;
                        g_vthi[idx] = h0;  g_vthi[idx + T_] = h1;
                        g_vtlo[idx] = l0;  g_vtlo[idx + T_] = l1;
                    }
                }
            }
        }
    }
}

// ---------------------------------------------------------------------------
// Flash attention on mma.sync (FA2 Ampere pattern), split-bf16 3-pass.
// Block: 256 thr = 8 warps, BR=128 (warp w: rows w*16..+15), BC=64.
// smem: per buffer Khi|Klo|Vthi|Vtlo, each 64 x 72 bf16 (pad-72 conflict-free),
// double-buffered cp.async. P stays in registers (C-frag == A-frag identity).
// Writes y split bf16 hi/lo directly.
// ---------------------------------------------------------------------------
#define RS2   72
#define ARR2B (64*RS2*2)      // 9216
#define TBUF  (4*ARR2B)       // 36864
#define ATTN_SMEM (2*TBUF)    // 73728

__global__ __launch_bounds__(256) void attn_mma()
{
    extern __shared__ char smc[];
    const int tid = threadIdx.x;
    const int w = tid >> 5, lane = tid & 31;
    const int g = lane >> 2, q = lane & 3;
    const int blk = blockIdx.x, bh = blockIdx.y;
    const int qbase = blk * 128;
    const unsigned sb = smem_u32(smc);

    const __nv_bfloat16* Qh = g_qhi + (size_t)bh * T_ * HD_ + (size_t)(qbase + w * 16) * HD_;
    const __nv_bfloat16* Ql = g_qlo + (size_t)bh * T_ * HD_ + (size_t)(qbase + w * 16) * HD_;
    const __nv_bfloat16* Kh = g_khi + (size_t)bh * T_ * HD_;
    const __nv_bfloat16* Kl = g_klo + (size_t)bh * T_ * HD_;
    const __nv_bfloat16* Vh = g_vthi + (size_t)bh * HD_ * T_;
    const __nv_bfloat16* Vl = g_vtlo + (size_t)bh * HD_ * T_;

    // Q fragments resident in registers (a-frag layout)
    unsigned qh[4][4], ql[4][4];
    #pragma unroll
    for (int s = 0; s < 4; ++s) {
        const int c0 = s * 16 + 2 * q;
        qh[s][0] = *(const unsigned*)(Qh + (g    ) * HD_ + c0);
        qh[s][1] = *(const unsigned*)(Qh + (g + 8) * HD_ + c0);
        qh[s][2] = *(const unsigned*)(Qh + (g    ) * HD_ + c0 + 8);
        qh[s][3] = *(const unsigned*)(Qh + (g + 8) * HD_ + c0 + 8);
        ql[s][0] = *(const unsigned*)(Ql + (g    ) * HD_ + c0);
        ql[s][1] = *(const unsigned*)(Ql + (g + 8) * HD_ + c0);
        ql[s][2] = *(const unsigned*)(Ql + (g    ) * HD_ + c0 + 8);
        ql[s][3] = *(const unsigned*)(Ql + (g + 8) * HD_ + c0 + 8);
    }

    float oacc[8][4] = {};
    float m[2] = {-1e30f, -1e30f}, l[2] = {0.f, 0.f};

    auto load_tile = [&](int jt, int buf) {
        const int jb = jt * 64;
        const unsigned boff = (unsigned)buf * TBUF;
        #pragma unroll
        for (int it = 0; it < 8; ++it) {
            const int u = it * 256 + tid;      // 0..2047
            const int arr = u >> 9;            // 0..3
            const int r   = (u >> 3) & 63;
            const int seg = u & 7;
            const __nv_bfloat16* src = (arr == 0) ? Kh : (arr == 1) ? Kl
                                      : (arr == 2) ? Vh : Vl;
            const void* gp = (arr < 2)
                ? (const void*)(src + ((size_t)(jb + r)) * HD_ + seg * 8)
                : (const void*)(src + ((size_t)r) * T_ + jb + seg * 8);
            const unsigned sp = sb + boff + (unsigned)arr * ARR2B
                              + (unsigned)(r * RS2 + seg * 8) * 2;
            cpa16(sp, gp);
        }
        cpa_commit();
    };

    const int ntiles = 2 * blk + 2;
    load_tile(0, 0);

    for (int jt = 0; jt < ntiles; ++jt) {
        if (jt < ntiles - 1) load_tile(jt + 1, (jt + 1) & 1);
        if (jt < ntiles - 1) cpa_wait1(); else cpa_wait0();
        __syncthreads();

        const int jb = jt * 64;
        if (jb <= qbase + w * 16 + 15) {   // warp-uniform causal skip
            const char* bufc = smc + (jt & 1) * TBUF;
            const __nv_bfloat16* Ksh = (const __nv_bfloat16*)(bufc);
            const __nv_bfloat16* Ksl = (const __nv_bfloat16*)(bufc + ARR2B);
            const __nv_bfloat16* Vsh = (const __nv_bfloat16*)(bufc + 2 * ARR2B);
            const __nv_bfloat16* Vsl = (const __nv_bfloat16*)(bufc + 3 * ARR2B);

            // ---- S = Q K^T (3-pass split) ----
            float sacc[8][4] = {};
            #pragma unroll
            for (int s = 0; s < 4; ++s) {
                const int ko = s * 16 + 2 * q;
                #pragma unroll
                for (int ntg = 0; ntg < 2; ++ntg) {
                    unsigned kbh[4][2], kbl[4][2];
                    #pragma unroll
                    for (int j = 0; j < 4; ++j) {
                        const int nr = (ntg * 4 + j) * 8 + g;
                        kbh[j][0] = *(const unsigned*)(Ksh + nr * RS2 + ko);
                        kbh[j][1] = *(const unsigned*)(Ksh + nr * RS2 + ko + 8);
                        kbl[j][0] = *(const unsigned*)(Ksl + nr * RS2 + ko);
                        kbl[j][1] = *(const unsigned*)(Ksl + nr * RS2 + ko + 8);
                    }
                    #pragma unroll
                    for (int j = 0; j < 4; ++j) mma16816(sacc[ntg*4+j], qh[s], kbh[j]);
                    #pragma unroll
                    for (int j = 0; j < 4; ++j) mma16816(sacc[ntg*4+j], qh[s], kbl[j]);
                    #pragma unroll
                    for (int j = 0; j < 4; ++j) mma16816(sacc[ntg*4+j], ql[s], kbh[j]);
                }
            }

            // ---- scale + causal mask ----
            const bool needmask = (jb + 63 > qbase + w * 16);
            #pragma unroll
            for (int nt = 0; nt < 8; ++nt) {
                #pragma unroll
                for (int e = 0; e < 4; ++e) {
                    float v = sacc[nt][e] * 0.125f;
                    if (needmask) {
                        const int col = jb + nt * 8 + 2 * q + (e & 1);
                        const int row = qbase + w * 16 + g + (e >> 1) * 8;
                        if (col > row) v = -1e30f;
                    }
                    sacc[nt][e] = v;
                }
            }

            // ---- online softmax ----
            float mn[2];
            #pragma unroll
            for (int i = 0; i < 2; ++i) {
                float rm = sacc[0][i*2];
                #pragma unroll
                for (int nt = 0; nt < 8; ++nt) {
                    rm = fmaxf(rm, sacc[nt][i*2]);
                    rm = fmaxf(rm, sacc[nt][i*2+1]);
                }
                rm = fmaxf(rm, __shfl_xor_sync(0xffffffffu, rm, 1));
                rm = fmaxf(rm, __shfl_xor_sync(0xffffffffu, rm, 2));
                mn[i] = fmaxf(m[i], rm);
            }
            const float al0 = __expf(m[0] - mn[0]);
            const float al1 = __expf(m[1] - mn[1]);
            float rs[2] = {0.f, 0.f};
            #pragma unroll
            for (int nt = 0; nt < 8; ++nt) {
                #pragma unroll
                for (int e = 0; e < 4; ++e) {
                    const float p = __expf(sacc[nt][e] - mn[e >> 1]);
                    sacc[nt][e] = p;
                    rs[e >> 1] += p;
                }
            }
            #pragma unroll
            for (int i = 0; i < 2; ++i) {
                rs[i] += __shfl_xor_sync(0xffffffffu, rs[i], 1);
                rs[i] += __shfl_xor_sync(0xffffffffu, rs[i], 2);
            }
            l[0] = al0 * l[0] + rs[0];  m[0] = mn[0];
            l[1] = al1 * l[1] + rs[1];  m[1] = mn[1];
            #pragma unroll
            for (int nt = 0; nt < 8; ++nt) {
                oacc[nt][0] *= al0; oacc[nt][1] *= al0;
                oacc[nt][2] *= al1; oacc[nt][3] *= al1;
            }

            // ---- pack P (C-frag -> A-frag) with split ----
            unsigned pah[4][4], pal[4][4];
            #pragma unroll
            for (int s = 0; s < 4; ++s) {
                split_pack(sacc[2*s  ][0], sacc[2*s  ][1], pah[s][0], pal[s][0]);
                split_pack(sacc[2*s  ][2], sacc[2*s  ][3], pah[s][1], pal[s][1]);
                split_pack(sacc[2*s+1][0], sacc[2*s+1][1], pah[s][2], pal[s][2]);
                split_pack(sacc[2*s+1][2], sacc[2*s+1][3], pah[s][3], pal[s][3]);
            }

            // ---- O += P V (3-pass split) ----
            #pragma unroll
            for (int s = 0; s < 4; ++s) {
                const int ko = s * 16 + 2 * q;
                #pragma unroll
                for (int ntg = 0; ntg < 2; ++ntg) {
                    unsigned vbh[4][2], vbl[4][2];
                    #pragma unroll
                    for (int j = 0; j < 4; ++j) {
                        const int nr = (ntg * 4 + j) * 8 + g;
                        vbh[j][0] = *(const unsigned*)(Vsh + nr * RS2 + ko);
                        vbh[j][1] = *(const unsigned*)(Vsh + nr * RS2 + ko + 8);
                        vbl[j][0] = *(const unsigned*)(Vsl + nr * RS2 + ko);
                        vbl[j][1] = *(const unsigned*)(Vsl + nr * RS2 + ko + 8);
                    }
                    #pragma unroll
                    for (int j = 0; j < 4; ++j) mma16816(oacc[ntg*4+j], pah[s], vbh[j]);
                    #pragma unroll
                    for (int j = 0; j < 4; ++j) mma16816(oacc[ntg*4+j], pah[s], vbl[j]);
                    #pragma unroll
                    for (int j = 0; j < 4; ++j) mma16816(oacc[ntg*4+j], pal[s], vbh[j]);
                }
            }
        }
        __syncthreads();
    }

    // ---- epilogue: y (split bf16) ----
    const int b = bh >> 4, h = bh & 15;
    #pragma unroll
    for (int i = 0; i < 2; ++i) {
        const int t = qbase + w * 16 + g + i * 8;
        const float inv = 1.f / l[i];
        const size_t base = ((size_t)(b * T_ + t)) * C_ + h * HD_;
        #pragma unroll
        for (int nt = 0; nt < 8; ++nt) {
            const float v0 = oacc[nt][i*2]     * inv;
            const float v1 = oacc[nt][i*2 + 1] * inv;
            unsigned hp, lp;
            split_pack(v0, v1, hp, lp);
            const int col = nt * 8 + 2 * q;
            *(unsigned*)(g_yhi + base + col) = hp;
            *(unsigned*)(g_ylo + base + col) = lp;
        }
    }
}

// ---------------------------------------------------------------------------
extern "C" void kernel_launch(void* const* d_in, const int* in_sizes, int n_in,
                              void* d_out, int out_size)
{
    const float* query = (const float*)d_in[0];
    const float* Wq = (const float*)d_in[1];  const float* bq = (const float*)d_in[2];
    const float* Wk = (const float*)d_in[3];  const float* bk = (const float*)d_in[4];
    const float* Wv = (const float*)d_in[5];  const float* bv = (const float*)d_in[6];
    const float* Wp = (const float*)d_in[7];  const float* bp = (const float*)d_in[8];

    __nv_bfloat16 *xhi, *xlo, *yhi, *ylo;
    __nv_bfloat16 *wqh, *wql, *wkh, *wkl, *wvh, *wvl, *wph, *wpl;
    cudaGetSymbolAddress((void**)&xhi, g_xhi); cudaGetSymbolAddress((void**)&xlo, g_xlo);
    cudaGetSymbolAddress((void**)&yhi, g_yhi); cudaGetSymbolAddress((void**)&ylo, g_ylo);
    cudaGetSymbolAddress((void**)&wqh, g_wqhi); cudaGetSymbolAddress((void**)&wql, g_wqlo);
    cudaGetSymbolAddress((void**)&wkh, g_wkhi); cudaGetSymbolAddress((void**)&wkl, g_wklo);
    cudaGetSymbolAddress((void**)&wvh, g_wvhi); cudaGetSymbolAddress((void**)&wvl, g_wvlo);
    cudaGetSymbolAddress((void**)&wph, g_wphi); cudaGetSymbolAddress((void**)&wpl, g_wplo);

    cudaFuncSetAttribute(proj_mma<0>, cudaFuncAttributeMaxDynamicSharedMemorySize, PROJ_SMEM);
    cudaFuncSetAttribute(proj_mma<1>, cudaFuncAttributeMaxDynamicSharedMemorySize, PROJ_SMEM);
    cudaFuncSetAttribute(proj_mma<2>, cudaFuncAttributeMaxDynamicSharedMemorySize, PROJ_SMEM);
    cudaFuncSetAttribute(proj_mma<3>, cudaFuncAttributeMaxDynamicSharedMemorySize, PROJ_SMEM);
    cudaFuncSetAttribute(attn_mma,    cudaFuncAttributeMaxDynamicSharedMemorySize, ATTN_SMEM);

    // splits
    split_kernel<<<2048, 256>>>(query, xhi, xlo, M_*C_);
    split_kernel<<<512, 256>>>(Wq, wqh, wql, C_*C_);
    split_kernel<<<512, 256>>>(Wk, wkh, wkl, C_*C_);
    split_kernel<<<512, 256>>>(Wv, wvh, wvl, C_*C_);
    split_kernel<<<512, 256>>>(Wp, wph, wpl, C_*C_);

    // q/k/v projections (emit split bf16; v transposed)
    const dim3 pg(C_/128, M_/128);   // (8, 64)
    proj_mma<0><<<pg, 256, PROJ_SMEM>>>(xhi, xlo, wqh, wql, bq, nullptr);
    proj_mma<1><<<pg, 256, PROJ_SMEM>>>(xhi, xlo, wkh, wkl, bk, nullptr);
    proj_mma<2><<<pg, 256, PROJ_SMEM>>>(xhi, xlo, wvh, wvl, bv, nullptr);

    // tensor-core flash attention (writes yhi/ylo)
    attn_mma<<<dim3(T_/128, B_*H_), 256, ATTN_SMEM>>>();

    // output projection (f32 out)
    proj_mma<3><<<pg, 256, PROJ_SMEM>>>(yhi, ylo, wph, wpl, bp, (float*)d_out);
}

// round 9
// speedup vs baseline: 4.3237x; 1.0277x over previous
#include <cuda_runtime.h>
#include <cuda_bf16.h>
#include <cstdint>

#define B_  4
#define T_  2048
#define C_  1024
#define H_  16
#define HD_ 64
#define M_  (B_*T_)   // 8192

// ---------------------------------------------------------------------------
// device scratch (bf16 split everywhere)
// ---------------------------------------------------------------------------
__device__ __nv_bfloat16 g_xhi[(size_t)M_*C_];
__device__ __nv_bfloat16 g_xlo[(size_t)M_*C_];
__device__ __nv_bfloat16 g_yhi[(size_t)M_*C_];
__device__ __nv_bfloat16 g_ylo[(size_t)M_*C_];
__device__ __nv_bfloat16 g_qhi[(size_t)B_*H_*T_*HD_], g_qlo[(size_t)B_*H_*T_*HD_];
__device__ __nv_bfloat16 g_khi[(size_t)B_*H_*T_*HD_], g_klo[(size_t)B_*H_*T_*HD_];
__device__ __nv_bfloat16 g_vthi[(size_t)B_*H_*HD_*T_], g_vtlo[(size_t)B_*H_*HD_*T_]; // [B,H,hd,T]
__device__ __nv_bfloat16 g_wqhi[(size_t)C_*C_], g_wqlo[(size_t)C_*C_];
__device__ __nv_bfloat16 g_wkhi[(size_t)C_*C_], g_wklo[(size_t)C_*C_];
__device__ __nv_bfloat16 g_wvhi[(size_t)C_*C_], g_wvlo[(size_t)C_*C_];
__device__ __nv_bfloat16 g_wphi[(size_t)C_*C_], g_wplo[(size_t)C_*C_];

// ---------------------------------------------------------------------------
// helpers
// ---------------------------------------------------------------------------
__device__ __forceinline__ unsigned smem_u32(const void* p) {
    unsigned a;
    asm("{ .reg .u64 t; cvta.to.shared.u64 t, %1; cvt.u32.u64 %0, t; }"
        : "=r"(a) : "l"(p));
    return a;
}
__device__ __forceinline__ void cpa16(unsigned s, const void* g) {
    asm volatile("cp.async.cg.shared.global [%0], [%1], 16;" :: "r"(s), "l"(g));
}
__device__ __forceinline__ void cpa_commit() {
    asm volatile("cp.async.commit_group;" ::: "memory");
}
__device__ __forceinline__ void cpa_wait1() {
    asm volatile("cp.async.wait_group 1;" ::: "memory");
}
__device__ __forceinline__ void cpa_wait0() {
    asm volatile("cp.async.wait_group 0;" ::: "memory");
}
__device__ __forceinline__ void mma16816(float* d, const unsigned* a, const unsigned* b) {
    asm volatile(
        "mma.sync.aligned.m16n8k16.row.col.f32.bf16.bf16.f32 "
        "{%0,%1,%2,%3}, {%4,%5,%6,%7}, {%8,%9}, {%0,%1,%2,%3};"
        : "+f"(d[0]), "+f"(d[1]), "+f"(d[2]), "+f"(d[3])
        : "r"(a[0]), "r"(a[1]), "r"(a[2]), "r"(a[3]), "r"(b[0]), "r"(b[1]));
}
__device__ __forceinline__ void ldsm_x4(unsigned* r, unsigned saddr) {
    asm volatile("ldmatrix.sync.aligned.m8n8.x4.shared.b16 {%0,%1,%2,%3}, [%4];"
        : "=r"(r[0]), "=r"(r[1]), "=r"(r[2]), "=r"(r[3]) : "r"(saddr));
}
__device__ __forceinline__ unsigned pack_bf(float lo, float hi) {
    unsigned d;
    asm("cvt.rn.bf16x2.f32 %0, %1, %2;" : "=r"(d) : "f"(hi), "f"(lo));
    return d;
}
__device__ __forceinline__ void split_pack(float p0, float p1, unsigned& hi, unsigned& lo) {
    hi = pack_bf(p0, p1);
    __nv_bfloat162 h2 = *reinterpret_cast<__nv_bfloat162*>(&hi);
    lo = pack_bf(p0 - __bfloat162float(h2.x), p1 - __bfloat162float(h2.y));
}

// ---------------------------------------------------------------------------
// split: fp32 -> (hi bf16, lo bf16)
// ---------------------------------------------------------------------------
__global__ __launch_bounds__(256) void split_kernel(
    const float* __restrict__ src, __nv_bfloat16* __restrict__ hi,
    __nv_bfloat16* __restrict__ lo, int n)
{
    int i = blockIdx.x * blockDim.x + threadIdx.x;
    const int stride = gridDim.x * blockDim.x;
    for (; i < n; i += stride) {
        const float x = src[i];
        const __nv_bfloat16 h = __float2bfloat16(x);
        hi[i] = h;
        lo[i] = __float2bfloat16(x - __bfloat162float(h));
    }
}

// ---------------------------------------------------------------------------
// Shared GEMM mainloop (split-bf16 3-pass, ldmatrix fragment loads)
// ---------------------------------------------------------------------------
#define RS    40
#define ABYTES (128*RS*2)
#define BUFB  (4*ABYTES)
#define PROJ_SMEM (2*BUFB)             // 81920 B

__device__ __forceinline__ void gemm_mainloop(
    const __nv_bfloat16* __restrict__ Ahi, const __nv_bfloat16* __restrict__ Alo,
    const __nv_bfloat16* __restrict__ Bhi, const __nv_bfloat16* __restrict__ Blo,
    int bm, int bn, unsigned sb, int tid, int lane,
    int wm, int wn, float acc[2][8][4])
{
    const int lrow = lane & 7;
    const int tsel = lane >> 3;
    const int b_nt = tsel >> 1, b_kh = tsel & 1;   // B-frag tile decode
    const int a_rh = tsel & 1,  a_kh = tsel >> 1;  // A-frag tile decode

    const __nv_bfloat16* srcs[4] = {Ahi, Alo, Bhi, Blo};

    auto load_chunk = [&](int k0, int buf) {
        const unsigned boff = (unsigned)buf * BUFB;
        #pragma unroll
        for (int it = 0; it < 8; ++it) {
            const int u   = it * 256 + tid;
            const int arr = u >> 9;
            const int r   = (u >> 2) & 127;
            const int seg = u & 3;
            const int rowg = ((arr < 2) ? bm : bn) + r;
            const void* gp = (const char*)srcs[arr] + ((size_t)rowg * C_ + k0 + seg * 8) * 2;
            const unsigned sp = sb + boff + (unsigned)arr * ABYTES
                              + (unsigned)(r * RS + seg * 8) * 2;
            cpa16(sp, gp);
        }
        cpa_commit();
    };

    load_chunk(0, 0);

    for (int c = 0; c < 32; ++c) {
        if (c < 31) load_chunk((c + 1) * 32, (c + 1) & 1);
        if (c < 31) cpa_wait1(); else cpa_wait0();
        __syncthreads();

        const unsigned sAh = sb + (unsigned)(c & 1) * BUFB;
        const unsigned sAl = sAh + ABYTES;
        const unsigned sBh = sAh + 2 * ABYTES;
        const unsigned sBl = sAh + 3 * ABYTES;

        #pragma unroll
        for (int ks = 0; ks < 2; ++ks) {
            const int ko = ks * 16;
            unsigned bh[8][2], bl[8][2];
            #pragma unroll
            for (int nb = 0; nb < 4; ++nb) {
                const int nrow = wn * 64 + (nb * 2 + b_nt) * 8 + lrow;
                ldsm_x4(&bh[nb*2][0], sBh + (unsigned)(nrow * RS + ko + b_kh * 8) * 2);
                ldsm_x4(&bl[nb*2][0], sBl + (unsigned)(nrow * RS + ko + b_kh * 8) * 2);
            }
            #pragma unroll
            for (int mt = 0; mt < 2; ++mt) {
                const int arow = wm * 32 + mt * 16 + a_rh * 8 + lrow;
                unsigned ah[4], al[4];
                ldsm_x4(ah, sAh + (unsigned)(arow * RS + ko + a_kh * 8) * 2);
                ldsm_x4(al, sAl + (unsigned)(arow * RS + ko + a_kh * 8) * 2);
                #pragma unroll
                for (int nt = 0; nt < 8; ++nt) mma16816(acc[mt][nt], ah, bh[nt]);
                #pragma unroll
                for (int nt = 0; nt < 8; ++nt) mma16816(acc[mt][nt], ah, bl[nt]);
                #pragma unroll
                for (int nt = 0; nt < 8; ++nt) mma16816(acc[mt][nt], al, bh[nt]);
            }
        }
        __syncthreads();
    }
}

// ---------------------------------------------------------------------------
// Fused QKV projection: grid (24, 64). blockIdx.x: [0,8)->Q [8,16)->K [16,24)->V
// ---------------------------------------------------------------------------
__global__ __launch_bounds__(256, 1) void proj_qkv(
    const __nv_bfloat16* __restrict__ Xhi, const __nv_bfloat16* __restrict__ Xlo,
    const float* __restrict__ bq, const float* __restrict__ bk,
    const float* __restrict__ bv)
{
    extern __shared__ char smc[];
    const int tid  = threadIdx.x;
    const int wid  = tid >> 5, lane = tid & 31;
    const int g    = lane >> 2, q = lane & 3;
    const int wm   = wid >> 1, wn = wid & 1;
    const int wsel = blockIdx.x >> 3;
    const int bn   = (blockIdx.x & 7) * 128;
    const int bm   = blockIdx.y * 128;
    const unsigned sb = smem_u32(smc);

    const __nv_bfloat16* Bhi = (wsel == 0) ? g_wqhi : (wsel == 1) ? g_wkhi : g_wvhi;
    const __nv_bfloat16* Blo = (wsel == 0) ? g_wqlo : (wsel == 1) ? g_wklo : g_wvlo;
    const float* bias = (wsel == 0) ? bq : (wsel == 1) ? bk : bv;

    float acc[2][8][4] = {};
    gemm_mainloop(Xhi, Xlo, Bhi, Blo, bm, bn, sb, tid, lane, wm, wn, acc);

    #pragma unroll
    for (int mt = 0; mt < 2; ++mt) {
        #pragma unroll
        for (int nt = 0; nt < 8; ++nt) {
            const int col = bn + wn * 64 + nt * 8 + q * 2;
            const float b0 = bias[col], b1 = bias[col + 1];
            #pragma unroll
            for (int hrow = 0; hrow < 2; ++hrow) {
                const int row = bm + wm * 32 + mt * 16 + g + hrow * 8;
                const float v0 = acc[mt][nt][hrow * 2 + 0] + b0;
                const float v1 = acc[mt][nt][hrow * 2 + 1] + b1;
                const __nv_bfloat16 h0 = __float2bfloat16(v0);
                const __nv_bfloat16 h1 = __float2bfloat16(v1);
                const __nv_bfloat16 l0 = __float2bfloat16(v0 - __bfloat162float(h0));
                const __nv_bfloat16 l1 = __float2bfloat16(v1 - __bfloat162float(h1));
                const int bb = row >> 11, t = row & 2047;
                const int hh = col >> 6,  d = col & 63;
                if (wsel < 2) {
                    const size_t idx = (((size_t)(bb * H_ + hh)) * T_ + t) * HD_ + d;
                    __nv_bfloat16* dh = (wsel == 0) ? g_qhi : g_khi;
                    __nv_bfloat16* dl = (wsel == 0) ? g_qlo : g_klo;
                    *(__nv_bfloat162*)(dh + idx) = __halves2bfloat162(h0, h1);
                    *(__nv_bfloat162*)(dl + idx) = __halves2bfloat162(l0, l1);
                } else {
                    const size_t idx = (((size_t)(bb * H_ + hh)) * HD_ + d) * T_ + t;
                    g_vthi[idx] = h0;  g_vthi[idx + T_] = h1;
                    g_vtlo[idx] = l0;  g_vtlo[idx + T_] = l1;
                }
            }
        }
    }
}

// ---------------------------------------------------------------------------
// Output projection: y(split bf16) @ Wp^T + bp -> f32 out
// ---------------------------------------------------------------------------
__global__ __launch_bounds__(256, 1) void proj_out(
    const __nv_bfloat16* __restrict__ Yhi, const __nv_bfloat16* __restrict__ Ylo,
    const float* __restrict__ bias, float* __restrict__ outp)
{
    extern __shared__ char smc[];
    const int tid  = threadIdx.x;
    const int wid  = tid >> 5, lane = tid & 31;
    const int g    = lane >> 2, q = lane & 3;
    const int wm   = wid >> 1, wn = wid & 1;
    const int bn   = blockIdx.x * 128;
    const int bm   = blockIdx.y * 128;
    const unsigned sb = smem_u32(smc);

    float acc[2][8][4] = {};
    gemm_mainloop(Yhi, Ylo, g_wphi, g_wplo, bm, bn, sb, tid, lane, wm, wn, acc);

    #pragma unroll
    for (int mt = 0; mt < 2; ++mt) {
        #pragma unroll
        for (int nt = 0; nt < 8; ++nt) {
            const int col = bn + wn * 64 + nt * 8 + q * 2;
            const float b0 = bias[col], b1 = bias[col + 1];
            #pragma unroll
            for (int hrow = 0; hrow < 2; ++hrow) {
                const int row = bm + wm * 32 + mt * 16 + g + hrow * 8;
                outp[(size_t)row * C_ + col]     = acc[mt][nt][hrow * 2 + 0] + b0;
                outp[(size_t)row * C_ + col + 1] = acc[mt][nt][hrow * 2 + 1] + b1;
            }
        }
    }
}

// ---------------------------------------------------------------------------
// Flash attention on mma.sync, split-bf16 3-pass, ldmatrix fragment loads.
// ---------------------------------------------------------------------------
#define RS2   72
#define ARR2B (64*RS2*2)      // 9216
#define TBUF  (4*ARR2B)       // 36864
#define ATTN_SMEM (2*TBUF)    // 73728

__global__ __launch_bounds__(256) void attn_mma()
{
    extern __shared__ char smc[];
    const int tid = threadIdx.x;
    const int w = tid >> 5, lane = tid & 31;
    const int g = lane >> 2, q = lane & 3;
    const int lrow = lane & 7;
    const int tsel = lane >> 3;
    const int b_nt = tsel >> 1, b_kh = tsel & 1;
    const int blk = blockIdx.x, bh = blockIdx.y;
    const int qbase = blk * 128;
    const unsigned sb = smem_u32(smc);

    const __nv_bfloat16* Qh = g_qhi + (size_t)bh * T_ * HD_ + (size_t)(qbase + w * 16) * HD_;
    const __nv_bfloat16* Ql = g_qlo + (size_t)bh * T_ * HD_ + (size_t)(qbase + w * 16) * HD_;
    const __nv_bfloat16* Kh = g_khi + (size_t)bh * T_ * HD_;
    const __nv_bfloat16* Kl = g_klo + (size_t)bh * T_ * HD_;
    const __nv_bfloat16* Vh = g_vthi + (size_t)bh * HD_ * T_;
    const __nv_bfloat16* Vl = g_vtlo + (size_t)bh * HD_ * T_;

    // Q fragments resident in registers (a-frag layout)
    unsigned qh[4][4], ql[4][4];
    #pragma unroll
    for (int s = 0; s < 4; ++s) {
        const int c0 = s * 16 + 2 * q;
        qh[s][0] = *(const unsigned*)(Qh + (g    ) * HD_ + c0);
        qh[s][1] = *(const unsigned*)(Qh + (g + 8) * HD_ + c0);
        qh[s][2] = *(const unsigned*)(Qh + (g    ) * HD_ + c0 + 8);
        qh[s][3] = *(const unsigned*)(Qh + (g + 8) * HD_ + c0 + 8);
        ql[s][0] = *(const unsigned*)(Ql + (g    ) * HD_ + c0);
        ql[s][1] = *(const unsigned*)(Ql + (g + 8) * HD_ + c0);
        ql[s][2] = *(const unsigned*)(Ql + (g    ) * HD_ + c0 + 8);
        ql[s][3] = *(const unsigned*)(Ql + (g + 8) * HD_ + c0 + 8);
    }

    float oacc[8][4] = {};
    float m[2] = {-1e30f, -1e30f}, l[2] = {0.f, 0.f};

    auto load_tile = [&](int jt, int buf) {
        const int jb = jt * 64;
        const unsigned boff = (unsigned)buf * TBUF;
        #pragma unroll
        for (int it = 0; it < 8; ++it) {
            const int u = it * 256 + tid;
            const int arr = u >> 9;
            const int r   = (u >> 3) & 63;
            const int seg = u & 7;
            const __nv_bfloat16* src = (arr == 0) ? Kh : (arr == 1) ? Kl
                                      : (arr == 2) ? Vh : Vl;
            const void* gp = (arr < 2)
                ? (const void*)(src + ((size_t)(jb + r)) * HD_ + seg * 8)
                : (const void*)(src + ((size_t)r) * T_ + jb + seg * 8);
            const unsigned sp = sb + boff + (unsigned)arr * ARR2B
                              + (unsigned)(r * RS2 + seg * 8) * 2;
            cpa16(sp, gp);
        }
        cpa_commit();
    };

    const int ntiles = 2 * blk + 2;
    load_tile(0, 0);

    for (int jt = 0; jt < ntiles; ++jt) {
        if (jt < ntiles - 1) load_tile(jt + 1, (jt + 1) & 1);
        if (jt < ntiles - 1) cpa_wait1(); else cpa_wait0();
        __syncthreads();

        const int jb = jt * 64;
        if (jb <= qbase + w * 16 + 15) {
            const unsigned bufo = sb + (unsigned)(jt & 1) * TBUF;
            const unsigned sKh = bufo, sKl = bufo + ARR2B;
            const unsigned sVh = bufo + 2 * ARR2B, sVl = bufo + 3 * ARR2B;

            // ---- S = Q K^T (3-pass split) ----
            float sacc[8][4] = {};
            #pragma unroll
            for (int s = 0; s < 4; ++s) {
                const int ko = s * 16;
                #pragma unroll
                for (int ntg = 0; ntg < 2; ++ntg) {
                    unsigned kbh[4][2], kbl[4][2];
                    #pragma unroll
                    for (int p = 0; p < 2; ++p) {
                        const int nr = (ntg * 4 + p * 2 + b_nt) * 8 + lrow;
                        ldsm_x4(&kbh[p*2][0], sKh + (unsigned)(nr * RS2 + ko + b_kh * 8) * 2);
                        ldsm_x4(&kbl[p*2][0], sKl + (unsigned)(nr * RS2 + ko + b_kh * 8) * 2);
                    }
                    #pragma unroll
                    for (int j = 0; j < 4; ++j) mma16816(sacc[ntg*4+j], qh[s], kbh[j]);
                    #pragma unroll
                    for (int j = 0; j < 4; ++j) mma16816(sacc[ntg*4+j], qh[s], kbl[j]);
                    #pragma unroll
                    for (int j = 0; j < 4; ++j) mma16816(sacc[ntg*4+j], ql[s], kbh[j]);
                }
            }

            // ---- scale + causal mask ----
            const bool needmask = (jb + 63 > qbase + w * 16);
            #pragma unroll
            for (int nt = 0; nt < 8; ++nt) {
                #pragma unroll
                for (int e = 0; e < 4; ++e) {
                    float v = sacc[nt][e] * 0.125f;
                    if (needmask) {
                        const int col = jb + nt * 8 + 2 * q + (e & 1);
                        const int row = qbase + w * 16 + g + (e >> 1) * 8;
                        if (col > row) v = -1e30f;
                    }
                    sacc[nt][e] = v;
                }
            }

            // ---- online softmax ----
            float mn[2];
            #pragma unroll
            for (int i = 0; i < 2; ++i) {
                float rm = sacc[0][i*2];
                #pragma unroll
                for (int nt = 0; nt < 8; ++nt) {
                    rm = fmaxf(rm, sacc[nt][i*2]);
                    rm = fmaxf(rm, sacc[nt][i*2+1]);
                }
                rm = fmaxf(rm, __shfl_xor_sync(0xffffffffu, rm, 1));
                rm = fmaxf(rm, __shfl_xor_sync(0xffffffffu, rm, 2));
                mn[i] = fmaxf(m[i], rm);
            }
            const float al0 = __expf(m[0] - mn[0]);
            const float al1 = __expf(m[1] - mn[1]);
            float rs[2] = {0.f, 0.f};
            #pragma unroll
            for (int nt = 0; nt < 8; ++nt) {
                #pragma unroll
                for (int e = 0; e < 4; ++e) {
                    const float p = __expf(sacc[nt][e] - mn[e >> 1]);
                    sacc[nt][e] = p;
                    rs[e >> 1] += p;
                }
            }
            #pragma unroll
            for (int i = 0; i < 2; ++i) {
                rs[i] += __shfl_xor_sync(0xffffffffu, rs[i], 1);
                rs[i] += __shfl_xor_sync(0xffffffffu, rs[i], 2);
            }
            l[0] = al0 * l[0] + rs[0];  m[0] = mn[0];
            l[1] = al1 * l[1] + rs[1];  m[1] = mn[1];
            #pragma unroll
            for (int nt = 0; nt < 8; ++nt) {
                oacc[nt][0] *= al0; oacc[nt][1] *= al0;
                oacc[nt][2] *= al1; oacc[nt][3] *= al1;
            }

            // ---- pack P (C-frag -> A-frag) with split ----
            unsigned pah[4][4], pal[4][4];
            #pragma unroll
            for (int s = 0; s < 4; ++s) {
                split_pack(sacc[2*s  ][0], sacc[2*s  ][1], pah[s][0], pal[s][0]);
                split_pack(sacc[2*s  ][2], sacc[2*s  ][3], pah[s][1], pal[s][1]);
                split_pack(sacc[2*s+1][0], sacc[2*s+1][1], pah[s][2], pal[s][2]);
                split_pack(sacc[2*s+1][2], sacc[2*s+1][3], pah[s][3], pal[s][3]);
            }

            // ---- O += P V (3-pass split) ----
            #pragma unroll
            for (int s = 0; s < 4; ++s) {
                const int ko = s * 16;
                #pragma unroll
                for (int ntg = 0; ntg < 2; ++ntg) {
                    unsigned vbh[4][2], vbl[4][2];
                    #pragma unroll
                    for (int p = 0; p < 2; ++p) {
                        const int nr = (ntg * 4 + p * 2 + b_nt) * 8 + lrow;
                        ldsm_x4(&vbh[p*2][0], sVh + (unsigned)(nr * RS2 + ko + b_kh * 8) * 2);
                        ldsm_x4(&vbl[p*2][0], sVl + (unsigned)(nr * RS2 + ko + b_kh * 8) * 2);
                    }
                    #pragma unroll
                    for (int j = 0; j < 4; ++j) mma16816(oacc[ntg*4+j], pah[s], vbh[j]);
                    #pragma unroll
                    for (int j = 0; j < 4; ++j) mma16816(oacc[ntg*4+j], pah[s], vbl[j]);
                    #pragma unroll
                    for (int j = 0; j < 4; ++j) mma16816(oacc[ntg*4+j], pal[s], vbh[j]);
                }
            }
        }
        __syncthreads();
    }

    // ---- epilogue: y (split bf16) ----
    const int b = bh >> 4, h = bh & 15;
    #pragma unroll
    for (int i = 0; i < 2; ++i) {
        const int t = qbase + w * 16 + g + i * 8;
        const float inv = 1.f / l[i];
        const size_t base = ((size_t)(b * T_ + t)) * C_ + h * HD_;
        #pragma unroll
        for (int nt = 0; nt < 8; ++nt) {
            const float v0 = oacc[nt][i*2]     * inv;
            const float v1 = oacc[nt][i*2 + 1] * inv;
            unsigned hp, lp;
            split_pack(v0, v1, hp, lp);
            const int col = nt * 8 + 2 * q;
            *(unsigned*)(g_yhi + base + col) = hp;
            *(unsigned*)(g_ylo + base + col) = lp;
        }
    }
}

// ---------------------------------------------------------------------------
extern "C" void kernel_launch(void* const* d_in, const int* in_sizes, int n_in,
                              void* d_out, int out_size)
{
    const float* query = (const float*)d_in[0];
    const float* Wq = (const float*)d_in[1];  const float* bq = (const float*)d_in[2];
    const float* Wk = (const float*)d_in[3];  const float* bk = (const float*)d_in[4];
    const float* Wv = (const float*)d_in[5];  const float* bv = (const float*)d_in[6];
    const float* Wp = (const float*)d_in[7];  const float* bp = (const float*)d_in[8];

    __nv_bfloat16 *xhi, *xlo, *yhi, *ylo;
    __nv_bfloat16 *wqh, *wql, *wkh, *wkl, *wvh, *wvl, *wph, *wpl;
    cudaGetSymbolAddress((void**)&xhi, g_xhi); cudaGetSymbolAddress((void**)&xlo, g_xlo);
    cudaGetSymbolAddress((void**)&yhi, g_yhi); cudaGetSymbolAddress((void**)&ylo, g_ylo);
    cudaGetSymbolAddress((void**)&wqh, g_wqhi); cudaGetSymbolAddress((void**)&wql, g_wqlo);
    cudaGetSymbolAddress((void**)&wkh, g_wkhi); cudaGetSymbolAddress((void**)&wkl, g_wklo);
    cudaGetSymbolAddress((void**)&wvh, g_wvhi); cudaGetSymbolAddress((void**)&wvl, g_wvlo);
    cudaGetSymbolAddress((void**)&wph, g_wphi); cudaGetSymbolAddress((void**)&wpl, g_wplo);

    cudaFuncSetAttribute(proj_qkv, cudaFuncAttributeMaxDynamicSharedMemorySize, PROJ_SMEM);
    cudaFuncSetAttribute(proj_out, cudaFuncAttributeMaxDynamicSharedMemorySize, PROJ_SMEM);
    cudaFuncSetAttribute(attn_mma, cudaFuncAttributeMaxDynamicSharedMemorySize, ATTN_SMEM);

    // splits
    split_kernel<<<2048, 256>>>(query, xhi, xlo, M_*C_);
    split_kernel<<<512, 256>>>(Wq, wqh, wql, C_*C_);
    split_kernel<<<512, 256>>>(Wk, wkh, wkl, C_*C_);
    split_kernel<<<512, 256>>>(Wv, wvh, wvl, C_*C_);
    split_kernel<<<512, 256>>>(Wp, wph, wpl, C_*C_);

    // fused QKV projection (one launch, 1536 CTAs)
    proj_qkv<<<dim3(24, M_/128), 256, PROJ_SMEM>>>(xhi, xlo, bq, bk, bv);

    // tensor-core flash attention (writes yhi/ylo)
    attn_mma<<<dim3(T_/128, B_*H_), 256, ATTN_SMEM>>>();

    // output projection (f32 out)
    proj_out<<<dim3(C_/128, M_/128), 256, PROJ_SMEM>>>(yhi, ylo, bp, (float*)d_out);
}

// round 11
// speedup vs baseline: 4.9473x; 1.1442x over previous
#include <cuda_runtime.h>
#include <cuda_bf16.h>
#include <cstdint>

#define B_  4
#define T_  2048
#define C_  1024
#define H_  16
#define HD_ 64
#define M_  (B_*T_)   // 8192

// ---------------------------------------------------------------------------
// device scratch (bf16 split everywhere)
// ---------------------------------------------------------------------------
__device__ __nv_bfloat16 g_xhi[(size_t)M_*C_];
__device__ __nv_bfloat16 g_xlo[(size_t)M_*C_];
__device__ __nv_bfloat16 g_yhi[(size_t)M_*C_];
__device__ __nv_bfloat16 g_ylo[(size_t)M_*C_];
__device__ __nv_bfloat16 g_qhi[(size_t)B_*H_*T_*HD_], g_qlo[(size_t)B_*H_*T_*HD_];
__device__ __nv_bfloat16 g_khi[(size_t)B_*H_*T_*HD_], g_klo[(size_t)B_*H_*T_*HD_];
__device__ __nv_bfloat16 g_vthi[(size_t)B_*H_*HD_*T_], g_vtlo[(size_t)B_*H_*HD_*T_]; // [B,H,hd,T]
__device__ __nv_bfloat16 g_wqhi[(size_t)C_*C_], g_wqlo[(size_t)C_*C_];
__device__ __nv_bfloat16 g_wkhi[(size_t)C_*C_], g_wklo[(size_t)C_*C_];
__device__ __nv_bfloat16 g_wvhi[(size_t)C_*C_], g_wvlo[(size_t)C_*C_];
__device__ __nv_bfloat16 g_wphi[(size_t)C_*C_], g_wplo[(size_t)C_*C_];

// ---------------------------------------------------------------------------
// helpers
// ---------------------------------------------------------------------------
__device__ __forceinline__ unsigned smem_u32(const void* p) {
    unsigned a;
    asm("{ .reg .u64 t; cvta.to.shared.u64 t, %1; cvt.u32.u64 %0, t; }"
        : "=r"(a) : "l"(p));
    return a;
}
__device__ __forceinline__ void cpa16(unsigned s, const void* g) {
    asm volatile("cp.async.cg.shared.global [%0], [%1], 16;" :: "r"(s), "l"(g));
}
__device__ __forceinline__ void cpa_commit() {
    asm volatile("cp.async.commit_group;" ::: "memory");
}
__device__ __forceinline__ void cpa_wait1() {
    asm volatile("cp.async.wait_group 1;" ::: "memory");
}
__device__ __forceinline__ void cpa_wait0() {
    asm volatile("cp.async.wait_group 0;" ::: "memory");
}
__device__ __forceinline__ void mma16816(float* d, const unsigned* a, const unsigned* b) {
    asm volatile(
        "mma.sync.aligned.m16n8k16.row.col.f32.bf16.bf16.f32 "
        "{%0,%1,%2,%3}, {%4,%5,%6,%7}, {%8,%9}, {%0,%1,%2,%3};"
        : "+f"(d[0]), "+f"(d[1]), "+f"(d[2]), "+f"(d[3])
        : "r"(a[0]), "r"(a[1]), "r"(a[2]), "r"(a[3]), "r"(b[0]), "r"(b[1]));
}
__device__ __forceinline__ void ldsm_x4(unsigned* r, unsigned saddr) {
    asm volatile("ldmatrix.sync.aligned.m8n8.x4.shared.b16 {%0,%1,%2,%3}, [%4];"
        : "=r"(r[0]), "=r"(r[1]), "=r"(r[2]), "=r"(r[3]) : "r"(saddr));
}
__device__ __forceinline__ unsigned pack_bf(float lo, float hi) {
    unsigned d;
    asm("cvt.rn.bf16x2.f32 %0, %1, %2;" : "=r"(d) : "f"(hi), "f"(lo));
    return d;
}
__device__ __forceinline__ void split_pack(float p0, float p1, unsigned& hi, unsigned& lo) {
    hi = pack_bf(p0, p1);
    __nv_bfloat162 h2 = *reinterpret_cast<__nv_bfloat162*>(&hi);
    lo = pack_bf(p0 - __bfloat162float(h2.x), p1 - __bfloat162float(h2.y));
}

// ---------------------------------------------------------------------------
// split: fp32 -> (hi bf16, lo bf16)   (single-array + fused-4 variants)
// ---------------------------------------------------------------------------
__global__ __launch_bounds__(256) void split_kernel(
    const float* __restrict__ src, __nv_bfloat16* __restrict__ hi,
    __nv_bfloat16* __restrict__ lo, int n)
{
    int i = blockIdx.x * blockDim.x + threadIdx.x;
    const int stride = gridDim.x * blockDim.x;
    for (; i < n; i += stride) {
        const float x = src[i];
        const __nv_bfloat16 h = __float2bfloat16(x);
        hi[i] = h;
        lo[i] = __float2bfloat16(x - __bfloat162float(h));
    }
}

__global__ __launch_bounds__(256) void split4_kernel(
    const float* __restrict__ s0, const float* __restrict__ s1,
    const float* __restrict__ s2, const float* __restrict__ s3,
    __nv_bfloat16* __restrict__ h0, __nv_bfloat16* __restrict__ l0,
    __nv_bfloat16* __restrict__ h1, __nv_bfloat16* __restrict__ l1,
    __nv_bfloat16* __restrict__ h2, __nv_bfloat16* __restrict__ l2,
    __nv_bfloat16* __restrict__ h3, __nv_bfloat16* __restrict__ l3)
{
    const int n = C_ * C_;
    const int stride = gridDim.x * blockDim.x;
    for (int i = blockIdx.x * blockDim.x + threadIdx.x; i < n; i += stride) {
        #pragma unroll
        for (int a = 0; a < 4; ++a) {
            const float* s = (a==0)?s0:(a==1)?s1:(a==2)?s2:s3;
            __nv_bfloat16* hh = (a==0)?h0:(a==1)?h1:(a==2)?h2:h3;
            __nv_bfloat16* ll = (a==0)?l0:(a==1)?l1:(a==2)?l2:l3;
            const float x = s[i];
            const __nv_bfloat16 h = __float2bfloat16(x);
            hh[i] = h;
            ll[i] = __float2bfloat16(x - __bfloat162float(h));
        }
    }
}

// ---------------------------------------------------------------------------
// Shared GEMM mainloop (split-bf16 3-pass, ldmatrix fragment loads).
// B lo-frags loaded AFTER the hi*hi pass to shrink peak live registers
// (matters under the 128-reg cap from __launch_bounds__(256,2)).
// ---------------------------------------------------------------------------
#define RS    40
#define ABYTES (128*RS*2)
#define BUFB  (4*ABYTES)
#define PROJ_SMEM (2*BUFB)             // 81920 B  (x2 CTAs = 160KB/SM, fits)

__device__ __forceinline__ void gemm_mainloop(
    const __nv_bfloat16* __restrict__ Ahi, const __nv_bfloat16* __restrict__ Alo,
    const __nv_bfloat16* __restrict__ Bhi, const __nv_bfloat16* __restrict__ Blo,
    int bm, int bn, unsigned sb, int tid, int lane,
    int wm, int wn, float acc[2][8][4])
{
    const int lrow = lane & 7;
    const int tsel = lane >> 3;
    const int b_nt = tsel >> 1, b_kh = tsel & 1;   // B-frag tile decode
    const int a_rh = tsel & 1,  a_kh = tsel >> 1;  // A-frag tile decode

    const __nv_bfloat16* srcs[4] = {Ahi, Alo, Bhi, Blo};

    auto load_chunk = [&](int k0, int buf) {
        const unsigned boff = (unsigned)buf * BUFB;
        #pragma unroll
        for (int it = 0; it < 8; ++it) {
            const int u   = it * 256 + tid;
            const int arr = u >> 9;
            const int r   = (u >> 2) & 127;
            const int seg = u & 3;
            const int rowg = ((arr < 2) ? bm : bn) + r;
            const void* gp = (const char*)srcs[arr] + ((size_t)rowg * C_ + k0 + seg * 8) * 2;
            const unsigned sp = sb + boff + (unsigned)arr * ABYTES
                              + (unsigned)(r * RS + seg * 8) * 2;
            cpa16(sp, gp);
        }
        cpa_commit();
    };

    load_chunk(0, 0);

    for (int c = 0; c < 32; ++c) {
        if (c < 31) load_chunk((c + 1) * 32, (c + 1) & 1);
        if (c < 31) cpa_wait1(); else cpa_wait0();
        __syncthreads();

        const unsigned sAh = sb + (unsigned)(c & 1) * BUFB;
        const unsigned sAl = sAh + ABYTES;
        const unsigned sBh = sAh + 2 * ABYTES;
        const unsigned sBl = sAh + 3 * ABYTES;

        #pragma unroll
        for (int ks = 0; ks < 2; ++ks) {
            const int ko = ks * 16;
            unsigned bh[8][2];
            #pragma unroll
            for (int nb = 0; nb < 4; ++nb) {
                const int nrow = wn * 64 + (nb * 2 + b_nt) * 8 + lrow;
                ldsm_x4(&bh[nb*2][0], sBh + (unsigned)(nrow * RS + ko + b_kh * 8) * 2);
            }
            #pragma unroll
            for (int mt = 0; mt < 2; ++mt) {
                const int arow = wm * 32 + mt * 16 + a_rh * 8 + lrow;
                unsigned ah[4], al[4];
                ldsm_x4(ah, sAh + (unsigned)(arow * RS + ko + a_kh * 8) * 2);
                ldsm_x4(al, sAl + (unsigned)(arow * RS + ko + a_kh * 8) * 2);
                // hi*hi and lo*hi passes (use bh)
                #pragma unroll
                for (int nt = 0; nt < 8; ++nt) mma16816(acc[mt][nt], ah, bh[nt]);
                #pragma unroll
                for (int nt = 0; nt < 8; ++nt) mma16816(acc[mt][nt], al, bh[nt]);
            }
            // hi*lo pass: load bl AFTER bh passes (lower peak registers)
            unsigned bl[8][2];
            #pragma unroll
            for (int nb = 0; nb < 4; ++nb) {
                const int nrow = wn * 64 + (nb * 2 + b_nt) * 8 + lrow;
                ldsm_x4(&bl[nb*2][0], sBl + (unsigned)(nrow * RS + ko + b_kh * 8) * 2);
            }
            #pragma unroll
            for (int mt = 0; mt < 2; ++mt) {
                const int arow = wm * 32 + mt * 16 + a_rh * 8 + lrow;
                unsigned ah[4];
                ldsm_x4(ah, sAh + (unsigned)(arow * RS + ko + a_kh * 8) * 2);
                #pragma unroll
                for (int nt = 0; nt < 8; ++nt) mma16816(acc[mt][nt], ah, bl[nt]);
            }
        }
        __syncthreads();
    }
}

// ---------------------------------------------------------------------------
// Fused QKV projection: grid (24, 64). blockIdx.x: [0,8)->Q [8,16)->K [16,24)->V
// __launch_bounds__(256, 2): cap regs at 128 so 2 CTAs co-reside per SM.
// ---------------------------------------------------------------------------
__global__ __launch_bounds__(256, 2) void proj_qkv(
    const __nv_bfloat16* __restrict__ Xhi, const __nv_bfloat16* __restrict__ Xlo,
    const float* __restrict__ bq, const float* __restrict__ bk,
    const float* __restrict__ bv)
{
    extern __shared__ char smc[];
    const int tid  = threadIdx.x;
    const int wid  = tid >> 5, lane = tid & 31;
    const int g    = lane >> 2, q = lane & 3;
    const int wm   = wid >> 1, wn = wid & 1;
    const int wsel = blockIdx.x >> 3;
    const int bn   = (blockIdx.x & 7) * 128;
    const int bm   = blockIdx.y * 128;
    const unsigned sb = smem_u32(smc);

    const __nv_bfloat16* Bhi = (wsel == 0) ? g_wqhi : (wsel == 1) ? g_wkhi : g_wvhi;
    const __nv_bfloat16* Blo = (wsel == 0) ? g_wqlo : (wsel == 1) ? g_wklo : g_wvlo;
    const float* bias = (wsel == 0) ? bq : (wsel == 1) ? bk : bv;

    float acc[2][8][4] = {};
    gemm_mainloop(Xhi, Xlo, Bhi, Blo, bm, bn, sb, tid, lane, wm, wn, acc);

    #pragma unroll
    for (int mt = 0; mt < 2; ++mt) {
        #pragma unroll
        for (int nt = 0; nt < 8; ++nt) {
            const int col = bn + wn * 64 + nt * 8 + q * 2;
            const float b0 = bias[col], b1 = bias[col + 1];
            #pragma unroll
            for (int hrow = 0; hrow < 2; ++hrow) {
                const int row = bm + wm * 32 + mt * 16 + g + hrow * 8;
                const float v0 = acc[mt][nt][hrow * 2 + 0] + b0;
                const float v1 = acc[mt][nt][hrow * 2 + 1] + b1;
                const __nv_bfloat16 h0 = __float2bfloat16(v0);
                const __nv_bfloat16 h1 = __float2bfloat16(v1);
                const __nv_bfloat16 l0 = __float2bfloat16(v0 - __bfloat162float(h0));
                const __nv_bfloat16 l1 = __float2bfloat16(v1 - __bfloat162float(h1));
                const int bb = row >> 11, t = row & 2047;
                const int hh = col >> 6,  d = col & 63;
                if (wsel < 2) {
                    const size_t idx = (((size_t)(bb * H_ + hh)) * T_ + t) * HD_ + d;
                    __nv_bfloat16* dh = (wsel == 0) ? g_qhi : g_khi;
                    __nv_bfloat16* dl = (wsel == 0) ? g_qlo : g_klo;
                    *(__nv_bfloat162*)(dh + idx) = __halves2bfloat162(h0, h1);
                    *(__nv_bfloat162*)(dl + idx) = __halves2bfloat162(l0, l1);
                } else {
                    const size_t idx = (((size_t)(bb * H_ + hh)) * HD_ + d) * T_ + t;
                    g_vthi[idx] = h0;  g_vthi[idx + T_] = h1;
                    g_vtlo[idx] = l0;  g_vtlo[idx + T_] = l1;
                }
            }
        }
    }
}

// ---------------------------------------------------------------------------
// Output projection: y(split bf16) @ Wp^T + bp -> f32 out
// ---------------------------------------------------------------------------
__global__ __launch_bounds__(256, 2) void proj_out(
    const __nv_bfloat16* __restrict__ Yhi, const __nv_bfloat16* __restrict__ Ylo,
    const float* __restrict__ bias, float* __restrict__ outp)
{
    extern __shared__ char smc[];
    const int tid  = threadIdx.x;
    const int wid  = tid >> 5, lane = tid & 31;
    const int g    = lane >> 2, q = lane & 3;
    const int wm   = wid >> 1, wn = wid & 1;
    const int bn   = blockIdx.x * 128;
    const int bm   = blockIdx.y * 128;
    const unsigned sb = smem_u32(smc);

    float acc[2][8][4] = {};
    gemm_mainloop(Yhi, Ylo, g_wphi, g_wplo, bm, bn, sb, tid, lane, wm, wn, acc);

    #pragma unroll
    for (int mt = 0; mt < 2; ++mt) {
        #pragma unroll
        for (int nt = 0; nt < 8; ++nt) {
            const int col = bn + wn * 64 + nt * 8 + q * 2;
            const float b0 = bias[col], b1 = bias[col + 1];
            #pragma unroll
            for (int hrow = 0; hrow < 2; ++hrow) {
                const int row = bm + wm * 32 + mt * 16 + g + hrow * 8;
                outp[(size_t)row * C_ + col]     = acc[mt][nt][hrow * 2 + 0] + b0;
                outp[(size_t)row * C_ + col + 1] = acc[mt][nt][hrow * 2 + 1] + b1;
            }
        }
    }
}

// ---------------------------------------------------------------------------
// Flash attention on mma.sync, split-bf16 3-pass, ldmatrix fragment loads.
// ---------------------------------------------------------------------------
#define RS2   72
#define ARR2B (64*RS2*2)      // 9216
#define TBUF  (4*ARR2B)       // 36864
#define ATTN_SMEM (2*TBUF)    // 73728

__global__ __launch_bounds__(256) void attn_mma()
{
    extern __shared__ char smc[];
    const int tid = threadIdx.x;
    const int w = tid >> 5, lane = tid & 31;
    const int g = lane >> 2, q = lane & 3;
    const int lrow = lane & 7;
    const int tsel = lane >> 3;
    const int b_nt = tsel >> 1, b_kh = tsel & 1;
    const int blk = blockIdx.x, bh = blockIdx.y;
    const int qbase = blk * 128;
    const unsigned sb = smem_u32(smc);

    const __nv_bfloat16* Qh = g_qhi + (size_t)bh * T_ * HD_ + (size_t)(qbase + w * 16) * HD_;
    const __nv_bfloat16* Ql = g_qlo + (size_t)bh * T_ * HD_ + (size_t)(qbase + w * 16) * HD_;
    const __nv_bfloat16* Kh = g_khi + (size_t)bh * T_ * HD_;
    const __nv_bfloat16* Kl = g_klo + (size_t)bh * T_ * HD_;
    const __nv_bfloat16* Vh = g_vthi + (size_t)bh * HD_ * T_;
    const __nv_bfloat16* Vl = g_vtlo + (size_t)bh * HD_ * T_;

    unsigned qh[4][4], ql[4][4];
    #pragma unroll
    for (int s = 0; s < 4; ++s) {
        const int c0 = s * 16 + 2 * q;
        qh[s][0] = *(const unsigned*)(Qh + (g    ) * HD_ + c0);
        qh[s][1] = *(const unsigned*)(Qh + (g + 8) * HD_ + c0);
        qh[s][2] = *(const unsigned*)(Qh + (g    ) * HD_ + c0 + 8);
        qh[s][3] = *(const unsigned*)(Qh + (g + 8) * HD_ + c0 + 8);
        ql[s][0] = *(const unsigned*)(Ql + (g    ) * HD_ + c0);
        ql[s][1] = *(const unsigned*)(Ql + (g + 8) * HD_ + c0);
        ql[s][2] = *(const unsigned*)(Ql + (g    ) * HD_ + c0 + 8);
        ql[s][3] = *(const unsigned*)(Ql + (g + 8) * HD_ + c0 + 8);
    }

    float oacc[8][4] = {};
    float m[2] = {-1e30f, -1e30f}, l[2] = {0.f, 0.f};

    auto load_tile = [&](int jt, int buf) {
        const int jb = jt * 64;
        const unsigned boff = (unsigned)buf * TBUF;
        #pragma unroll
        for (int it = 0; it < 8; ++it) {
            const int u = it * 256 + tid;
            const int arr = u >> 9;
            const int r   = (u >> 3) & 63;
            const int seg = u & 7;
            const __nv_bfloat16* src = (arr == 0) ? Kh : (arr == 1) ? Kl
                                      : (arr == 2) ? Vh : Vl;
            const void* gp = (arr < 2)
                ? (const void*)(src + ((size_t)(jb + r)) * HD_ + seg * 8)
                : (const void*)(src + ((size_t)r) * T_ + jb + seg * 8);
            const unsigned sp = sb + boff + (unsigned)arr * ARR2B
                              + (unsigned)(r * RS2 + seg * 8) * 2;
            cpa16(sp, gp);
        }
        cpa_commit();
    };

    const int ntiles = 2 * blk + 2;
    load_tile(0, 0);

    for (int jt = 0; jt < ntiles; ++jt) {
        if (jt < ntiles - 1) load_tile(jt + 1, (jt + 1) & 1);
        if (jt < ntiles - 1) cpa_wait1(); else cpa_wait0();
        __syncthreads();

        const int jb = jt * 64;
        if (jb <= qbase + w * 16 + 15) {
            const unsigned bufo = sb + (unsigned)(jt & 1) * TBUF;
            const unsigned sKh = bufo, sKl = bufo + ARR2B;
            const unsigned sVh = bufo + 2 * ARR2B, sVl = bufo + 3 * ARR2B;

            float sacc[8][4] = {};
            #pragma unroll
            for (int s = 0; s < 4; ++s) {
                const int ko = s * 16;
                #pragma unroll
                for (int ntg = 0; ntg < 2; ++ntg) {
                    unsigned kbh[4][2], kbl[4][2];
                    #pragma unroll
                    for (int p = 0; p < 2; ++p) {
                        const int nr = (ntg * 4 + p * 2 + b_nt) * 8 + lrow;
                        ldsm_x4(&kbh[p*2][0], sKh + (unsigned)(nr * RS2 + ko + b_kh * 8) * 2);
                        ldsm_x4(&kbl[p*2][0], sKl + (unsigned)(nr * RS2 + ko + b_kh * 8) * 2);
                    }
                    #pragma unroll
                    for (int j = 0; j < 4; ++j) mma16816(sacc[ntg*4+j], qh[s], kbh[j]);
                    #pragma unroll
                    for (int j = 0; j < 4; ++j) mma16816(sacc[ntg*4+j], qh[s], kbl[j]);
                    #pragma unroll
                    for (int j = 0; j < 4; ++j) mma16816(sacc[ntg*4+j], ql[s], kbh[j]);
                }
            }

            const bool needmask = (jb + 63 > qbase + w * 16);
            #pragma unroll
            for (int nt = 0; nt < 8; ++nt) {
                #pragma unroll
                for (int e = 0; e < 4; ++e) {
                    float v = sacc[nt][e] * 0.125f;
                    if (needmask) {
                        const int col = jb + nt * 8 + 2 * q + (e & 1);
                        const int row = qbase + w * 16 + g + (e >> 1) * 8;
                        if (col > row) v = -1e30f;
                    }
                    sacc[nt][e] = v;
                }
            }

            float mn[2];
            #pragma unroll
            for (int i = 0; i < 2; ++i) {
                float rm = sacc[0][i*2];
                #pragma unroll
                for (int nt = 0; nt < 8; ++nt) {
                    rm = fmaxf(rm, sacc[nt][i*2]);
                    rm = fmaxf(rm, sacc[nt][i*2+1]);
                }
                rm = fmaxf(rm, __shfl_xor_sync(0xffffffffu, rm, 1));
                rm = fmaxf(rm, __shfl_xor_sync(0xffffffffu, rm, 2));
                mn[i] = fmaxf(m[i], rm);
            }
            const float al0 = __expf(m[0] - mn[0]);
            const float al1 = __expf(m[1] - mn[1]);
            float rs[2] = {0.f, 0.f};
            #pragma unroll
            for (int nt = 0; nt < 8; ++nt) {
                #pragma unroll
                for (int e = 0; e < 4; ++e) {
                    const float p = __expf(sacc[nt][e] - mn[e >> 1]);
                    sacc[nt][e] = p;
                    rs[e >> 1] += p;
                }
            }
            #pragma unroll
            for (int i = 0; i < 2; ++i) {
                rs[i] += __shfl_xor_sync(0xffffffffu, rs[i], 1);
                rs[i] += __shfl_xor_sync(0xffffffffu, rs[i], 2);
            }
            l[0] = al0 * l[0] + rs[0];  m[0] = mn[0];
            l[1] = al1 * l[1] + rs[1];  m[1] = mn[1];
            #pragma unroll
            for (int nt = 0; nt < 8; ++nt) {
                oacc[nt][0] *= al0; oacc[nt][1] *= al0;
                oacc[nt][2] *= al1; oacc[nt][3] *= al1;
            }

            unsigned pah[4][4], pal[4][4];
            #pragma unroll
            for (int s = 0; s < 4; ++s) {
                split_pack(sacc[2*s  ][0], sacc[2*s  ][1], pah[s][0], pal[s][0]);
                split_pack(sacc[2*s  ][2], sacc[2*s  ][3], pah[s][1], pal[s][1]);
                split_pack(sacc[2*s+1][0], sacc[2*s+1][1], pah[s][2], pal[s][2]);
                split_pack(sacc[2*s+1][2], sacc[2*s+1][3], pah[s][3], pal[s][3]);
            }

            #pragma unroll
            for (int s = 0; s < 4; ++s) {
                const int ko = s * 16;
                #pragma unroll
                for (int ntg = 0; ntg < 2; ++ntg) {
                    unsigned vbh[4][2], vbl[4][2];
                    #pragma unroll
                    for (int p = 0; p < 2; ++p) {
                        const int nr = (ntg * 4 + p * 2 + b_nt) * 8 + lrow;
                        ldsm_x4(&vbh[p*2][0], sVh + (unsigned)(nr * RS2 + ko + b_kh * 8) * 2);
                        ldsm_x4(&vbl[p*2][0], sVl + (unsigned)(nr * RS2 + ko + b_kh * 8) * 2);
                    }
                    #pragma unroll
                    for (int j = 0; j < 4; ++j) mma16816(oacc[ntg*4+j], pah[s], vbh[j]);
                    #pragma unroll
                    for (int j = 0; j < 4; ++j) mma16816(oacc[ntg*4+j], pah[s], vbl[j]);
                    #pragma unroll
                    for (int j = 0; j < 4; ++j) mma16816(oacc[ntg*4+j], pal[s], vbh[j]);
                }
            }
        }
        __syncthreads();
    }

    const int b = bh >> 4, h = bh & 15;
    #pragma unroll
    for (int i = 0; i < 2; ++i) {
        const int t = qbase + w * 16 + g + i * 8;
        const float inv = 1.f / l[i];
        const size_t base = ((size_t)(b * T_ + t)) * C_ + h * HD_;
        #pragma unroll
        for (int nt = 0; nt < 8; ++nt) {
            const float v0 = oacc[nt][i*2]     * inv;
            const float v1 = oacc[nt][i*2 + 1] * inv;
            unsigned hp, lp;
            split_pack(v0, v1, hp, lp);
            const int col = nt * 8 + 2 * q;
            *(unsigned*)(g_yhi + base + col) = hp;
            *(unsigned*)(g_ylo + base + col) = lp;
        }
    }
}

// ---------------------------------------------------------------------------
extern "C" void kernel_launch(void* const* d_in, const int* in_sizes, int n_in,
                              void* d_out, int out_size)
{
    const float* query = (const float*)d_in[0];
    const float* Wq = (const float*)d_in[1];  const float* bq = (const float*)d_in[2];
    const float* Wk = (const float*)d_in[3];  const float* bk = (const float*)d_in[4];
    const float* Wv = (const float*)d_in[5];  const float* bv = (const float*)d_in[6];
    const float* Wp = (const float*)d_in[7];  const float* bp = (const float*)d_in[8];

    __nv_bfloat16 *xhi, *xlo, *yhi, *ylo;
    __nv_bfloat16 *wqh, *wql, *wkh, *wkl, *wvh, *wvl, *wph, *wpl;
    cudaGetSymbolAddress((void**)&xhi, g_xhi); cudaGetSymbolAddress((void**)&xlo, g_xlo);
    cudaGetSymbolAddress((void**)&yhi, g_yhi); cudaGetSymbolAddress((void**)&ylo, g_ylo);
    cudaGetSymbolAddress((void**)&wqh, g_wqhi); cudaGetSymbolAddress((void**)&wql, g_wqlo);
    cudaGetSymbolAddress((void**)&wkh, g_wkhi); cudaGetSymbolAddress((void**)&wkl, g_wklo);
    cudaGetSymbolAddress((void**)&wvh, g_wvhi); cudaGetSymbolAddress((void**)&wvl, g_wvlo);
    cudaGetSymbolAddress((void**)&wph, g_wphi); cudaGetSymbolAddress((void**)&wpl, g_wplo);

    cudaFuncSetAttribute(proj_qkv, cudaFuncAttributeMaxDynamicSharedMemorySize, PROJ_SMEM);
    cudaFuncSetAttribute(proj_out, cudaFuncAttributeMaxDynamicSharedMemorySize, PROJ_SMEM);
    cudaFuncSetAttribute(attn_mma, cudaFuncAttributeMaxDynamicSharedMemorySize, ATTN_SMEM);

    // splits: x (big) + all 4 weights fused
    split_kernel<<<2048, 256>>>(query, xhi, xlo, M_*C_);
    split4_kernel<<<1024, 256>>>(Wq, Wk, Wv, Wp,
                                 wqh, wql, wkh, wkl, wvh, wvl, wph, wpl);

    // fused QKV projection (one launch, 1536 CTAs, 2 CTAs/SM)
    proj_qkv<<<dim3(24, M_/128), 256, PROJ_SMEM>>>(xhi, xlo, bq, bk, bv);

    // tensor-core flash attention (writes yhi/ylo)
    attn_mma<<<dim3(T_/128, B_*H_), 256, ATTN_SMEM>>>();

    // output projection (f32 out, 2 CTAs/SM)
    proj_out<<<dim3(C_/128, M_/128), 256, PROJ_SMEM>>>(yhi, ylo, bp, (float*)d_out);
}

// round 12
// speedup vs baseline: 5.0722x; 1.0253x over previous
#include <cuda_runtime.h>
#include <cuda_bf16.h>
#include <cstdint>

#define B_  4
#define T_  2048
#define C_  1024
#define H_  16
#define HD_ 64
#define M_  (B_*T_)   // 8192

// ---------------------------------------------------------------------------
// device scratch (bf16 split everywhere)
// ---------------------------------------------------------------------------
__device__ __nv_bfloat16 g_xhi[(size_t)M_*C_];
__device__ __nv_bfloat16 g_xlo[(size_t)M_*C_];
__device__ __nv_bfloat16 g_yhi[(size_t)M_*C_];
__device__ __nv_bfloat16 g_ylo[(size_t)M_*C_];
__device__ __nv_bfloat16 g_qhi[(size_t)B_*H_*T_*HD_], g_qlo[(size_t)B_*H_*T_*HD_];
__device__ __nv_bfloat16 g_khi[(size_t)B_*H_*T_*HD_], g_klo[(size_t)B_*H_*T_*HD_];
__device__ __nv_bfloat16 g_vthi[(size_t)B_*H_*HD_*T_], g_vtlo[(size_t)B_*H_*HD_*T_]; // [B,H,hd,T]
__device__ __nv_bfloat16 g_wqhi[(size_t)C_*C_], g_wqlo[(size_t)C_*C_];
__device__ __nv_bfloat16 g_wkhi[(size_t)C_*C_], g_wklo[(size_t)C_*C_];
__device__ __nv_bfloat16 g_wvhi[(size_t)C_*C_], g_wvlo[(size_t)C_*C_];
__device__ __nv_bfloat16 g_wphi[(size_t)C_*C_], g_wplo[(size_t)C_*C_];

// ---------------------------------------------------------------------------
// helpers
// ---------------------------------------------------------------------------
__device__ __forceinline__ unsigned smem_u32(const void* p) {
    unsigned a;
    asm("{ .reg .u64 t; cvta.to.shared.u64 t, %1; cvt.u32.u64 %0, t; }"
        : "=r"(a) : "l"(p));
    return a;
}
__device__ __forceinline__ void cpa16(unsigned s, const void* g) {
    asm volatile("cp.async.cg.shared.global [%0], [%1], 16;" :: "r"(s), "l"(g));
}
__device__ __forceinline__ void cpa_commit() {
    asm volatile("cp.async.commit_group;" ::: "memory");
}
__device__ __forceinline__ void cpa_wait1() {
    asm volatile("cp.async.wait_group 1;" ::: "memory");
}
__device__ __forceinline__ void cpa_wait0() {
    asm volatile("cp.async.wait_group 0;" ::: "memory");
}
__device__ __forceinline__ void mma16816(float* d, const unsigned* a, const unsigned* b) {
    asm volatile(
        "mma.sync.aligned.m16n8k16.row.col.f32.bf16.bf16.f32 "
        "{%0,%1,%2,%3}, {%4,%5,%6,%7}, {%8,%9}, {%0,%1,%2,%3};"
        : "+f"(d[0]), "+f"(d[1]), "+f"(d[2]), "+f"(d[3])
        : "r"(a[0]), "r"(a[1]), "r"(a[2]), "r"(a[3]), "r"(b[0]), "r"(b[1]));
}
__device__ __forceinline__ void ldsm_x4(unsigned* r, unsigned saddr) {
    asm volatile("ldmatrix.sync.aligned.m8n8.x4.shared.b16 {%0,%1,%2,%3}, [%4];"
        : "=r"(r[0]), "=r"(r[1]), "=r"(r[2]), "=r"(r[3]) : "r"(saddr));
}
__device__ __forceinline__ unsigned pack_bf(float lo, float hi) {
    unsigned d;
    asm("cvt.rn.bf16x2.f32 %0, %1, %2;" : "=r"(d) : "f"(hi), "f"(lo));
    return d;
}
__device__ __forceinline__ void split_pack(float p0, float p1, unsigned& hi, unsigned& lo) {
    hi = pack_bf(p0, p1);
    __nv_bfloat162 h2 = *reinterpret_cast<__nv_bfloat162*>(&hi);
    lo = pack_bf(p0 - __bfloat162float(h2.x), p1 - __bfloat162float(h2.y));
}

// ---------------------------------------------------------------------------
// split: fp32 -> (hi bf16, lo bf16)   (single-array + fused-4 variants)
// ---------------------------------------------------------------------------
__global__ __launch_bounds__(256) void split_kernel(
    const float* __restrict__ src, __nv_bfloat16* __restrict__ hi,
    __nv_bfloat16* __restrict__ lo, int n)
{
    int i = blockIdx.x * blockDim.x + threadIdx.x;
    const int stride = gridDim.x * blockDim.x;
    for (; i < n; i += stride) {
        const float x = src[i];
        const __nv_bfloat16 h = __float2bfloat16(x);
        hi[i] = h;
        lo[i] = __float2bfloat16(x - __bfloat162float(h));
    }
}

__global__ __launch_bounds__(256) void split4_kernel(
    const float* __restrict__ s0, const float* __restrict__ s1,
    const float* __restrict__ s2, const float* __restrict__ s3,
    __nv_bfloat16* __restrict__ h0, __nv_bfloat16* __restrict__ l0,
    __nv_bfloat16* __restrict__ h1, __nv_bfloat16* __restrict__ l1,
    __nv_bfloat16* __restrict__ h2, __nv_bfloat16* __restrict__ l2,
    __nv_bfloat16* __restrict__ h3, __nv_bfloat16* __restrict__ l3)
{
    const int n = C_ * C_;
    const int stride = gridDim.x * blockDim.x;
    for (int i = blockIdx.x * blockDim.x + threadIdx.x; i < n; i += stride) {
        #pragma unroll
        for (int a = 0; a < 4; ++a) {
            const float* s = (a==0)?s0:(a==1)?s1:(a==2)?s2:s3;
            __nv_bfloat16* hh = (a==0)?h0:(a==1)?h1:(a==2)?h2:h3;
            __nv_bfloat16* ll = (a==0)?l0:(a==1)?l1:(a==2)?l2:l3;
            const float x = s[i];
            const __nv_bfloat16 h = __float2bfloat16(x);
            hh[i] = h;
            ll[i] = __float2bfloat16(x - __bfloat162float(h));
        }
    }
}

// ---------------------------------------------------------------------------
// Shared GEMM mainloop (split-bf16 3-pass, ldmatrix fragment loads).
// ---------------------------------------------------------------------------
#define RS    40
#define ABYTES (128*RS*2)
#define BUFB  (4*ABYTES)
#define PROJ_SMEM (2*BUFB)             // 81920 B  (x2 CTAs = 160KB/SM, fits)

__device__ __forceinline__ void gemm_mainloop(
    const __nv_bfloat16* __restrict__ Ahi, const __nv_bfloat16* __restrict__ Alo,
    const __nv_bfloat16* __restrict__ Bhi, const __nv_bfloat16* __restrict__ Blo,
    int bm, int bn, unsigned sb, int tid, int lane,
    int wm, int wn, float acc[2][8][4])
{
    const int lrow = lane & 7;
    const int tsel = lane >> 3;
    const int b_nt = tsel >> 1, b_kh = tsel & 1;   // B-frag tile decode
    const int a_rh = tsel & 1,  a_kh = tsel >> 1;  // A-frag tile decode

    const __nv_bfloat16* srcs[4] = {Ahi, Alo, Bhi, Blo};

    auto load_chunk = [&](int k0, int buf) {
        const unsigned boff = (unsigned)buf * BUFB;
        #pragma unroll
        for (int it = 0; it < 8; ++it) {
            const int u   = it * 256 + tid;
            const int arr = u >> 9;
            const int r   = (u >> 2) & 127;
            const int seg = u & 3;
            const int rowg = ((arr < 2) ? bm : bn) + r;
            const void* gp = (const char*)srcs[arr] + ((size_t)rowg * C_ + k0 + seg * 8) * 2;
            const unsigned sp = sb + boff + (unsigned)arr * ABYTES
                              + (unsigned)(r * RS + seg * 8) * 2;
            cpa16(sp, gp);
        }
        cpa_commit();
    };

    load_chunk(0, 0);

    for (int c = 0; c < 32; ++c) {
        if (c < 31) load_chunk((c + 1) * 32, (c + 1) & 1);
        if (c < 31) cpa_wait1(); else cpa_wait0();
        __syncthreads();

        const unsigned sAh = sb + (unsigned)(c & 1) * BUFB;
        const unsigned sAl = sAh + ABYTES;
        const unsigned sBh = sAh + 2 * ABYTES;
        const unsigned sBl = sAh + 3 * ABYTES;

        #pragma unroll
        for (int ks = 0; ks < 2; ++ks) {
            const int ko = ks * 16;
            unsigned bh[8][2];
            #pragma unroll
            for (int nb = 0; nb < 4; ++nb) {
                const int nrow = wn * 64 + (nb * 2 + b_nt) * 8 + lrow;
                ldsm_x4(&bh[nb*2][0], sBh + (unsigned)(nrow * RS + ko + b_kh * 8) * 2);
            }
            #pragma unroll
            for (int mt = 0; mt < 2; ++mt) {
                const int arow = wm * 32 + mt * 16 + a_rh * 8 + lrow;
                unsigned ah[4], al[4];
                ldsm_x4(ah, sAh + (unsigned)(arow * RS + ko + a_kh * 8) * 2);
                ldsm_x4(al, sAl + (unsigned)(arow * RS + ko + a_kh * 8) * 2);
                #pragma unroll
                for (int nt = 0; nt < 8; ++nt) mma16816(acc[mt][nt], ah, bh[nt]);
                #pragma unroll
                for (int nt = 0; nt < 8; ++nt) mma16816(acc[mt][nt], al, bh[nt]);
            }
            // hi*lo pass: load bl AFTER bh passes (lower peak registers)
            unsigned bl[8][2];
            #pragma unroll
            for (int nb = 0; nb < 4; ++nb) {
                const int nrow = wn * 64 + (nb * 2 + b_nt) * 8 + lrow;
                ldsm_x4(&bl[nb*2][0], sBl + (unsigned)(nrow * RS + ko + b_kh * 8) * 2);
            }
            #pragma unroll
            for (int mt = 0; mt < 2; ++mt) {
                const int arow = wm * 32 + mt * 16 + a_rh * 8 + lrow;
                unsigned ah[4];
                ldsm_x4(ah, sAh + (unsigned)(arow * RS + ko + a_kh * 8) * 2);
                #pragma unroll
                for (int nt = 0; nt < 8; ++nt) mma16816(acc[mt][nt], ah, bl[nt]);
            }
        }
        __syncthreads();
    }
}

// ---------------------------------------------------------------------------
// Fused QKV projection: grid (24, 64). blockIdx.x: [0,8)->Q [8,16)->K [16,24)->V
// ---------------------------------------------------------------------------
__global__ __launch_bounds__(256, 2) void proj_qkv(
    const __nv_bfloat16* __restrict__ Xhi, const __nv_bfloat16* __restrict__ Xlo,
    const float* __restrict__ bq, const float* __restrict__ bk,
    const float* __restrict__ bv)
{
    extern __shared__ char smc[];
    const int tid  = threadIdx.x;
    const int wid  = tid >> 5, lane = tid & 31;
    const int g    = lane >> 2, q = lane & 3;
    const int wm   = wid >> 1, wn = wid & 1;
    const int wsel = blockIdx.x >> 3;
    const int bn   = (blockIdx.x & 7) * 128;
    const int bm   = blockIdx.y * 128;
    const unsigned sb = smem_u32(smc);

    const __nv_bfloat16* Bhi = (wsel == 0) ? g_wqhi : (wsel == 1) ? g_wkhi : g_wvhi;
    const __nv_bfloat16* Blo = (wsel == 0) ? g_wqlo : (wsel == 1) ? g_wklo : g_wvlo;
    const float* bias = (wsel == 0) ? bq : (wsel == 1) ? bk : bv;

    float acc[2][8][4] = {};
    gemm_mainloop(Xhi, Xlo, Bhi, Blo, bm, bn, sb, tid, lane, wm, wn, acc);

    #pragma unroll
    for (int mt = 0; mt < 2; ++mt) {
        #pragma unroll
        for (int nt = 0; nt < 8; ++nt) {
            const int col = bn + wn * 64 + nt * 8 + q * 2;
            const float b0 = bias[col], b1 = bias[col + 1];
            #pragma unroll
            for (int hrow = 0; hrow < 2; ++hrow) {
                const int row = bm + wm * 32 + mt * 16 + g + hrow * 8;
                const float v0 = acc[mt][nt][hrow * 2 + 0] + b0;
                const float v1 = acc[mt][nt][hrow * 2 + 1] + b1;
                const __nv_bfloat16 h0 = __float2bfloat16(v0);
                const __nv_bfloat16 h1 = __float2bfloat16(v1);
                const __nv_bfloat16 l0 = __float2bfloat16(v0 - __bfloat162float(h0));
                const __nv_bfloat16 l1 = __float2bfloat16(v1 - __bfloat162float(h1));
                const int bb = row >> 11, t = row & 2047;
                const int hh = col >> 6,  d = col & 63;
                if (wsel < 2) {
                    const size_t idx = (((size_t)(bb * H_ + hh)) * T_ + t) * HD_ + d;
                    __nv_bfloat16* dh = (wsel == 0) ? g_qhi : g_khi;
                    __nv_bfloat16* dl = (wsel == 0) ? g_qlo : g_klo;
                    *(__nv_bfloat162*)(dh + idx) = __halves2bfloat162(h0, h1);
                    *(__nv_bfloat162*)(dl + idx) = __halves2bfloat162(l0, l1);
                } else {
                    const size_t idx = (((size_t)(bb * H_ + hh)) * HD_ + d) * T_ + t;
                    g_vthi[idx] = h0;  g_vthi[idx + T_] = h1;
                    g_vtlo[idx] = l0;  g_vtlo[idx + T_] = l1;
                }
            }
        }
    }
}

// ---------------------------------------------------------------------------
// Output projection: y(split bf16) @ Wp^T + bp -> f32 out
// ---------------------------------------------------------------------------
__global__ __launch_bounds__(256, 2) void proj_out(
    const __nv_bfloat16* __restrict__ Yhi, const __nv_bfloat16* __restrict__ Ylo,
    const float* __restrict__ bias, float* __restrict__ outp)
{
    extern __shared__ char smc[];
    const int tid  = threadIdx.x;
    const int wid  = tid >> 5, lane = tid & 31;
    const int g    = lane >> 2, q = lane & 3;
    const int wm   = wid >> 1, wn = wid & 1;
    const int bn   = blockIdx.x * 128;
    const int bm   = blockIdx.y * 128;
    const unsigned sb = smem_u32(smc);

    float acc[2][8][4] = {};
    gemm_mainloop(Yhi, Ylo, g_wphi, g_wplo, bm, bn, sb, tid, lane, wm, wn, acc);

    #pragma unroll
    for (int mt = 0; mt < 2; ++mt) {
        #pragma unroll
        for (int nt = 0; nt < 8; ++nt) {
            const int col = bn + wn * 64 + nt * 8 + q * 2;
            const float b0 = bias[col], b1 = bias[col + 1];
            #pragma unroll
            for (int hrow = 0; hrow < 2; ++hrow) {
                const int row = bm + wm * 32 + mt * 16 + g + hrow * 8;
                outp[(size_t)row * C_ + col]     = acc[mt][nt][hrow * 2 + 0] + b0;
                outp[(size_t)row * C_ + col + 1] = acc[mt][nt][hrow * 2 + 1] + b1;
            }
        }
    }
}

// ---------------------------------------------------------------------------
// Flash attention on mma.sync, split-bf16 3-pass, ldmatrix fragment loads.
// R12: __launch_bounds__(256,2) + staged lo-frag loads (peak-reg relief)
//      + heavy-blocks-first scheduling.
// ---------------------------------------------------------------------------
#define RS2   72
#define ARR2B (64*RS2*2)      // 9216
#define TBUF  (4*ARR2B)       // 36864
#define ATTN_SMEM (2*TBUF)    // 73728  (x2 CTAs = 147KB/SM, fits)

__global__ __launch_bounds__(256, 2) void attn_mma()
{
    extern __shared__ char smc[];
    const int tid = threadIdx.x;
    const int w = tid >> 5, lane = tid & 31;
    const int g = lane >> 2, q = lane & 3;
    const int lrow = lane & 7;
    const int tsel = lane >> 3;
    const int b_nt = tsel >> 1, b_kh = tsel & 1;
    const int blk = (int)gridDim.x - 1 - (int)blockIdx.x;   // heavy blocks first
    const int bh = blockIdx.y;
    const int qbase = blk * 128;
    const unsigned sb = smem_u32(smc);

    const __nv_bfloat16* Qh = g_qhi + (size_t)bh * T_ * HD_ + (size_t)(qbase + w * 16) * HD_;
    const __nv_bfloat16* Ql = g_qlo + (size_t)bh * T_ * HD_ + (size_t)(qbase + w * 16) * HD_;
    const __nv_bfloat16* Kh = g_khi + (size_t)bh * T_ * HD_;
    const __nv_bfloat16* Kl = g_klo + (size_t)bh * T_ * HD_;
    const __nv_bfloat16* Vh = g_vthi + (size_t)bh * HD_ * T_;
    const __nv_bfloat16* Vl = g_vtlo + (size_t)bh * HD_ * T_;

    unsigned qh[4][4], ql[4][4];
    #pragma unroll
    for (int s = 0; s < 4; ++s) {
        const int c0 = s * 16 + 2 * q;
        qh[s][0] = *(const unsigned*)(Qh + (g    ) * HD_ + c0);
        qh[s][1] = *(const unsigned*)(Qh + (g + 8) * HD_ + c0);
        qh[s][2] = *(const unsigned*)(Qh + (g    ) * HD_ + c0 + 8);
        qh[s][3] = *(const unsigned*)(Qh + (g + 8) * HD_ + c0 + 8);
        ql[s][0] = *(const unsigned*)(Ql + (g    ) * HD_ + c0);
        ql[s][1] = *(const unsigned*)(Ql + (g + 8) * HD_ + c0);
        ql[s][2] = *(const unsigned*)(Ql + (g    ) * HD_ + c0 + 8);
        ql[s][3] = *(const unsigned*)(Ql + (g + 8) * HD_ + c0 + 8);
    }

    float oacc[8][4] = {};
    float m[2] = {-1e30f, -1e30f}, l[2] = {0.f, 0.f};

    auto load_tile = [&](int jt, int buf) {
        const int jb = jt * 64;
        const unsigned boff = (unsigned)buf * TBUF;
        #pragma unroll
        for (int it = 0; it < 8; ++it) {
            const int u = it * 256 + tid;
            const int arr = u >> 9;
            const int r   = (u >> 3) & 63;
            const int seg = u & 7;
            const __nv_bfloat16* src = (arr == 0) ? Kh : (arr == 1) ? Kl
                                      : (arr == 2) ? Vh : Vl;
            const void* gp = (arr < 2)
                ? (const void*)(src + ((size_t)(jb + r)) * HD_ + seg * 8)
                : (const void*)(src + ((size_t)r) * T_ + jb + seg * 8);
            const unsigned sp = sb + boff + (unsigned)arr * ARR2B
                              + (unsigned)(r * RS2 + seg * 8) * 2;
            cpa16(sp, gp);
        }
        cpa_commit();
    };

    const int ntiles = 2 * blk + 2;
    load_tile(0, 0);

    for (int jt = 0; jt < ntiles; ++jt) {
        if (jt < ntiles - 1) load_tile(jt + 1, (jt + 1) & 1);
        if (jt < ntiles - 1) cpa_wait1(); else cpa_wait0();
        __syncthreads();

        const int jb = jt * 64;
        if (jb <= qbase + w * 16 + 15) {
            const unsigned bufo = sb + (unsigned)(jt & 1) * TBUF;
            const unsigned sKh = bufo, sKl = bufo + ARR2B;
            const unsigned sVh = bufo + 2 * ARR2B, sVl = bufo + 3 * ARR2B;

            // ---- S = Q K^T (3-pass split; staged lo loads) ----
            float sacc[8][4] = {};
            #pragma unroll
            for (int s = 0; s < 4; ++s) {
                const int ko = s * 16;
                #pragma unroll
                for (int ntg = 0; ntg < 2; ++ntg) {
                    unsigned kbh[4][2];
                    #pragma unroll
                    for (int p = 0; p < 2; ++p) {
                        const int nr = (ntg * 4 + p * 2 + b_nt) * 8 + lrow;
                        ldsm_x4(&kbh[p*2][0], sKh + (unsigned)(nr * RS2 + ko + b_kh * 8) * 2);
                    }
                    #pragma unroll
                    for (int j = 0; j < 4; ++j) mma16816(sacc[ntg*4+j], qh[s], kbh[j]);
                    #pragma unroll
                    for (int j = 0; j < 4; ++j) mma16816(sacc[ntg*4+j], ql[s], kbh[j]);
                    unsigned kbl[4][2];
                    #pragma unroll
                    for (int p = 0; p < 2; ++p) {
                        const int nr = (ntg * 4 + p * 2 + b_nt) * 8 + lrow;
                        ldsm_x4(&kbl[p*2][0], sKl + (unsigned)(nr * RS2 + ko + b_kh * 8) * 2);
                    }
                    #pragma unroll
                    for (int j = 0; j < 4; ++j) mma16816(sacc[ntg*4+j], qh[s], kbl[j]);
                }
            }

            const bool needmask = (jb + 63 > qbase + w * 16);
            #pragma unroll
            for (int nt = 0; nt < 8; ++nt) {
                #pragma unroll
                for (int e = 0; e < 4; ++e) {
                    float v = sacc[nt][e] * 0.125f;
                    if (needmask) {
                        const int col = jb + nt * 8 + 2 * q + (e & 1);
                        const int row = qbase + w * 16 + g + (e >> 1) * 8;
                        if (col > row) v = -1e30f;
                    }
                    sacc[nt][e] = v;
                }
            }

            float mn[2];
            #pragma unroll
            for (int i = 0; i < 2; ++i) {
                float rm = sacc[0][i*2];
                #pragma unroll
                for (int nt = 0; nt < 8; ++nt) {
                    rm = fmaxf(rm, sacc[nt][i*2]);
                    rm = fmaxf(rm, sacc[nt][i*2+1]);
                }
                rm = fmaxf(rm, __shfl_xor_sync(0xffffffffu, rm, 1));
                rm = fmaxf(rm, __shfl_xor_sync(0xffffffffu, rm, 2));
                mn[i] = fmaxf(m[i], rm);
            }
            const float al0 = __expf(m[0] - mn[0]);
            const float al1 = __expf(m[1] - mn[1]);
            float rs[2] = {0.f, 0.f};
            #pragma unroll
            for (int nt = 0; nt < 8; ++nt) {
                #pragma unroll
                for (int e = 0; e < 4; ++e) {
                    const float p = __expf(sacc[nt][e] - mn[e >> 1]);
                    sacc[nt][e] = p;
                    rs[e >> 1] += p;
                }
            }
            #pragma unroll
            for (int i = 0; i < 2; ++i) {
                rs[i] += __shfl_xor_sync(0xffffffffu, rs[i], 1);
                rs[i] += __shfl_xor_sync(0xffffffffu, rs[i], 2);
            }
            l[0] = al0 * l[0] + rs[0];  m[0] = mn[0];
            l[1] = al1 * l[1] + rs[1];  m[1] = mn[1];
            #pragma unroll
            for (int nt = 0; nt < 8; ++nt) {
                oacc[nt][0] *= al0; oacc[nt][1] *= al0;
                oacc[nt][2] *= al1; oacc[nt][3] *= al1;
            }

            // ---- pack P (C-frag -> A-frag) with split ----
            unsigned pah[4][4], pal[4][4];
            #pragma unroll
            for (int s = 0; s < 4; ++s) {
                split_pack(sacc[2*s  ][0], sacc[2*s  ][1], pah[s][0], pal[s][0]);
                split_pack(sacc[2*s  ][2], sacc[2*s  ][3], pah[s][1], pal[s][1]);
                split_pack(sacc[2*s+1][0], sacc[2*s+1][1], pah[s][2], pal[s][2]);
                split_pack(sacc[2*s+1][2], sacc[2*s+1][3], pah[s][3], pal[s][3]);
            }

            // ---- O += P V (3-pass split; staged lo loads) ----
            #pragma unroll
            for (int s = 0; s < 4; ++s) {
                const int ko = s * 16;
                #pragma unroll
                for (int ntg = 0; ntg < 2; ++ntg) {
                    unsigned vbh[4][2];
                    #pragma unroll
                    for (int p = 0; p < 2; ++p) {
                        const int nr = (ntg * 4 + p * 2 + b_nt) * 8 + lrow;
                        ldsm_x4(&vbh[p*2][0], sVh + (unsigned)(nr * RS2 + ko + b_kh * 8) * 2);
                    }
                    #pragma unroll
                    for (int j = 0; j < 4; ++j) mma16816(oacc[ntg*4+j], pah[s], vbh[j]);
                    #pragma unroll
                    for (int j = 0; j < 4; ++j) mma16816(oacc[ntg*4+j], pal[s], vbh[j]);
                    unsigned vbl[4][2];
                    #pragma unroll
                    for (int p = 0; p < 2; ++p) {
                        const int nr = (ntg * 4 + p * 2 + b_nt) * 8 + lrow;
                        ldsm_x4(&vbl[p*2][0], sVl + (unsigned)(nr * RS2 + ko + b_kh * 8) * 2);
                    }
                    #pragma unroll
                    for (int j = 0; j < 4; ++j) mma16816(oacc[ntg*4+j], pah[s], vbl[j]);
                }
            }
        }
        __syncthreads();
    }

    const int b = bh >> 4, h = bh & 15;
    #pragma unroll
    for (int i = 0; i < 2; ++i) {
        const int t = qbase + w * 16 + g + i * 8;
        const float inv = 1.f / l[i];
        const size_t base = ((size_t)(b * T_ + t)) * C_ + h * HD_;
        #pragma unroll
        for (int nt = 0; nt < 8; ++nt) {
            const float v0 = oacc[nt][i*2]     * inv;
            const float v1 = oacc[nt][i*2 + 1] * inv;
            unsigned hp, lp;
            split_pack(v0, v1, hp, lp);
            const int col = nt * 8 + 2 * q;
            *(unsigned*)(g_yhi + base + col) = hp;
            *(unsigned*)(g_ylo + base + col) = lp;
        }
    }
}

// ---------------------------------------------------------------------------
extern "C" void kernel_launch(void* const* d_in, const int* in_sizes, int n_in,
                              void* d_out, int out_size)
{
    const float* query = (const float*)d_in[0];
    const float* Wq = (const float*)d_in[1];  const float* bq = (const float*)d_in[2];
    const float* Wk = (const float*)d_in[3];  const float* bk = (const float*)d_in[4];
    const float* Wv = (const float*)d_in[5];  const float* bv = (const float*)d_in[6];
    const float* Wp = (const float*)d_in[7];  const float* bp = (const float*)d_in[8];

    __nv_bfloat16 *xhi, *xlo, *yhi, *ylo;
    __nv_bfloat16 *wqh, *wql, *wkh, *wkl, *wvh, *wvl, *wph, *wpl;
    cudaGetSymbolAddress((void**)&xhi, g_xhi); cudaGetSymbolAddress((void**)&xlo, g_xlo);
    cudaGetSymbolAddress((void**)&yhi, g_yhi); cudaGetSymbolAddress((void**)&ylo, g_ylo);
    cudaGetSymbolAddress((void**)&wqh, g_wqhi); cudaGetSymbolAddress((void**)&wql, g_wqlo);
    cudaGetSymbolAddress((void**)&wkh, g_wkhi); cudaGetSymbolAddress((void**)&wkl, g_wklo);
    cudaGetSymbolAddress((void**)&wvh, g_wvhi); cudaGetSymbolAddress((void**)&wvl, g_wvlo);
    cudaGetSymbolAddress((void**)&wph, g_wphi); cudaGetSymbolAddress((void**)&wpl, g_wplo);

    cudaFuncSetAttribute(proj_qkv, cudaFuncAttributeMaxDynamicSharedMemorySize, PROJ_SMEM);
    cudaFuncSetAttribute(proj_out, cudaFuncAttributeMaxDynamicSharedMemorySize, PROJ_SMEM);
    cudaFuncSetAttribute(attn_mma, cudaFuncAttributeMaxDynamicSharedMemorySize, ATTN_SMEM);

    // splits
    split_kernel<<<2048, 256>>>(query, xhi, xlo, M_*C_);
    split4_kernel<<<1024, 256>>>(Wq, Wk, Wv, Wp,
                                 wqh, wql, wkh, wkl, wvh, wvl, wph, wpl);

    // fused QKV projection
    proj_qkv<<<dim3(24, M_/128), 256, PROJ_SMEM>>>(xhi, xlo, bq, bk, bv);

    // tensor-core flash attention (2 CTAs/SM target)
    attn_mma<<<dim3(T_/128, B_*H_), 256, ATTN_SMEM>>>();

    // output projection
    proj_out<<<dim3(C_/128, M_/128), 256, PROJ_SMEM>>>(yhi, ylo, bp, (float*)d_out);
}

// round 14
// speedup vs baseline: 5.1821x; 1.0217x over previous
#include <cuda_runtime.h>
#include <cuda_bf16.h>
#include <cstdint>

#define B_  4
#define T_  2048
#define C_  1024
#define H_  16
#define HD_ 64
#define M_  (B_*T_)   // 8192

// ---------------------------------------------------------------------------
// device scratch (bf16 split everywhere)
// ---------------------------------------------------------------------------
__device__ __nv_bfloat16 g_xhi[(size_t)M_*C_];
__device__ __nv_bfloat16 g_xlo[(size_t)M_*C_];
__device__ __nv_bfloat16 g_yhi[(size_t)M_*C_];
__device__ __nv_bfloat16 g_ylo[(size_t)M_*C_];
__device__ __nv_bfloat16 g_qhi[(size_t)B_*H_*T_*HD_], g_qlo[(size_t)B_*H_*T_*HD_];
__device__ __nv_bfloat16 g_khi[(size_t)B_*H_*T_*HD_], g_klo[(size_t)B_*H_*T_*HD_];
__device__ __nv_bfloat16 g_vthi[(size_t)B_*H_*HD_*T_], g_vtlo[(size_t)B_*H_*HD_*T_]; // [B,H,hd,T]
__device__ __nv_bfloat16 g_wqhi[(size_t)C_*C_], g_wqlo[(size_t)C_*C_];
__device__ __nv_bfloat16 g_wkhi[(size_t)C_*C_], g_wklo[(size_t)C_*C_];
__device__ __nv_bfloat16 g_wvhi[(size_t)C_*C_], g_wvlo[(size_t)C_*C_];
__device__ __nv_bfloat16 g_wphi[(size_t)C_*C_], g_wplo[(size_t)C_*C_];

// ---------------------------------------------------------------------------
// helpers
// ---------------------------------------------------------------------------
__device__ __forceinline__ unsigned smem_u32(const void* p) {
    unsigned a;
    asm("{ .reg .u64 t; cvta.to.shared.u64 t, %1; cvt.u32.u64 %0, t; }"
        : "=r"(a) : "l"(p));
    return a;
}
__device__ __forceinline__ void cpa16(unsigned s, const void* g) {
    asm volatile("cp.async.cg.shared.global [%0], [%1], 16;" :: "r"(s), "l"(g));
}
__device__ __forceinline__ void cpa_commit() {
    asm volatile("cp.async.commit_group;" ::: "memory");
}
__device__ __forceinline__ void cpa_wait1() {
    asm volatile("cp.async.wait_group 1;" ::: "memory");
}
__device__ __forceinline__ void cpa_wait0() {
    asm volatile("cp.async.wait_group 0;" ::: "memory");
}
__device__ __forceinline__ void mma16816(float* d, const unsigned* a, const unsigned* b) {
    asm volatile(
        "mma.sync.aligned.m16n8k16.row.col.f32.bf16.bf16.f32 "
        "{%0,%1,%2,%3}, {%4,%5,%6,%7}, {%8,%9}, {%0,%1,%2,%3};"
        : "+f"(d[0]), "+f"(d[1]), "+f"(d[2]), "+f"(d[3])
        : "r"(a[0]), "r"(a[1]), "r"(a[2]), "r"(a[3]), "r"(b[0]), "r"(b[1]));
}
__device__ __forceinline__ void ldsm_x4(unsigned* r, unsigned saddr) {
    asm volatile("ldmatrix.sync.aligned.m8n8.x4.shared.b16 {%0,%1,%2,%3}, [%4];"
        : "=r"(r[0]), "=r"(r[1]), "=r"(r[2]), "=r"(r[3]) : "r"(saddr));
}
__device__ __forceinline__ unsigned pack_bf(float lo, float hi) {
    unsigned d;
    asm("cvt.rn.bf16x2.f32 %0, %1, %2;" : "=r"(d) : "f"(hi), "f"(lo));
    return d;
}
__device__ __forceinline__ void split_pack(float p0, float p1, unsigned& hi, unsigned& lo) {
    hi = pack_bf(p0, p1);
    __nv_bfloat162 h2 = *reinterpret_cast<__nv_bfloat162*>(&hi);
    lo = pack_bf(p0 - __bfloat162float(h2.x), p1 - __bfloat162float(h2.y));
}

// ---------------------------------------------------------------------------
// vectorized splits: float4 in -> bf16x2-pair (uint2) out
// ---------------------------------------------------------------------------
__global__ __launch_bounds__(256) void splitv_kernel(
    const float4* __restrict__ src, uint2* __restrict__ hi,
    uint2* __restrict__ lo, int n4)
{
    int i = blockIdx.x * blockDim.x + threadIdx.x;
    const int stride = gridDim.x * blockDim.x;
    for (; i < n4; i += stride) {
        const float4 v = src[i];
        unsigned h0, l0, h1, l1;
        split_pack(v.x, v.y, h0, l0);
        split_pack(v.z, v.w, h1, l1);
        hi[i] = make_uint2(h0, h1);
        lo[i] = make_uint2(l0, l1);
    }
}

__global__ __launch_bounds__(256) void split4v_kernel(
    const float4* __restrict__ s0, const float4* __restrict__ s1,
    const float4* __restrict__ s2, const float4* __restrict__ s3,
    uint2* __restrict__ h0, uint2* __restrict__ l0,
    uint2* __restrict__ h1, uint2* __restrict__ l1,
    uint2* __restrict__ h2, uint2* __restrict__ l2,
    uint2* __restrict__ h3, uint2* __restrict__ l3)
{
    const int n4 = C_ * C_ / 4;
    const int stride = gridDim.x * blockDim.x;
    for (int i = blockIdx.x * blockDim.x + threadIdx.x; i < n4; i += stride) {
        #pragma unroll
        for (int a = 0; a < 4; ++a) {
            const float4* s = (a==0)?s0:(a==1)?s1:(a==2)?s2:s3;
            uint2* hh = (a==0)?h0:(a==1)?h1:(a==2)?h2:h3;
            uint2* ll = (a==0)?l0:(a==1)?l1:(a==2)?l2:l3;
            const float4 v = s[i];
            unsigned a0, b0, a1, b1;
            split_pack(v.x, v.y, a0, b0);
            split_pack(v.z, v.w, a1, b1);
            hh[i] = make_uint2(a0, a1);
            ll[i] = make_uint2(b0, b1);
        }
    }
}

// ---------------------------------------------------------------------------
// Shared GEMM mainloop (split-bf16 3-pass, ldmatrix fragment loads).
// ---------------------------------------------------------------------------
#define RS    40
#define ABYTES (128*RS*2)
#define BUFB  (4*ABYTES)
#define PROJ_SMEM (2*BUFB)             // 81920 B  (x2 CTAs = 160KB/SM, fits)

__device__ __forceinline__ void gemm_mainloop(
    const __nv_bfloat16* __restrict__ Ahi, const __nv_bfloat16* __restrict__ Alo,
    const __nv_bfloat16* __restrict__ Bhi, const __nv_bfloat16* __restrict__ Blo,
    int bm, int bn, unsigned sb, int tid, int lane,
    int wm, int wn, float acc[2][8][4])
{
    const int lrow = lane & 7;
    const int tsel = lane >> 3;
    const int b_nt = tsel >> 1, b_kh = tsel & 1;
    const int a_rh = tsel & 1,  a_kh = tsel >> 1;

    const __nv_bfloat16* srcs[4] = {Ahi, Alo, Bhi, Blo};

    auto load_chunk = [&](int k0, int buf) {
        const unsigned boff = (unsigned)buf * BUFB;
        #pragma unroll
        for (int it = 0; it < 8; ++it) {
            const int u   = it * 256 + tid;
            const int arr = u >> 9;
            const int r   = (u >> 2) & 127;
            const int seg = u & 3;
            const int rowg = ((arr < 2) ? bm : bn) + r;
            const void* gp = (const char*)srcs[arr] + ((size_t)rowg * C_ + k0 + seg * 8) * 2;
            const unsigned sp = sb + boff + (unsigned)arr * ABYTES
                              + (unsigned)(r * RS + seg * 8) * 2;
            cpa16(sp, gp);
        }
        cpa_commit();
    };

    load_chunk(0, 0);

    for (int c = 0; c < 32; ++c) {
        if (c < 31) load_chunk((c + 1) * 32, (c + 1) & 1);
        if (c < 31) cpa_wait1(); else cpa_wait0();
        __syncthreads();

        const unsigned sAh = sb + (unsigned)(c & 1) * BUFB;
        const unsigned sAl = sAh + ABYTES;
        const unsigned sBh = sAh + 2 * ABYTES;
        const unsigned sBl = sAh + 3 * ABYTES;

        #pragma unroll
        for (int ks = 0; ks < 2; ++ks) {
            const int ko = ks * 16;
            unsigned bh[8][2];
            #pragma unroll
            for (int nb = 0; nb < 4; ++nb) {
                const int nrow = wn * 64 + (nb * 2 + b_nt) * 8 + lrow;
                ldsm_x4(&bh[nb*2][0], sBh + (unsigned)(nrow * RS + ko + b_kh * 8) * 2);
            }
            #pragma unroll
            for (int mt = 0; mt < 2; ++mt) {
                const int arow = wm * 32 + mt * 16 + a_rh * 8 + lrow;
                unsigned ah[4], al[4];
                ldsm_x4(ah, sAh + (unsigned)(arow * RS + ko + a_kh * 8) * 2);
                ldsm_x4(al, sAl + (unsigned)(arow * RS + ko + a_kh * 8) * 2);
                #pragma unroll
                for (int nt = 0; nt < 8; ++nt) mma16816(acc[mt][nt], ah, bh[nt]);
                #pragma unroll
                for (int nt = 0; nt < 8; ++nt) mma16816(acc[mt][nt], al, bh[nt]);
            }
            unsigned bl[8][2];
            #pragma unroll
            for (int nb = 0; nb < 4; ++nb) {
                const int nrow = wn * 64 + (nb * 2 + b_nt) * 8 + lrow;
                ldsm_x4(&bl[nb*2][0], sBl + (unsigned)(nrow * RS + ko + b_kh * 8) * 2);
            }
            #pragma unroll
            for (int mt = 0; mt < 2; ++mt) {
                const int arow = wm * 32 + mt * 16 + a_rh * 8 + lrow;
                unsigned ah[4];
                ldsm_x4(ah, sAh + (unsigned)(arow * RS + ko + a_kh * 8) * 2);
                #pragma unroll
                for (int nt = 0; nt < 8; ++nt) mma16816(acc[mt][nt], ah, bl[nt]);
            }
        }
        __syncthreads();
    }
}

// ---------------------------------------------------------------------------
// Fused QKV projection. Q output pre-scaled by 0.125 (exact; attention skips
// the per-tile scale).
// ---------------------------------------------------------------------------
__global__ __launch_bounds__(256, 2) void proj_qkv(
    const __nv_bfloat16* __restrict__ Xhi, const __nv_bfloat16* __restrict__ Xlo,
    const float* __restrict__ bq, const float* __restrict__ bk,
    const float* __restrict__ bv)
{
    extern __shared__ char smc[];
    const int tid  = threadIdx.x;
    const int wid  = tid >> 5, lane = tid & 31;
    const int g    = lane >> 2, q = lane & 3;
    const int wm   = wid >> 1, wn = wid & 1;
    const int wsel = blockIdx.x >> 3;
    const int bn   = (blockIdx.x & 7) * 128;
    const int bm   = blockIdx.y * 128;
    const unsigned sb = smem_u32(smc);

    const __nv_bfloat16* Bhi = (wsel == 0) ? g_wqhi : (wsel == 1) ? g_wkhi : g_wvhi;
    const __nv_bfloat16* Blo = (wsel == 0) ? g_wqlo : (wsel == 1) ? g_wklo : g_wvlo;
    const float* bias = (wsel == 0) ? bq : (wsel == 1) ? bk : bv;
    const float oscale = (wsel == 0) ? 0.125f : 1.0f;   // fold 1/sqrt(hd) into Q

    float acc[2][8][4] = {};
    gemm_mainloop(Xhi, Xlo, Bhi, Blo, bm, bn, sb, tid, lane, wm, wn, acc);

    #pragma unroll
    for (int mt = 0; mt < 2; ++mt) {
        #pragma unroll
        for (int nt = 0; nt < 8; ++nt) {
            const int col = bn + wn * 64 + nt * 8 + q * 2;
            const float b0 = bias[col], b1 = bias[col + 1];
            #pragma unroll
            for (int hrow = 0; hrow < 2; ++hrow) {
                const int row = bm + wm * 32 + mt * 16 + g + hrow * 8;
                const float v0 = (acc[mt][nt][hrow * 2 + 0] + b0) * oscale;
                const float v1 = (acc[mt][nt][hrow * 2 + 1] + b1) * oscale;
                const __nv_bfloat16 h0 = __float2bfloat16(v0);
                const __nv_bfloat16 h1 = __float2bfloat16(v1);
                const __nv_bfloat16 l0 = __float2bfloat16(v0 - __bfloat162float(h0));
                const __nv_bfloat16 l1 = __float2bfloat16(v1 - __bfloat162float(h1));
                const int bb = row >> 11, t = row & 2047;
                const int hh = col >> 6,  d = col & 63;
                if (wsel < 2) {
                    const size_t idx = (((size_t)(bb * H_ + hh)) * T_ + t) * HD_ + d;
                    __nv_bfloat16* dh = (wsel == 0) ? g_qhi : g_khi;
                    __nv_bfloat16* dl = (wsel == 0) ? g_qlo : g_klo;
                    *(__nv_bfloat162*)(dh + idx) = __halves2bfloat162(h0, h1);
                    *(__nv_bfloat162*)(dl + idx) = __halves2bfloat162(l0, l1);
                } else {
                    const size_t idx = (((size_t)(bb * H_ + hh)) * HD_ + d) * T_ + t;
                    g_vthi[idx] = h0;  g_vthi[idx + T_] = h1;
                    g_vtlo[idx] = l0;  g_vtlo[idx + T_] = l1;
                }
            }
        }
    }
}

// ---------------------------------------------------------------------------
// Output projection: y(split bf16) @ Wp^T + bp -> f32 out
// ---------------------------------------------------------------------------
__global__ __launch_bounds__(256, 2) void proj_out(
    const __nv_bfloat16* __restrict__ Yhi, const __nv_bfloat16* __restrict__ Ylo,
    const float* __restrict__ bias, float* __restrict__ outp)
{
    extern __shared__ char smc[];
    const int tid  = threadIdx.x;
    const int wid  = tid >> 5, lane = tid & 31;
    const int g    = lane >> 2, q = lane & 3;
    const int wm   = wid >> 1, wn = wid & 1;
    const int bn   = blockIdx.x * 128;
    const int bm   = blockIdx.y * 128;
    const unsigned sb = smem_u32(smc);

    float acc[2][8][4] = {};
    gemm_mainloop(Yhi, Ylo, g_wphi, g_wplo, bm, bn, sb, tid, lane, wm, wn, acc);

    #pragma unroll
    for (int mt = 0; mt < 2; ++mt) {
        #pragma unroll
        for (int nt = 0; nt < 8; ++nt) {
            const int col = bn + wn * 64 + nt * 8 + q * 2;
            const float b0 = bias[col], b1 = bias[col + 1];
            #pragma unroll
            for (int hrow = 0; hrow < 2; ++hrow) {
                const int row = bm + wm * 32 + mt * 16 + g + hrow * 8;
                outp[(size_t)row * C_ + col]     = acc[mt][nt][hrow * 2 + 0] + b0;
                outp[(size_t)row * C_ + col + 1] = acc[mt][nt][hrow * 2 + 1] + b1;
            }
        }
    }
}

// ---------------------------------------------------------------------------
// Flash attention on mma.sync, split-bf16 3-pass.
// Q pre-scaled (no per-tile scale); masking diagonal-only, warp-uniform.
// ---------------------------------------------------------------------------
#define RS2   72
#define ARR2B (64*RS2*2)      // 9216
#define TBUF  (4*ARR2B)       // 36864
#define ATTN_SMEM (2*TBUF)    // 73728  (x2 CTAs = 147KB/SM, fits)

__global__ __launch_bounds__(256, 2) void attn_mma()
{
    extern __shared__ char smc[];
    const int tid = threadIdx.x;
    const int w = tid >> 5, lane = tid & 31;
    const int g = lane >> 2, q = lane & 3;
    const int lrow = lane & 7;
    const int tsel = lane >> 3;
    const int b_nt = tsel >> 1, b_kh = tsel & 1;
    const int blk = (int)gridDim.x - 1 - (int)blockIdx.x;   // heavy blocks first
    const int bh = blockIdx.y;
    const int qbase = blk * 128;
    const unsigned sb = smem_u32(smc);

    const __nv_bfloat16* Qh = g_qhi + (size_t)bh * T_ * HD_ + (size_t)(qbase + w * 16) * HD_;
    const __nv_bfloat16* Ql = g_qlo + (size_t)bh * T_ * HD_ + (size_t)(qbase + w * 16) * HD_;
    const __nv_bfloat16* Kh = g_khi + (size_t)bh * T_ * HD_;
    const __nv_bfloat16* Kl = g_klo + (size_t)bh * T_ * HD_;
    const __nv_bfloat16* Vh = g_vthi + (size_t)bh * HD_ * T_;
    const __nv_bfloat16* Vl = g_vtlo + (size_t)bh * HD_ * T_;

    unsigned qh[4][4], ql[4][4];
    #pragma unroll
    for (int s = 0; s < 4; ++s) {
        const int c0 = s * 16 + 2 * q;
        qh[s][0] = *(const unsigned*)(Qh + (g    ) * HD_ + c0);
        qh[s][1] = *(const unsigned*)(Qh + (g + 8) * HD_ + c0);
        qh[s][2] = *(const unsigned*)(Qh + (g    ) * HD_ + c0 + 8);
        qh[s][3] = *(const unsigned*)(Qh + (g + 8) * HD_ + c0 + 8);
        ql[s][0] = *(const unsigned*)(Ql + (g    ) * HD_ + c0);
        ql[s][1] = *(const unsigned*)(Ql + (g + 8) * HD_ + c0);
        ql[s][2] = *(const unsigned*)(Ql + (g    ) * HD_ + c0 + 8);
        ql[s][3] = *(const unsigned*)(Ql + (g + 8) * HD_ + c0 + 8);
    }

    float oacc[8][4] = {};
    float m[2] = {-1e30f, -1e30f}, l[2] = {0.f, 0.f};

    auto load_tile = [&](int jt, int buf) {
        const int jb = jt * 64;
        const unsigned boff = (unsigned)buf * TBUF;
        #pragma unroll
        for (int it = 0; it < 8; ++it) {
            const int u = it * 256 + tid;
            const int arr = u >> 9;
            const int r   = (u >> 3) & 63;
            const int seg = u & 7;
            const __nv_bfloat16* src = (arr == 0) ? Kh : (arr == 1) ? Kl
                                      : (arr == 2) ? Vh : Vl;
            const void* gp = (arr < 2)
                ? (const void*)(src + ((size_t)(jb + r)) * HD_ + seg * 8)
                : (const void*)(src + ((size_t)r) * T_ + jb + seg * 8);
            const unsigned sp = sb + boff + (unsigned)arr * ARR2B
                              + (unsigned)(r * RS2 + seg * 8) * 2;
            cpa16(sp, gp);
        }
        cpa_commit();
    };

    const int ntiles = 2 * blk + 2;
    load_tile(0, 0);

    for (int jt = 0; jt < ntiles; ++jt) {
        if (jt < ntiles - 1) load_tile(jt + 1, (jt + 1) & 1);
        if (jt < ntiles - 1) cpa_wait1(); else cpa_wait0();
        __syncthreads();

        const int jb = jt * 64;
        if (jb <= qbase + w * 16 + 15) {
            const unsigned bufo = sb + (unsigned)(jt & 1) * TBUF;
            const unsigned sKh = bufo, sKl = bufo + ARR2B;
            const unsigned sVh = bufo + 2 * ARR2B, sVl = bufo + 3 * ARR2B;

            // ---- S = Q K^T (Q pre-scaled; 3-pass split) ----
            float sacc[8][4] = {};
            #pragma unroll
            for (int s = 0; s < 4; ++s) {
                const int ko = s * 16;
                #pragma unroll
                for (int ntg = 0; ntg < 2; ++ntg) {
                    unsigned kbh[4][2];
                    #pragma unroll
                    for (int p = 0; p < 2; ++p) {
                        const int nr = (ntg * 4 + p * 2 + b_nt) * 8 + lrow;
                        ldsm_x4(&kbh[p*2][0], sKh + (unsigned)(nr * RS2 + ko + b_kh * 8) * 2);
                    }
                    #pragma unroll
                    for (int j = 0; j < 4; ++j) mma16816(sacc[ntg*4+j], qh[s], kbh[j]);
                    #pragma unroll
                    for (int j = 0; j < 4; ++j) mma16816(sacc[ntg*4+j], ql[s], kbh[j]);
                    unsigned kbl[4][2];
                    #pragma unroll
                    for (int p = 0; p < 2; ++p) {
                        const int nr = (ntg * 4 + p * 2 + b_nt) * 8 + lrow;
                        ldsm_x4(&kbl[p*2][0], sKl + (unsigned)(nr * RS2 + ko + b_kh * 8) * 2);
                    }
                    #pragma unroll
                    for (int j = 0; j < 4; ++j) mma16816(sacc[ntg*4+j], qh[s], kbl[j]);
                }
            }

            // ---- causal mask (diagonal tiles only; warp-uniform branch) ----
            if (jb + 63 > qbase + w * 16) {
                #pragma unroll
                for (int nt = 0; nt < 8; ++nt) {
                    #pragma unroll
                    for (int e = 0; e < 4; ++e) {
                        const int col = jb + nt * 8 + 2 * q + (e & 1);
                        const int row = qbase + w * 16 + g + (e >> 1) * 8;
                        if (col > row) sacc[nt][e] = -1e30f;
                    }
                }
            }

            // ---- online softmax ----
            float mn[2];
            #pragma unroll
            for (int i = 0; i < 2; ++i) {
                float rm = sacc[0][i*2];
                #pragma unroll
                for (int nt = 0; nt < 8; ++nt) {
                    rm = fmaxf(rm, sacc[nt][i*2]);
                    rm = fmaxf(rm, sacc[nt][i*2+1]);
                }
                rm = fmaxf(rm, __shfl_xor_sync(0xffffffffu, rm, 1));
                rm = fmaxf(rm, __shfl_xor_sync(0xffffffffu, rm, 2));
                mn[i] = fmaxf(m[i], rm);
            }
            const float al0 = __expf(m[0] - mn[0]);
            const float al1 = __expf(m[1] - mn[1]);
            float rs[2] = {0.f, 0.f};
            #pragma unroll
            for (int nt = 0; nt < 8; ++nt) {
                #pragma unroll
                for (int e = 0; e < 4; ++e) {
                    const float p = __expf(sacc[nt][e] - mn[e >> 1]);
                    sacc[nt][e] = p;
                    rs[e >> 1] += p;
                }
            }
            #pragma unroll
            for (int i = 0; i < 2; ++i) {
                rs[i] += __shfl_xor_sync(0xffffffffu, rs[i], 1);
                rs[i] += __shfl_xor_sync(0xffffffffu, rs[i], 2);
            }
            l[0] = al0 * l[0] + rs[0];  m[0] = mn[0];
            l[1] = al1 * l[1] + rs[1];  m[1] = mn[1];
            #pragma unroll
            for (int nt = 0; nt < 8; ++nt) {
                oacc[nt][0] *= al0; oacc[nt][1] *= al0;
                oacc[nt][2] *= al1; oacc[nt][3] *= al1;
            }

            // ---- pack P (C-frag -> A-frag) with split ----
            unsigned pah[4][4], pal[4][4];
            #pragma unroll
            for (int s = 0; s < 4; ++s) {
                split_pack(sacc[2*s  ][0], sacc[2*s  ][1], pah[s][0], pal[s][0]);
                split_pack(sacc[2*s  ][2], sacc[2*s  ][3], pah[s][1], pal[s][1]);
                split_pack(sacc[2*s+1][0], sacc[2*s+1][1], pah[s][2], pal[s][2]);
                split_pack(sacc[2*s+1][2], sacc[2*s+1][3], pah[s][3], pal[s][3]);
            }

            // ---- O += P V (3-pass split) ----
            #pragma unroll
            for (int s = 0; s < 4; ++s) {
                const int ko = s * 16;
                #pragma unroll
                for (int ntg = 0; ntg < 2; ++ntg) {
                    unsigned vbh[4][2];
                    #pragma unroll
                    for (int p = 0; p < 2; ++p) {
                        const int nr = (ntg * 4 + p * 2 + b_nt) * 8 + lrow;
                        ldsm_x4(&vbh[p*2][0], sVh + (unsigned)(nr * RS2 + ko + b_kh * 8) * 2);
                    }
                    #pragma unroll
                    for (int j = 0; j < 4; ++j) mma16816(oacc[ntg*4+j], pah[s], vbh[j]);
                    #pragma unroll
                    for (int j = 0; j < 4; ++j) mma16816(oacc[ntg*4+j], pal[s], vbh[j]);
                    unsigned vbl[4][2];
                    #pragma unroll
                    for (int p = 0; p < 2; ++p) {
                        const int nr = (ntg * 4 + p * 2 + b_nt) * 8 + lrow;
                        ldsm_x4(&vbl[p*2][0], sVl + (unsigned)(nr * RS2 + ko + b_kh * 8) * 2);
                    }
                    #pragma unroll
                    for (int j = 0; j < 4; ++j) mma16816(oacc[ntg*4+j], pah[s], vbl[j]);
                }
            }
        }
        __syncthreads();
    }

    const int b = bh >> 4, h = bh & 15;
    #pragma unroll
    for (int i = 0; i < 2; ++i) {
        const int t = qbase + w * 16 + g + i * 8;
        const float inv = 1.f / l[i];
        const size_t base = ((size_t)(b * T_ + t)) * C_ + h * HD_;
        #pragma unroll
        for (int nt = 0; nt < 8; ++nt) {
            const float v0 = oacc[nt][i*2]     * inv;
            const float v1 = oacc[nt][i*2 + 1] * inv;
            unsigned hp, lp;
            split_pack(v0, v1, hp, lp);
            const int col = nt * 8 + 2 * q;
            *(unsigned*)(g_yhi + base + col) = hp;
            *(unsigned*)(g_ylo + base + col) = lp;
        }
    }
}

// ---------------------------------------------------------------------------
extern "C" void kernel_launch(void* const* d_in, const int* in_sizes, int n_in,
                              void* d_out, int out_size)
{
    const float* query = (const float*)d_in[0];
    const float* Wq = (const float*)d_in[1];  const float* bq = (const float*)d_in[2];
    const float* Wk = (const float*)d_in[3];  const float* bk = (const float*)d_in[4];
    const float* Wv = (const float*)d_in[5];  const float* bv = (const float*)d_in[6];
    const float* Wp = (const float*)d_in[7];  const float* bp = (const float*)d_in[8];

    __nv_bfloat16 *xhi, *xlo, *yhi, *ylo;
    __nv_bfloat16 *wqh, *wql, *wkh, *wkl, *wvh, *wvl, *wph, *wpl;
    cudaGetSymbolAddress((void**)&xhi, g_xhi); cudaGetSymbolAddress((void**)&xlo, g_xlo);
    cudaGetSymbolAddress((void**)&yhi, g_yhi); cudaGetSymbolAddress((void**)&ylo, g_ylo);
    cudaGetSymbolAddress((void**)&wqh, g_wqhi); cudaGetSymbolAddress((void**)&wql, g_wqlo);
    cudaGetSymbolAddress((void**)&wkh, g_wkhi); cudaGetSymbolAddress((void**)&wkl, g_wklo);
    cudaGetSymbolAddress((void**)&wvh, g_wvhi); cudaGetSymbolAddress((void**)&wvl, g_wvlo);
    cudaGetSymbolAddress((void**)&wph, g_wphi); cudaGetSymbolAddress((void**)&wpl, g_wplo);

    cudaFuncSetAttribute(proj_qkv, cudaFuncAttributeMaxDynamicSharedMemorySize, PROJ_SMEM);
    cudaFuncSetAttribute(proj_out, cudaFuncAttributeMaxDynamicSharedMemorySize, PROJ_SMEM);
    cudaFuncSetAttribute(attn_mma, cudaFuncAttributeMaxDynamicSharedMemorySize, ATTN_SMEM);

    // vectorized splits
    splitv_kernel<<<1184, 256>>>((const float4*)query, (uint2*)xhi, (uint2*)xlo,
                                 M_*C_/4);
    split4v_kernel<<<1024, 256>>>((const float4*)Wq, (const float4*)Wk,
                                  (const float4*)Wv, (const float4*)Wp,
                                  (uint2*)wqh, (uint2*)wql, (uint2*)wkh, (uint2*)wkl,
                                  (uint2*)wvh, (uint2*)wvl, (uint2*)wph, (uint2*)wpl);

    // fused QKV projection (Q pre-scaled by 1/8)
    proj_qkv<<<dim3(24, M_/128), 256, PROJ_SMEM>>>(xhi, xlo, bq, bk, bv);

    // tensor-core flash attention
    attn_mma<<<dim3(T_/128, B_*H_), 256, ATTN_SMEM>>>();

    // output projection
    proj_out<<<dim3(C_/128, M_/128), 256, PROJ_SMEM>>>(yhi, ylo, bp, (float*)d_out);
}

// round 15
// speedup vs baseline: 5.1922x; 1.0020x over previous
#include <cuda_runtime.h>
#include <cuda_bf16.h>
#include <cstdint>

#define B_  4
#define T_  2048
#define C_  1024
#define H_  16
#define HD_ 64
#define M_  (B_*T_)   // 8192

// ---------------------------------------------------------------------------
// device scratch (bf16 split everywhere)
// ---------------------------------------------------------------------------
__device__ __nv_bfloat16 g_xhi[(size_t)M_*C_];
__device__ __nv_bfloat16 g_xlo[(size_t)M_*C_];
__device__ __nv_bfloat16 g_yhi[(size_t)M_*C_];
__device__ __nv_bfloat16 g_ylo[(size_t)M_*C_];
__device__ __nv_bfloat16 g_qhi[(size_t)B_*H_*T_*HD_], g_qlo[(size_t)B_*H_*T_*HD_];
__device__ __nv_bfloat16 g_khi[(size_t)B_*H_*T_*HD_], g_klo[(size_t)B_*H_*T_*HD_];
__device__ __nv_bfloat16 g_vthi[(size_t)B_*H_*HD_*T_], g_vtlo[(size_t)B_*H_*HD_*T_]; // [B,H,hd,T]
__device__ __nv_bfloat16 g_wqhi[(size_t)C_*C_], g_wqlo[(size_t)C_*C_];
__device__ __nv_bfloat16 g_wkhi[(size_t)C_*C_], g_wklo[(size_t)C_*C_];
__device__ __nv_bfloat16 g_wvhi[(size_t)C_*C_], g_wvlo[(size_t)C_*C_];
__device__ __nv_bfloat16 g_wphi[(size_t)C_*C_], g_wplo[(size_t)C_*C_];

// ---------------------------------------------------------------------------
// helpers
// ---------------------------------------------------------------------------
__device__ __forceinline__ unsigned smem_u32(const void* p) {
    unsigned a;
    asm("{ .reg .u64 t; cvta.to.shared.u64 t, %1; cvt.u32.u64 %0, t; }"
        : "=r"(a) : "l"(p));
    return a;
}
__device__ __forceinline__ void cpa16(unsigned s, const void* g) {
    asm volatile("cp.async.cg.shared.global [%0], [%1], 16;" :: "r"(s), "l"(g));
}
__device__ __forceinline__ void cpa_commit() {
    asm volatile("cp.async.commit_group;" ::: "memory");
}
__device__ __forceinline__ void cpa_wait1() {
    asm volatile("cp.async.wait_group 1;" ::: "memory");
}
__device__ __forceinline__ void cpa_wait0() {
    asm volatile("cp.async.wait_group 0;" ::: "memory");
}
__device__ __forceinline__ void mma16816(float* d, const unsigned* a, const unsigned* b) {
    asm volatile(
        "mma.sync.aligned.m16n8k16.row.col.f32.bf16.bf16.f32 "
        "{%0,%1,%2,%3}, {%4,%5,%6,%7}, {%8,%9}, {%0,%1,%2,%3};"
        : "+f"(d[0]), "+f"(d[1]), "+f"(d[2]), "+f"(d[3])
        : "r"(a[0]), "r"(a[1]), "r"(a[2]), "r"(a[3]), "r"(b[0]), "r"(b[1]));
}
__device__ __forceinline__ void ldsm_x4(unsigned* r, unsigned saddr) {
    asm volatile("ldmatrix.sync.aligned.m8n8.x4.shared.b16 {%0,%1,%2,%3}, [%4];"
        : "=r"(r[0]), "=r"(r[1]), "=r"(r[2]), "=r"(r[3]) : "r"(saddr));
}
__device__ __forceinline__ unsigned pack_bf(float lo, float hi) {
    unsigned d;
    asm("cvt.rn.bf16x2.f32 %0, %1, %2;" : "=r"(d) : "f"(hi), "f"(lo));
    return d;
}
__device__ __forceinline__ void split_pack(float p0, float p1, unsigned& hi, unsigned& lo) {
    hi = pack_bf(p0, p1);
    __nv_bfloat162 h2 = *reinterpret_cast<__nv_bfloat162*>(&hi);
    lo = pack_bf(p0 - __bfloat162float(h2.x), p1 - __bfloat162float(h2.y));
}

// ---------------------------------------------------------------------------
// fused split: x (n4x elements of float4) + 4 weight matrices, one launch
// ---------------------------------------------------------------------------
__global__ __launch_bounds__(256) void split_all_kernel(
    const float4* __restrict__ sx,
    const float4* __restrict__ s0, const float4* __restrict__ s1,
    const float4* __restrict__ s2, const float4* __restrict__ s3,
    uint2* __restrict__ xh, uint2* __restrict__ xl,
    uint2* __restrict__ h0, uint2* __restrict__ l0,
    uint2* __restrict__ h1, uint2* __restrict__ l1,
    uint2* __restrict__ h2, uint2* __restrict__ l2,
    uint2* __restrict__ h3, uint2* __restrict__ l3)
{
    const int stride = gridDim.x * blockDim.x;
    // x: M*C/4 elements
    const int nx = M_ * C_ / 4;
    for (int i = blockIdx.x * blockDim.x + threadIdx.x; i < nx; i += stride) {
        const float4 v = sx[i];
        unsigned a0, b0, a1, b1;
        split_pack(v.x, v.y, a0, b0);
        split_pack(v.z, v.w, a1, b1);
        xh[i] = make_uint2(a0, a1);
        xl[i] = make_uint2(b0, b1);
    }
    // weights: C*C/4 each
    const int nw = C_ * C_ / 4;
    for (int i = blockIdx.x * blockDim.x + threadIdx.x; i < nw; i += stride) {
        #pragma unroll
        for (int a = 0; a < 4; ++a) {
            const float4* s = (a==0)?s0:(a==1)?s1:(a==2)?s2:s3;
            uint2* hh = (a==0)?h0:(a==1)?h1:(a==2)?h2:h3;
            uint2* ll = (a==0)?l0:(a==1)?l1:(a==2)?l2:l3;
            const float4 v = s[i];
            unsigned a0, b0, a1, b1;
            split_pack(v.x, v.y, a0, b0);
            split_pack(v.z, v.w, a1, b1);
            hh[i] = make_uint2(a0, a1);
            ll[i] = make_uint2(b0, b1);
        }
    }
}

// ---------------------------------------------------------------------------
// Shared GEMM mainloop (split-bf16 3-pass, ldmatrix fragment loads).
// ---------------------------------------------------------------------------
#define RS    40
#define ABYTES (128*RS*2)
#define BUFB  (4*ABYTES)
#define PROJ_SMEM (2*BUFB)             // 81920 B  (x2 CTAs = 160KB/SM, fits)

__device__ __forceinline__ void gemm_mainloop(
    const __nv_bfloat16* __restrict__ Ahi, const __nv_bfloat16* __restrict__ Alo,
    const __nv_bfloat16* __restrict__ Bhi, const __nv_bfloat16* __restrict__ Blo,
    int bm, int bn, unsigned sb, int tid, int lane,
    int wm, int wn, float acc[2][8][4])
{
    const int lrow = lane & 7;
    const int tsel = lane >> 3;
    const int b_nt = tsel >> 1, b_kh = tsel & 1;
    const int a_rh = tsel & 1,  a_kh = tsel >> 1;

    const __nv_bfloat16* srcs[4] = {Ahi, Alo, Bhi, Blo};

    auto load_chunk = [&](int k0, int buf) {
        const unsigned boff = (unsigned)buf * BUFB;
        #pragma unroll
        for (int it = 0; it < 8; ++it) {
            const int u   = it * 256 + tid;
            const int arr = u >> 9;
            const int r   = (u >> 2) & 127;
            const int seg = u & 3;
            const int rowg = ((arr < 2) ? bm : bn) + r;
            const void* gp = (const char*)srcs[arr] + ((size_t)rowg * C_ + k0 + seg * 8) * 2;
            const unsigned sp = sb + boff + (unsigned)arr * ABYTES
                              + (unsigned)(r * RS + seg * 8) * 2;
            cpa16(sp, gp);
        }
        cpa_commit();
    };

    load_chunk(0, 0);

    for (int c = 0; c < 32; ++c) {
        if (c < 31) load_chunk((c + 1) * 32, (c + 1) & 1);
        if (c < 31) cpa_wait1(); else cpa_wait0();
        __syncthreads();

        const unsigned sAh = sb + (unsigned)(c & 1) * BUFB;
        const unsigned sAl = sAh + ABYTES;
        const unsigned sBh = sAh + 2 * ABYTES;
        const unsigned sBl = sAh + 3 * ABYTES;

        #pragma unroll
        for (int ks = 0; ks < 2; ++ks) {
            const int ko = ks * 16;
            unsigned bh[8][2];
            #pragma unroll
            for (int nb = 0; nb < 4; ++nb) {
                const int nrow = wn * 64 + (nb * 2 + b_nt) * 8 + lrow;
                ldsm_x4(&bh[nb*2][0], sBh + (unsigned)(nrow * RS + ko + b_kh * 8) * 2);
            }
            #pragma unroll
            for (int mt = 0; mt < 2; ++mt) {
                const int arow = wm * 32 + mt * 16 + a_rh * 8 + lrow;
                unsigned ah[4], al[4];
                ldsm_x4(ah, sAh + (unsigned)(arow * RS + ko + a_kh * 8) * 2);
                ldsm_x4(al, sAl + (unsigned)(arow * RS + ko + a_kh * 8) * 2);
                #pragma unroll
                for (int nt = 0; nt < 8; ++nt) mma16816(acc[mt][nt], ah, bh[nt]);
                #pragma unroll
                for (int nt = 0; nt < 8; ++nt) mma16816(acc[mt][nt], al, bh[nt]);
            }
            unsigned bl[8][2];
            #pragma unroll
            for (int nb = 0; nb < 4; ++nb) {
                const int nrow = wn * 64 + (nb * 2 + b_nt) * 8 + lrow;
                ldsm_x4(&bl[nb*2][0], sBl + (unsigned)(nrow * RS + ko + b_kh * 8) * 2);
            }
            #pragma unroll
            for (int mt = 0; mt < 2; ++mt) {
                const int arow = wm * 32 + mt * 16 + a_rh * 8 + lrow;
                unsigned ah[4];
                ldsm_x4(ah, sAh + (unsigned)(arow * RS + ko + a_kh * 8) * 2);
                #pragma unroll
                for (int nt = 0; nt < 8; ++nt) mma16816(acc[mt][nt], ah, bl[nt]);
            }
        }
        __syncthreads();
    }
}

// ---------------------------------------------------------------------------
// Fused QKV projection. Q output pre-scaled by 0.125.
// ---------------------------------------------------------------------------
__global__ __launch_bounds__(256, 2) void proj_qkv(
    const __nv_bfloat16* __restrict__ Xhi, const __nv_bfloat16* __restrict__ Xlo,
    const float* __restrict__ bq, const float* __restrict__ bk,
    const float* __restrict__ bv)
{
    extern __shared__ char smc[];
    const int tid  = threadIdx.x;
    const int wid  = tid >> 5, lane = tid & 31;
    const int g    = lane >> 2, q = lane & 3;
    const int wm   = wid >> 1, wn = wid & 1;
    const int wsel = blockIdx.x >> 3;
    const int bn   = (blockIdx.x & 7) * 128;
    const int bm   = blockIdx.y * 128;
    const unsigned sb = smem_u32(smc);

    const __nv_bfloat16* Bhi = (wsel == 0) ? g_wqhi : (wsel == 1) ? g_wkhi : g_wvhi;
    const __nv_bfloat16* Blo = (wsel == 0) ? g_wqlo : (wsel == 1) ? g_wklo : g_wvlo;
    const float* bias = (wsel == 0) ? bq : (wsel == 1) ? bk : bv;
    const float oscale = (wsel == 0) ? 0.125f : 1.0f;

    float acc[2][8][4] = {};
    gemm_mainloop(Xhi, Xlo, Bhi, Blo, bm, bn, sb, tid, lane, wm, wn, acc);

    #pragma unroll
    for (int mt = 0; mt < 2; ++mt) {
        #pragma unroll
        for (int nt = 0; nt < 8; ++nt) {
            const int col = bn + wn * 64 + nt * 8 + q * 2;
            const float b0 = bias[col], b1 = bias[col + 1];
            #pragma unroll
            for (int hrow = 0; hrow < 2; ++hrow) {
                const int row = bm + wm * 32 + mt * 16 + g + hrow * 8;
                const float v0 = (acc[mt][nt][hrow * 2 + 0] + b0) * oscale;
                const float v1 = (acc[mt][nt][hrow * 2 + 1] + b1) * oscale;
                const __nv_bfloat16 h0 = __float2bfloat16(v0);
                const __nv_bfloat16 h1 = __float2bfloat16(v1);
                const __nv_bfloat16 l0 = __float2bfloat16(v0 - __bfloat162float(h0));
                const __nv_bfloat16 l1 = __float2bfloat16(v1 - __bfloat162float(h1));
                const int bb = row >> 11, t = row & 2047;
                const int hh = col >> 6,  d = col & 63;
                if (wsel < 2) {
                    const size_t idx = (((size_t)(bb * H_ + hh)) * T_ + t) * HD_ + d;
                    __nv_bfloat16* dh = (wsel == 0) ? g_qhi : g_khi;
                    __nv_bfloat16* dl = (wsel == 0) ? g_qlo : g_klo;
                    *(__nv_bfloat162*)(dh + idx) = __halves2bfloat162(h0, h1);
                    *(__nv_bfloat162*)(dl + idx) = __halves2bfloat162(l0, l1);
                } else {
                    const size_t idx = (((size_t)(bb * H_ + hh)) * HD_ + d) * T_ + t;
                    g_vthi[idx] = h0;  g_vthi[idx + T_] = h1;
                    g_vtlo[idx] = l0;  g_vtlo[idx + T_] = l1;
                }
            }
        }
    }
}

// ---------------------------------------------------------------------------
// Output projection: y(split bf16) @ Wp^T + bp -> f32 out
// ---------------------------------------------------------------------------
__global__ __launch_bounds__(256, 2) void proj_out(
    const __nv_bfloat16* __restrict__ Yhi, const __nv_bfloat16* __restrict__ Ylo,
    const float* __restrict__ bias, float* __restrict__ outp)
{
    extern __shared__ char smc[];
    const int tid  = threadIdx.x;
    const int wid  = tid >> 5, lane = tid & 31;
    const int g    = lane >> 2, q = lane & 3;
    const int wm   = wid >> 1, wn = wid & 1;
    const int bn   = blockIdx.x * 128;
    const int bm   = blockIdx.y * 128;
    const unsigned sb = smem_u32(smc);

    float acc[2][8][4] = {};
    gemm_mainloop(Yhi, Ylo, g_wphi, g_wplo, bm, bn, sb, tid, lane, wm, wn, acc);

    #pragma unroll
    for (int mt = 0; mt < 2; ++mt) {
        #pragma unroll
        for (int nt = 0; nt < 8; ++nt) {
            const int col = bn + wn * 64 + nt * 8 + q * 2;
            const float b0 = bias[col], b1 = bias[col + 1];
            #pragma unroll
            for (int hrow = 0; hrow < 2; ++hrow) {
                const int row = bm + wm * 32 + mt * 16 + g + hrow * 8;
                outp[(size_t)row * C_ + col]     = acc[mt][nt][hrow * 2 + 0] + b0;
                outp[(size_t)row * C_ + col + 1] = acc[mt][nt][hrow * 2 + 1] + b1;
            }
        }
    }
}

// ---------------------------------------------------------------------------
// Flash attention on mma.sync, split-bf16 3-pass.
// R15: 8-wide MMA passes (8 independent accumulators between reuses) to
// break HMMA RAW chains — mirrors the proj mainloop pattern.
// ---------------------------------------------------------------------------
#define RS2   72
#define ARR2B (64*RS2*2)      // 9216
#define TBUF  (4*ARR2B)       // 36864
#define ATTN_SMEM (2*TBUF)    // 73728  (x2 CTAs = 147KB/SM, fits)

__global__ __launch_bounds__(256, 2) void attn_mma()
{
    extern __shared__ char smc[];
    const int tid = threadIdx.x;
    const int w = tid >> 5, lane = tid & 31;
    const int g = lane >> 2, q = lane & 3;
    const int lrow = lane & 7;
    const int tsel = lane >> 3;
    const int b_nt = tsel >> 1, b_kh = tsel & 1;
    const int blk = (int)gridDim.x - 1 - (int)blockIdx.x;   // heavy blocks first
    const int bh = blockIdx.y;
    const int qbase = blk * 128;
    const unsigned sb = smem_u32(smc);

    const __nv_bfloat16* Qh = g_qhi + (size_t)bh * T_ * HD_ + (size_t)(qbase + w * 16) * HD_;
    const __nv_bfloat16* Ql = g_qlo + (size_t)bh * T_ * HD_ + (size_t)(qbase + w * 16) * HD_;
    const __nv_bfloat16* Kh = g_khi + (size_t)bh * T_ * HD_;
    const __nv_bfloat16* Kl = g_klo + (size_t)bh * T_ * HD_;
    const __nv_bfloat16* Vh = g_vthi + (size_t)bh * HD_ * T_;
    const __nv_bfloat16* Vl = g_vtlo + (size_t)bh * HD_ * T_;

    unsigned qh[4][4], ql[4][4];
    #pragma unroll
    for (int s = 0; s < 4; ++s) {
        const int c0 = s * 16 + 2 * q;
        qh[s][0] = *(const unsigned*)(Qh + (g    ) * HD_ + c0);
        qh[s][1] = *(const unsigned*)(Qh + (g + 8) * HD_ + c0);
        qh[s][2] = *(const unsigned*)(Qh + (g    ) * HD_ + c0 + 8);
        qh[s][3] = *(const unsigned*)(Qh + (g + 8) * HD_ + c0 + 8);
        ql[s][0] = *(const unsigned*)(Ql + (g    ) * HD_ + c0);
        ql[s][1] = *(const unsigned*)(Ql + (g + 8) * HD_ + c0);
        ql[s][2] = *(const unsigned*)(Ql + (g    ) * HD_ + c0 + 8);
        ql[s][3] = *(const unsigned*)(Ql + (g + 8) * HD_ + c0 + 8);
    }

    float oacc[8][4] = {};
    float m[2] = {-1e30f, -1e30f}, l[2] = {0.f, 0.f};

    auto load_tile = [&](int jt, int buf) {
        const int jb = jt * 64;
        const unsigned boff = (unsigned)buf * TBUF;
        #pragma unroll
        for (int it = 0; it < 8; ++it) {
            const int u = it * 256 + tid;
            const int arr = u >> 9;
            const int r   = (u >> 3) & 63;
            const int seg = u & 7;
            const __nv_bfloat16* src = (arr == 0) ? Kh : (arr == 1) ? Kl
                                      : (arr == 2) ? Vh : Vl;
            const void* gp = (arr < 2)
                ? (const void*)(src + ((size_t)(jb + r)) * HD_ + seg * 8)
                : (const void*)(src + ((size_t)r) * T_ + jb + seg * 8);
            const unsigned sp = sb + boff + (unsigned)arr * ARR2B
                              + (unsigned)(r * RS2 + seg * 8) * 2;
            cpa16(sp, gp);
        }
        cpa_commit();
    };

    const int ntiles = 2 * blk + 2;
    load_tile(0, 0);

    for (int jt = 0; jt < ntiles; ++jt) {
        if (jt < ntiles - 1) load_tile(jt + 1, (jt + 1) & 1);
        if (jt < ntiles - 1) cpa_wait1(); else cpa_wait0();
        __syncthreads();

        const int jb = jt * 64;
        if (jb <= qbase + w * 16 + 15) {
            const unsigned bufo = sb + (unsigned)(jt & 1) * TBUF;
            const unsigned sKh = bufo, sKl = bufo + ARR2B;
            const unsigned sVh = bufo + 2 * ARR2B, sVl = bufo + 3 * ARR2B;

            // ---- S = Q K^T (8-wide passes; 3-pass split) ----
            float sacc[8][4] = {};
            #pragma unroll
            for (int s = 0; s < 4; ++s) {
                const int ko = s * 16;
                unsigned kbh[8][2];
                #pragma unroll
                for (int p = 0; p < 4; ++p) {
                    const int nr = (p * 2 + b_nt) * 8 + lrow;
                    ldsm_x4(&kbh[p*2][0], sKh + (unsigned)(nr * RS2 + ko + b_kh * 8) * 2);
                }
                #pragma unroll
                for (int j = 0; j < 8; ++j) mma16816(sacc[j], qh[s], kbh[j]);
                #pragma unroll
                for (int j = 0; j < 8; ++j) mma16816(sacc[j], ql[s], kbh[j]);
                unsigned kbl[8][2];
                #pragma unroll
                for (int p = 0; p < 4; ++p) {
                    const int nr = (p * 2 + b_nt) * 8 + lrow;
                    ldsm_x4(&kbl[p*2][0], sKl + (unsigned)(nr * RS2 + ko + b_kh * 8) * 2);
                }
                #pragma unroll
                for (int j = 0; j < 8; ++j) mma16816(sacc[j], qh[s], kbl[j]);
            }

            // ---- causal mask (diagonal tiles only; warp-uniform branch) ----
            if (jb + 63 > qbase + w * 16) {
                #pragma unroll
                for (int nt = 0; nt < 8; ++nt) {
                    #pragma unroll
                    for (int e = 0; e < 4; ++e) {
                        const int col = jb + nt * 8 + 2 * q + (e & 1);
                        const int row = qbase + w * 16 + g + (e >> 1) * 8;
                        if (col > row) sacc[nt][e] = -1e30f;
                    }
                }
            }

            // ---- online softmax ----
            float mn[2];
            #pragma unroll
            for (int i = 0; i < 2; ++i) {
                float rm = sacc[0][i*2];
                #pragma unroll
                for (int nt = 0; nt < 8; ++nt) {
                    rm = fmaxf(rm, sacc[nt][i*2]);
                    rm = fmaxf(rm, sacc[nt][i*2+1]);
                }
                rm = fmaxf(rm, __shfl_xor_sync(0xffffffffu, rm, 1));
                rm = fmaxf(rm, __shfl_xor_sync(0xffffffffu, rm, 2));
                mn[i] = fmaxf(m[i], rm);
            }
            const float al0 = __expf(m[0] - mn[0]);
            const float al1 = __expf(m[1] - mn[1]);
            float rs[2] = {0.f, 0.f};
            #pragma unroll
            for (int nt = 0; nt < 8; ++nt) {
                #pragma unroll
                for (int e = 0; e < 4; ++e) {
                    const float p = __expf(sacc[nt][e] - mn[e >> 1]);
                    sacc[nt][e] = p;
                    rs[e >> 1] += p;
                }
            }
            #pragma unroll
            for (int i = 0; i < 2; ++i) {
                rs[i] += __shfl_xor_sync(0xffffffffu, rs[i], 1);
                rs[i] += __shfl_xor_sync(0xffffffffu, rs[i], 2);
            }
            l[0] = al0 * l[0] + rs[0];  m[0] = mn[0];
            l[1] = al1 * l[1] + rs[1];  m[1] = mn[1];
            #pragma unroll
            for (int nt = 0; nt < 8; ++nt) {
                oacc[nt][0] *= al0; oacc[nt][1] *= al0;
                oacc[nt][2] *= al1; oacc[nt][3] *= al1;
            }

            // ---- pack P (C-frag -> A-frag) with split ----
            unsigned pah[4][4], pal[4][4];
            #pragma unroll
            for (int s = 0; s < 4; ++s) {
                split_pack(sacc[2*s  ][0], sacc[2*s  ][1], pah[s][0], pal[s][0]);
                split_pack(sacc[2*s  ][2], sacc[2*s  ][3], pah[s][1], pal[s][1]);
                split_pack(sacc[2*s+1][0], sacc[2*s+1][1], pah[s][2], pal[s][2]);
                split_pack(sacc[2*s+1][2], sacc[2*s+1][3], pah[s][3], pal[s][3]);
            }

            // ---- O += P V (8-wide passes; 3-pass split) ----
            #pragma unroll
            for (int s = 0; s < 4; ++s) {
                const int ko = s * 16;
                unsigned vbh[8][2];
                #pragma unroll
                for (int p = 0; p < 4; ++p) {
                    const int nr = (p * 2 + b_nt) * 8 + lrow;
                    ldsm_x4(&vbh[p*2][0], sVh + (unsigned)(nr * RS2 + ko + b_kh * 8) * 2);
                }
                #pragma unroll
                for (int j = 0; j < 8; ++j) mma16816(oacc[j], pah[s], vbh[j]);
                #pragma unroll
                for (int j = 0; j < 8; ++j) mma16816(oacc[j], pal[s], vbh[j]);
                unsigned vbl[8][2];
                #pragma unroll
                for (int p = 0; p < 4; ++p) {
                    const int nr = (p * 2 + b_nt) * 8 + lrow;
                    ldsm_x4(&vbl[p*2][0], sVl + (unsigned)(nr * RS2 + ko + b_kh * 8) * 2);
                }
                #pragma unroll
                for (int j = 0; j < 8; ++j) mma16816(oacc[j], pah[s], vbl[j]);
            }
        }
        __syncthreads();
    }

    const int b = bh >> 4, h = bh & 15;
    #pragma unroll
    for (int i = 0; i < 2; ++i) {
        const int t = qbase + w * 16 + g + i * 8;
        const float inv = 1.f / l[i];
        const size_t base = ((size_t)(b * T_ + t)) * C_ + h * HD_;
        #pragma unroll
        for (int nt = 0; nt < 8; ++nt) {
            const float v0 = oacc[nt][i*2]     * inv;
            const float v1 = oacc[nt][i*2 + 1] * inv;
            unsigned hp, lp;
            split_pack(v0, v1, hp, lp);
            const int col = nt * 8 + 2 * q;
            *(unsigned*)(g_yhi + base + col) = hp;
            *(unsigned*)(g_ylo + base + col) = lp;
        }
    }
}

// ---------------------------------------------------------------------------
extern "C" void kernel_launch(void* const* d_in, const int* in_sizes, int n_in,
                              void* d_out, int out_size)
{
    const float* query = (const float*)d_in[0];
    const float* Wq = (const float*)d_in[1];  const float* bq = (const float*)d_in[2];
    const float* Wk = (const float*)d_in[3];  const float* bk = (const float*)d_in[4];
    const float* Wv = (const float*)d_in[5];  const float* bv = (const float*)d_in[6];
    const float* Wp = (const float*)d_in[7];  const float* bp = (const float*)d_in[8];

    __nv_bfloat16 *xhi, *xlo, *yhi, *ylo;
    __nv_bfloat16 *wqh, *wql, *wkh, *wkl, *wvh, *wvl, *wph, *wpl;
    cudaGetSymbolAddress((void**)&xhi, g_xhi); cudaGetSymbolAddress((void**)&xlo, g_xlo);
    cudaGetSymbolAddress((void**)&yhi, g_yhi); cudaGetSymbolAddress((void**)&ylo, g_ylo);
    cudaGetSymbolAddress((void**)&wqh, g_wqhi); cudaGetSymbolAddress((void**)&wql, g_wqlo);
    cudaGetSymbolAddress((void**)&wkh, g_wkhi); cudaGetSymbolAddress((void**)&wkl, g_wklo);
    cudaGetSymbolAddress((void**)&wvh, g_wvhi); cudaGetSymbolAddress((void**)&wvl, g_wvlo);
    cudaGetSymbolAddress((void**)&wph, g_wphi); cudaGetSymbolAddress((void**)&wpl, g_wplo);

    cudaFuncSetAttribute(proj_qkv, cudaFuncAttributeMaxDynamicSharedMemorySize, PROJ_SMEM);
    cudaFuncSetAttribute(proj_out, cudaFuncAttributeMaxDynamicSharedMemorySize, PROJ_SMEM);
    cudaFuncSetAttribute(attn_mma, cudaFuncAttributeMaxDynamicSharedMemorySize, ATTN_SMEM);

    // one fused split launch
    split_all_kernel<<<1184, 256>>>(
        (const float4*)query,
        (const float4*)Wq, (const float4*)Wk, (const float4*)Wv, (const float4*)Wp,
        (uint2*)xhi, (uint2*)xlo,
        (uint2*)wqh, (uint2*)wql, (uint2*)wkh, (uint2*)wkl,
        (uint2*)wvh, (uint2*)wvl, (uint2*)wph, (uint2*)wpl);

    // fused QKV projection (Q pre-scaled by 1/8)
    proj_qkv<<<dim3(24, M_/128), 256, PROJ_SMEM>>>(xhi, xlo, bq, bk, bv);

    // tensor-core flash attention
    attn_mma<<<dim3(T_/128, B_*H_), 256, ATTN_SMEM>>>();

    // output projection
    proj_out<<<dim3(C_/128, M_/128), 256, PROJ_SMEM>>>(yhi, ylo, bp, (float*)d_out);
}

// round 16
// speedup vs baseline: 7.2699x; 1.4002x over previous
#include <cuda_runtime.h>
#include <cuda_fp16.h>
#include <cstdint>

#define B_  4
#define T_  2048
#define C_  1024
#define H_  16
#define HD_ 64
#define M_  (B_*T_)   // 8192

// ---------------------------------------------------------------------------
// device scratch (fp16; A-operands split hi/lo, B-operands single)
// ---------------------------------------------------------------------------
__device__ __half g_xhi[(size_t)M_*C_], g_xlo[(size_t)M_*C_];
__device__ __half g_yhi[(size_t)M_*C_], g_ylo[(size_t)M_*C_];
__device__ __half g_qhi[(size_t)B_*H_*T_*HD_], g_qlo[(size_t)B_*H_*T_*HD_];
__device__ __half g_k [(size_t)B_*H_*T_*HD_];          // single
__device__ __half g_vt[(size_t)B_*H_*HD_*T_];          // single, [B,H,hd,T]
__device__ __half g_wq[(size_t)C_*C_], g_wk[(size_t)C_*C_];
__device__ __half g_wv[(size_t)C_*C_], g_wp[(size_t)C_*C_];

// ---------------------------------------------------------------------------
// helpers
// ---------------------------------------------------------------------------
__device__ __forceinline__ unsigned smem_u32(const void* p) {
    unsigned a;
    asm("{ .reg .u64 t; cvta.to.shared.u64 t, %1; cvt.u32.u64 %0, t; }"
        : "=r"(a) : "l"(p));
    return a;
}
__device__ __forceinline__ void cpa16(unsigned s, const void* g) {
    asm volatile("cp.async.cg.shared.global [%0], [%1], 16;" :: "r"(s), "l"(g));
}
__device__ __forceinline__ void cpa_commit() {
    asm volatile("cp.async.commit_group;" ::: "memory");
}
__device__ __forceinline__ void cpa_wait1() {
    asm volatile("cp.async.wait_group 1;" ::: "memory");
}
__device__ __forceinline__ void cpa_wait0() {
    asm volatile("cp.async.wait_group 0;" ::: "memory");
}
__device__ __forceinline__ void mma16816(float* d, const unsigned* a, const unsigned* b) {
    asm volatile(
        "mma.sync.aligned.m16n8k16.row.col.f32.f16.f16.f32 "
        "{%0,%1,%2,%3}, {%4,%5,%6,%7}, {%8,%9}, {%0,%1,%2,%3};"
        : "+f"(d[0]), "+f"(d[1]), "+f"(d[2]), "+f"(d[3])
        : "r"(a[0]), "r"(a[1]), "r"(a[2]), "r"(a[3]), "r"(b[0]), "r"(b[1]));
}
__device__ __forceinline__ void ldsm_x4(unsigned* r, unsigned saddr) {
    asm volatile("ldmatrix.sync.aligned.m8n8.x4.shared.b16 {%0,%1,%2,%3}, [%4];"
        : "=r"(r[0]), "=r"(r[1]), "=r"(r[2]), "=r"(r[3]) : "r"(saddr));
}
__device__ __forceinline__ unsigned pack_h(float p0, float p1) {
    __half2 h = __float22half2_rn(make_float2(p0, p1));
    return *reinterpret_cast<unsigned*>(&h);
}
__device__ __forceinline__ void split_pack_h(float p0, float p1,
                                             unsigned& hi, unsigned& lo) {
    __half2 h = __float22half2_rn(make_float2(p0, p1));
    hi = *reinterpret_cast<unsigned*>(&h);
    lo = pack_h(p0 - __half2float(__low2half(h)),
                p1 - __half2float(__high2half(h)));
}

// ---------------------------------------------------------------------------
// fused split: x -> (hi, lo) f16; 4 weight matrices -> single f16
// ---------------------------------------------------------------------------
__global__ __launch_bounds__(256) void split_all_kernel(
    const float4* __restrict__ sx,
    const float4* __restrict__ s0, const float4* __restrict__ s1,
    const float4* __restrict__ s2, const float4* __restrict__ s3,
    uint2* __restrict__ xh, uint2* __restrict__ xl,
    uint2* __restrict__ w0, uint2* __restrict__ w1,
    uint2* __restrict__ w2, uint2* __restrict__ w3)
{
    const int stride = gridDim.x * blockDim.x;
    const int nx = M_ * C_ / 4;
    for (int i = blockIdx.x * blockDim.x + threadIdx.x; i < nx; i += stride) {
        const float4 v = sx[i];
        unsigned a0, b0, a1, b1;
        split_pack_h(v.x, v.y, a0, b0);
        split_pack_h(v.z, v.w, a1, b1);
        xh[i] = make_uint2(a0, a1);
        xl[i] = make_uint2(b0, b1);
    }
    const int nw = C_ * C_ / 4;
    for (int i = blockIdx.x * blockDim.x + threadIdx.x; i < nw; i += stride) {
        #pragma unroll
        for (int a = 0; a < 4; ++a) {
            const float4* s = (a==0)?s0:(a==1)?s1:(a==2)?s2:s3;
            uint2* w = (a==0)?w0:(a==1)?w1:(a==2)?w2:w3;
            const float4 v = s[i];
            w[i] = make_uint2(pack_h(v.x, v.y), pack_h(v.z, v.w));
        }
    }
}

// ---------------------------------------------------------------------------
// Shared GEMM mainloop: A split f16 (2 arrays) x B single f16, 2 passes.
// ---------------------------------------------------------------------------
#define RS    40
#define ABYTES (128*RS*2)
#define BUFB  (3*ABYTES)               // 30720 per buffer (Ahi, Alo, B)
#define PROJ_SMEM (2*BUFB)             // 61440 (x2 CTAs = 120KB/SM)

__device__ __forceinline__ void gemm_mainloop(
    const __half* __restrict__ Ahi, const __half* __restrict__ Alo,
    const __half* __restrict__ Bw,
    int bm, int bn, unsigned sb, int tid, int lane,
    int wm, int wn, float acc[2][8][4])
{
    const int lrow = lane & 7;
    const int tsel = lane >> 3;
    const int b_nt = tsel >> 1, b_kh = tsel & 1;
    const int a_rh = tsel & 1,  a_kh = tsel >> 1;

    const __half* srcs[3] = {Ahi, Alo, Bw};

    auto load_chunk = [&](int k0, int buf) {
        const unsigned boff = (unsigned)buf * BUFB;
        #pragma unroll
        for (int it = 0; it < 6; ++it) {
            const int u   = it * 256 + tid;      // 0..1535
            const int arr = u >> 9;              // 0..2
            const int r   = (u >> 2) & 127;
            const int seg = u & 3;
            const int rowg = ((arr < 2) ? bm : bn) + r;
            const void* gp = (const char*)srcs[arr] + ((size_t)rowg * C_ + k0 + seg * 8) * 2;
            const unsigned sp = sb + boff + (unsigned)arr * ABYTES
                              + (unsigned)(r * RS + seg * 8) * 2;
            cpa16(sp, gp);
        }
        cpa_commit();
    };

    load_chunk(0, 0);

    for (int c = 0; c < 32; ++c) {
        if (c < 31) load_chunk((c + 1) * 32, (c + 1) & 1);
        if (c < 31) cpa_wait1(); else cpa_wait0();
        __syncthreads();

        const unsigned sAh = sb + (unsigned)(c & 1) * BUFB;
        const unsigned sAl = sAh + ABYTES;
        const unsigned sBw = sAh + 2 * ABYTES;

        #pragma unroll
        for (int ks = 0; ks < 2; ++ks) {
            const int ko = ks * 16;
            unsigned bw[8][2];
            #pragma unroll
            for (int nb = 0; nb < 4; ++nb) {
                const int nrow = wn * 64 + (nb * 2 + b_nt) * 8 + lrow;
                ldsm_x4(&bw[nb*2][0], sBw + (unsigned)(nrow * RS + ko + b_kh * 8) * 2);
            }
            #pragma unroll
            for (int mt = 0; mt < 2; ++mt) {
                const int arow = wm * 32 + mt * 16 + a_rh * 8 + lrow;
                unsigned ah[4], al[4];
                ldsm_x4(ah, sAh + (unsigned)(arow * RS + ko + a_kh * 8) * 2);
                ldsm_x4(al, sAl + (unsigned)(arow * RS + ko + a_kh * 8) * 2);
                #pragma unroll
                for (int nt = 0; nt < 8; ++nt) mma16816(acc[mt][nt], ah, bw[nt]);
                #pragma unroll
                for (int nt = 0; nt < 8; ++nt) mma16816(acc[mt][nt], al, bw[nt]);
            }
        }
        __syncthreads();
    }
}

// ---------------------------------------------------------------------------
// Fused QKV projection. Q split (pre-scaled 1/8), K single, V single transposed.
// ---------------------------------------------------------------------------
__global__ __launch_bounds__(256, 2) void proj_qkv(
    const __half* __restrict__ Xhi, const __half* __restrict__ Xlo,
    const float* __restrict__ bq, const float* __restrict__ bk,
    const float* __restrict__ bv)
{
    extern __shared__ char smc[];
    const int tid  = threadIdx.x;
    const int wid  = tid >> 5, lane = tid & 31;
    const int g    = lane >> 2, q = lane & 3;
    const int wm   = wid >> 1, wn = wid & 1;
    const int wsel = blockIdx.x >> 3;
    const int bn   = (blockIdx.x & 7) * 128;
    const int bm   = blockIdx.y * 128;
    const unsigned sb = smem_u32(smc);

    const __half* Bw = (wsel == 0) ? g_wq : (wsel == 1) ? g_wk : g_wv;
    const float* bias = (wsel == 0) ? bq : (wsel == 1) ? bk : bv;
    const float oscale = (wsel == 0) ? 0.125f : 1.0f;

    float acc[2][8][4] = {};
    gemm_mainloop(Xhi, Xlo, Bw, bm, bn, sb, tid, lane, wm, wn, acc);

    #pragma unroll
    for (int mt = 0; mt < 2; ++mt) {
        #pragma unroll
        for (int nt = 0; nt < 8; ++nt) {
            const int col = bn + wn * 64 + nt * 8 + q * 2;
            const float b0 = bias[col], b1 = bias[col + 1];
            #pragma unroll
            for (int hrow = 0; hrow < 2; ++hrow) {
                const int row = bm + wm * 32 + mt * 16 + g + hrow * 8;
                const float v0 = (acc[mt][nt][hrow * 2 + 0] + b0) * oscale;
                const float v1 = (acc[mt][nt][hrow * 2 + 1] + b1) * oscale;
                const int bb = row >> 11, t = row & 2047;
                const int hh = col >> 6,  d = col & 63;
                if (wsel == 0) {
                    unsigned hp, lp;
                    split_pack_h(v0, v1, hp, lp);
                    const size_t idx = (((size_t)(bb * H_ + hh)) * T_ + t) * HD_ + d;
                    *(unsigned*)(g_qhi + idx) = hp;
                    *(unsigned*)(g_qlo + idx) = lp;
                } else if (wsel == 1) {
                    const size_t idx = (((size_t)(bb * H_ + hh)) * T_ + t) * HD_ + d;
                    *(unsigned*)(g_k + idx) = pack_h(v0, v1);
                } else {
                    const size_t idx = (((size_t)(bb * H_ + hh)) * HD_ + d) * T_ + t;
                    g_vt[idx]      = __float2half_rn(v0);
                    g_vt[idx + T_] = __float2half_rn(v1);
                }
            }
        }
    }
}

// ---------------------------------------------------------------------------
// Output projection: y(split f16) @ Wp(single)^T + bp -> f32 out
// ---------------------------------------------------------------------------
__global__ __launch_bounds__(256, 2) void proj_out(
    const __half* __restrict__ Yhi, const __half* __restrict__ Ylo,
    const float* __restrict__ bias, float* __restrict__ outp)
{
    extern __shared__ char smc[];
    const int tid  = threadIdx.x;
    const int wid  = tid >> 5, lane = tid & 31;
    const int g    = lane >> 2, q = lane & 3;
    const int wm   = wid >> 1, wn = wid & 1;
    const int bn   = blockIdx.x * 128;
    const int bm   = blockIdx.y * 128;
    const unsigned sb = smem_u32(smc);

    float acc[2][8][4] = {};
    gemm_mainloop(Yhi, Ylo, g_wp, bm, bn, sb, tid, lane, wm, wn, acc);

    #pragma unroll
    for (int mt = 0; mt < 2; ++mt) {
        #pragma unroll
        for (int nt = 0; nt < 8; ++nt) {
            const int col = bn + wn * 64 + nt * 8 + q * 2;
            const float b0 = bias[col], b1 = bias[col + 1];
            #pragma unroll
            for (int hrow = 0; hrow < 2; ++hrow) {
                const int row = bm + wm * 32 + mt * 16 + g + hrow * 8;
                outp[(size_t)row * C_ + col]     = acc[mt][nt][hrow * 2 + 0] + b0;
                outp[(size_t)row * C_ + col + 1] = acc[mt][nt][hrow * 2 + 1] + b1;
            }
        }
    }
}

// ---------------------------------------------------------------------------
// Flash attention, f16: Q split x K single (2-pass), P split x V single (2-pass)
// ---------------------------------------------------------------------------
#define RS2   72
#define ARR2B (64*RS2*2)      // 9216
#define TBUF  (2*ARR2B)       // 18432 (K, V single)
#define ATTN_SMEM (2*TBUF)    // 36864  (x2 CTAs = 74KB/SM)

__global__ __launch_bounds__(256, 2) void attn_mma()
{
    extern __shared__ char smc[];
    const int tid = threadIdx.x;
    const int w = tid >> 5, lane = tid & 31;
    const int g = lane >> 2, q = lane & 3;
    const int lrow = lane & 7;
    const int tsel = lane >> 3;
    const int b_nt = tsel >> 1, b_kh = tsel & 1;
    const int blk = (int)gridDim.x - 1 - (int)blockIdx.x;   // heavy blocks first
    const int bh = blockIdx.y;
    const int qbase = blk * 128;
    const unsigned sb = smem_u32(smc);

    const __half* Qh = g_qhi + (size_t)bh * T_ * HD_ + (size_t)(qbase + w * 16) * HD_;
    const __half* Ql = g_qlo + (size_t)bh * T_ * HD_ + (size_t)(qbase + w * 16) * HD_;
    const __half* Kg = g_k  + (size_t)bh * T_ * HD_;
    const __half* Vg = g_vt + (size_t)bh * HD_ * T_;

    unsigned qh[4][4], ql[4][4];
    #pragma unroll
    for (int s = 0; s < 4; ++s) {
        const int c0 = s * 16 + 2 * q;
        qh[s][0] = *(const unsigned*)(Qh + (g    ) * HD_ + c0);
        qh[s][1] = *(const unsigned*)(Qh + (g + 8) * HD_ + c0);
        qh[s][2] = *(const unsigned*)(Qh + (g    ) * HD_ + c0 + 8);
        qh[s][3] = *(const unsigned*)(Qh + (g + 8) * HD_ + c0 + 8);
        ql[s][0] = *(const unsigned*)(Ql + (g    ) * HD_ + c0);
        ql[s][1] = *(const unsigned*)(Ql + (g + 8) * HD_ + c0);
        ql[s][2] = *(const unsigned*)(Ql + (g    ) * HD_ + c0 + 8);
        ql[s][3] = *(const unsigned*)(Ql + (g + 8) * HD_ + c0 + 8);
    }

    float oacc[8][4] = {};
    float m[2] = {-1e30f, -1e30f}, l[2] = {0.f, 0.f};

    auto load_tile = [&](int jt, int buf) {
        const int jb = jt * 64;
        const unsigned boff = (unsigned)buf * TBUF;
        #pragma unroll
        for (int it = 0; it < 4; ++it) {
            const int u = it * 256 + tid;        // 0..1023
            const int arr = u >> 9;              // 0: K, 1: V
            const int r   = (u >> 3) & 63;
            const int seg = u & 7;
            const void* gp = (arr == 0)
                ? (const void*)(Kg + ((size_t)(jb + r)) * HD_ + seg * 8)
                : (const void*)(Vg + ((size_t)r) * T_ + jb + seg * 8);
            const unsigned sp = sb + boff + (unsigned)arr * ARR2B
                              + (unsigned)(r * RS2 + seg * 8) * 2;
            cpa16(sp, gp);
        }
        cpa_commit();
    };

    const int ntiles = 2 * blk + 2;
    load_tile(0, 0);

    for (int jt = 0; jt < ntiles; ++jt) {
        if (jt < ntiles - 1) load_tile(jt + 1, (jt + 1) & 1);
        if (jt < ntiles - 1) cpa_wait1(); else cpa_wait0();
        __syncthreads();

        const int jb = jt * 64;
        if (jb <= qbase + w * 16 + 15) {
            const unsigned bufo = sb + (unsigned)(jt & 1) * TBUF;
            const unsigned sK = bufo, sV = bufo + ARR2B;

            // ---- S = Q K^T (Q split x K single, 2 passes) ----
            float sacc[8][4] = {};
            #pragma unroll
            for (int s = 0; s < 4; ++s) {
                const int ko = s * 16;
                unsigned kb[8][2];
                #pragma unroll
                for (int p = 0; p < 4; ++p) {
                    const int nr = (p * 2 + b_nt) * 8 + lrow;
                    ldsm_x4(&kb[p*2][0], sK + (unsigned)(nr * RS2 + ko + b_kh * 8) * 2);
                }
                #pragma unroll
                for (int j = 0; j < 8; ++j) mma16816(sacc[j], qh[s], kb[j]);
                #pragma unroll
                for (int j = 0; j < 8; ++j) mma16816(sacc[j], ql[s], kb[j]);
            }

            // ---- causal mask (diagonal tiles only; warp-uniform branch) ----
            if (jb + 63 > qbase + w * 16) {
                #pragma unroll
                for (int nt = 0; nt < 8; ++nt) {
                    #pragma unroll
                    for (int e = 0; e < 4; ++e) {
                        const int col = jb + nt * 8 + 2 * q + (e & 1);
                        const int row = qbase + w * 16 + g + (e >> 1) * 8;
                        if (col > row) sacc[nt][e] = -1e30f;
                    }
                }
            }

            // ---- online softmax ----
            float mn[2];
            #pragma unroll
            for (int i = 0; i < 2; ++i) {
                float rm = sacc[0][i*2];
                #pragma unroll
                for (int nt = 0; nt < 8; ++nt) {
                    rm = fmaxf(rm, sacc[nt][i*2]);
                    rm = fmaxf(rm, sacc[nt][i*2+1]);
                }
                rm = fmaxf(rm, __shfl_xor_sync(0xffffffffu, rm, 1));
                rm = fmaxf(rm, __shfl_xor_sync(0xffffffffu, rm, 2));
                mn[i] = fmaxf(m[i], rm);
            }
            const float al0 = __expf(m[0] - mn[0]);
            const float al1 = __expf(m[1] - mn[1]);
            float rs[2] = {0.f, 0.f};
            #pragma unroll
            for (int nt = 0; nt < 8; ++nt) {
                #pragma unroll
                for (int e = 0; e < 4; ++e) {
                    const float p = __expf(sacc[nt][e] - mn[e >> 1]);
                    sacc[nt][e] = p;
                    rs[e >> 1] += p;
                }
            }
            #pragma unroll
            for (int i = 0; i < 2; ++i) {
                rs[i] += __shfl_xor_sync(0xffffffffu, rs[i], 1);
                rs[i] += __shfl_xor_sync(0xffffffffu, rs[i], 2);
            }
            l[0] = al0 * l[0] + rs[0];  m[0] = mn[0];
            l[1] = al1 * l[1] + rs[1];  m[1] = mn[1];
            #pragma unroll
            for (int nt = 0; nt < 8; ++nt) {
                oacc[nt][0] *= al0; oacc[nt][1] *= al0;
                oacc[nt][2] *= al1; oacc[nt][3] *= al1;
            }

            // ---- pack P (C-frag -> A-frag) with f16 split ----
            unsigned pah[4][4], pal[4][4];
            #pragma unroll
            for (int s = 0; s < 4; ++s) {
                split_pack_h(sacc[2*s  ][0], sacc[2*s  ][1], pah[s][0], pal[s][0]);
                split_pack_h(sacc[2*s  ][2], sacc[2*s  ][3], pah[s][1], pal[s][1]);
                split_pack_h(sacc[2*s+1][0], sacc[2*s+1][1], pah[s][2], pal[s][2]);
                split_pack_h(sacc[2*s+1][2], sacc[2*s+1][3], pah[s][3], pal[s][3]);
            }

            // ---- O += P V (P split x V single, 2 passes) ----
            #pragma unroll
            for (int s = 0; s < 4; ++s) {
                const int ko = s * 16;
                unsigned vb[8][2];
                #pragma unroll
                for (int p = 0; p < 4; ++p) {
                    const int nr = (p * 2 + b_nt) * 8 + lrow;
                    ldsm_x4(&vb[p*2][0], sV + (unsigned)(nr * RS2 + ko + b_kh * 8) * 2);
                }
                #pragma unroll
                for (int j = 0; j < 8; ++j) mma16816(oacc[j], pah[s], vb[j]);
                #pragma unroll
                for (int j = 0; j < 8; ++j) mma16816(oacc[j], pal[s], vb[j]);
            }
        }
        __syncthreads();
    }

    const int b = bh >> 4, h = bh & 15;
    #pragma unroll
    for (int i = 0; i < 2; ++i) {
        const int t = qbase + w * 16 + g + i * 8;
        const float inv = 1.f / l[i];
        const size_t base = ((size_t)(b * T_ + t)) * C_ + h * HD_;
        #pragma unroll
        for (int nt = 0; nt < 8; ++nt) {
            const float v0 = oacc[nt][i*2]     * inv;
            const float v1 = oacc[nt][i*2 + 1] * inv;
            unsigned hp, lp;
            split_pack_h(v0, v1, hp, lp);
            const int col = nt * 8 + 2 * q;
            *(unsigned*)(g_yhi + base + col) = hp;
            *(unsigned*)(g_ylo + base + col) = lp;
        }
    }
}

// ---------------------------------------------------------------------------
extern "C" void kernel_launch(void* const* d_in, const int* in_sizes, int n_in,
                              void* d_out, int out_size)
{
    const float* query = (const float*)d_in[0];
    const float* Wq = (const float*)d_in[1];  const float* bq = (const float*)d_in[2];
    const float* Wk = (const float*)d_in[3];  const float* bk = (const float*)d_in[4];
    const float* Wv = (const float*)d_in[5];  const float* bv = (const float*)d_in[6];
    const float* Wp = (const float*)d_in[7];  const float* bp = (const float*)d_in[8];

    __half *xhi, *xlo, *yhi, *ylo, *wq, *wk, *wv, *wp;
    cudaGetSymbolAddress((void**)&xhi, g_xhi); cudaGetSymbolAddress((void**)&xlo, g_xlo);
    cudaGetSymbolAddress((void**)&yhi, g_yhi); cudaGetSymbolAddress((void**)&ylo, g_ylo);
    cudaGetSymbolAddress((void**)&wq, g_wq);   cudaGetSymbolAddress((void**)&wk, g_wk);
    cudaGetSymbolAddress((void**)&wv, g_wv);   cudaGetSymbolAddress((void**)&wp, g_wp);

    cudaFuncSetAttribute(proj_qkv, cudaFuncAttributeMaxDynamicSharedMemorySize, PROJ_SMEM);
    cudaFuncSetAttribute(proj_out, cudaFuncAttributeMaxDynamicSharedMemorySize, PROJ_SMEM);
    cudaFuncSetAttribute(attn_mma, cudaFuncAttributeMaxDynamicSharedMemorySize, ATTN_SMEM);

    // fused split (x hi/lo + 4 single-f16 weights)
    split_all_kernel<<<1184, 256>>>(
        (const float4*)query,
        (const float4*)Wq, (const float4*)Wk, (const float4*)Wv, (const float4*)Wp,
        (uint2*)xhi, (uint2*)xlo,
        (uint2*)wq, (uint2*)wk, (uint2*)wv, (uint2*)wp);

    // fused QKV projection (Q pre-scaled by 1/8)
    proj_qkv<<<dim3(24, M_/128), 256, PROJ_SMEM>>>(xhi, xlo, bq, bk, bv);

    // tensor-core flash attention
    attn_mma<<<dim3(T_/128, B_*H_), 256, ATTN_SMEM>>>();

    // output projection
    proj_out<<<dim3(C_/128, M_/128), 256, PROJ_SMEM>>>(yhi, ylo, bp, (float*)d_out);
}

// round 17
// speedup vs baseline: 12.0058x; 1.6514x over previous
#include <cuda_runtime.h>
#include <cuda_fp16.h>
#include <cstdint>

#define B_  4
#define T_  2048
#define C_  1024
#define H_  16
#define HD_ 64
#define M_  (B_*T_)   // 8192

// ---------------------------------------------------------------------------
// device scratch (single f16 everywhere)
// ---------------------------------------------------------------------------
__device__ __half g_x [(size_t)M_*C_];
__device__ __half g_y [(size_t)M_*C_];
__device__ __half g_q [(size_t)B_*H_*T_*HD_];
__device__ __half g_k [(size_t)B_*H_*T_*HD_];
__device__ __half g_vt[(size_t)B_*H_*HD_*T_];          // [B,H,hd,T]
__device__ __half g_wq[(size_t)C_*C_], g_wk[(size_t)C_*C_];
__device__ __half g_wv[(size_t)C_*C_], g_wp[(size_t)C_*C_];

// ---------------------------------------------------------------------------
// helpers
// ---------------------------------------------------------------------------
__device__ __forceinline__ unsigned smem_u32(const void* p) {
    unsigned a;
    asm("{ .reg .u64 t; cvta.to.shared.u64 t, %1; cvt.u32.u64 %0, t; }"
        : "=r"(a) : "l"(p));
    return a;
}
__device__ __forceinline__ void cpa16(unsigned s, const void* g) {
    asm volatile("cp.async.cg.shared.global [%0], [%1], 16;" :: "r"(s), "l"(g));
}
__device__ __forceinline__ void cpa_commit() {
    asm volatile("cp.async.commit_group;" ::: "memory");
}
__device__ __forceinline__ void cpa_wait1() {
    asm volatile("cp.async.wait_group 1;" ::: "memory");
}
__device__ __forceinline__ void cpa_wait0() {
    asm volatile("cp.async.wait_group 0;" ::: "memory");
}
__device__ __forceinline__ void mma16816(float* d, const unsigned* a, const unsigned* b) {
    asm volatile(
        "mma.sync.aligned.m16n8k16.row.col.f32.f16.f16.f32 "
        "{%0,%1,%2,%3}, {%4,%5,%6,%7}, {%8,%9}, {%0,%1,%2,%3};"
        : "+f"(d[0]), "+f"(d[1]), "+f"(d[2]), "+f"(d[3])
        : "r"(a[0]), "r"(a[1]), "r"(a[2]), "r"(a[3]), "r"(b[0]), "r"(b[1]));
}
__device__ __forceinline__ void ldsm_x4(unsigned* r, unsigned saddr) {
    asm volatile("ldmatrix.sync.aligned.m8n8.x4.shared.b16 {%0,%1,%2,%3}, [%4];"
        : "=r"(r[0]), "=r"(r[1]), "=r"(r[2]), "=r"(r[3]) : "r"(saddr));
}
__device__ __forceinline__ unsigned pack_h(float p0, float p1) {
    __half2 h = __float22half2_rn(make_float2(p0, p1));
    return *reinterpret_cast<unsigned*>(&h);
}

// ---------------------------------------------------------------------------
// fused convert: x + 4 weight matrices -> f16 (single)
// ---------------------------------------------------------------------------
__global__ __launch_bounds__(256) void conv_all_kernel(
    const float4* __restrict__ sx,
    const float4* __restrict__ s0, const float4* __restrict__ s1,
    const float4* __restrict__ s2, const float4* __restrict__ s3,
    uint2* __restrict__ xo,
    uint2* __restrict__ w0, uint2* __restrict__ w1,
    uint2* __restrict__ w2, uint2* __restrict__ w3)
{
    const int stride = gridDim.x * blockDim.x;
    const int nx = M_ * C_ / 4;
    for (int i = blockIdx.x * blockDim.x + threadIdx.x; i < nx; i += stride) {
        const float4 v = sx[i];
        xo[i] = make_uint2(pack_h(v.x, v.y), pack_h(v.z, v.w));
    }
    const int nw = C_ * C_ / 4;
    for (int i = blockIdx.x * blockDim.x + threadIdx.x; i < nw; i += stride) {
        #pragma unroll
        for (int a = 0; a < 4; ++a) {
            const float4* s = (a==0)?s0:(a==1)?s1:(a==2)?s2:s3;
            uint2* w = (a==0)?w0:(a==1)?w1:(a==2)?w2:w3;
            const float4 v = s[i];
            w[i] = make_uint2(pack_h(v.x, v.y), pack_h(v.z, v.w));
        }
    }
}

// ---------------------------------------------------------------------------
// Shared GEMM mainloop: single f16 A x single f16 B, 1 pass.
// ---------------------------------------------------------------------------
#define RS    40
#define ABYTES (128*RS*2)
#define BUFB  (2*ABYTES)               // 20480 per buffer (A, B)
#define PROJ_SMEM (2*BUFB)             // 40960 (x2 CTAs = 80KB/SM)

__device__ __forceinline__ void gemm_mainloop(
    const __half* __restrict__ Aa, const __half* __restrict__ Bw,
    int bm, int bn, unsigned sb, int tid, int lane,
    int wm, int wn, float acc[2][8][4])
{
    const int lrow = lane & 7;
    const int tsel = lane >> 3;
    const int b_nt = tsel >> 1, b_kh = tsel & 1;
    const int a_rh = tsel & 1,  a_kh = tsel >> 1;

    auto load_chunk = [&](int k0, int buf) {
        const unsigned boff = (unsigned)buf * BUFB;
        #pragma unroll
        for (int it = 0; it < 4; ++it) {
            const int u   = it * 256 + tid;      // 0..1023
            const int arr = u >> 9;              // 0: A, 1: B
            const int r   = (u >> 2) & 127;
            const int seg = u & 3;
            const int rowg = ((arr == 0) ? bm : bn) + r;
            const __half* src = (arr == 0) ? Aa : Bw;
            const void* gp = (const char*)src + ((size_t)rowg * C_ + k0 + seg * 8) * 2;
            const unsigned sp = sb + boff + (unsigned)arr * ABYTES
                              + (unsigned)(r * RS + seg * 8) * 2;
            cpa16(sp, gp);
        }
        cpa_commit();
    };

    load_chunk(0, 0);

    for (int c = 0; c < 32; ++c) {
        if (c < 31) load_chunk((c + 1) * 32, (c + 1) & 1);
        if (c < 31) cpa_wait1(); else cpa_wait0();
        __syncthreads();

        const unsigned sA = sb + (unsigned)(c & 1) * BUFB;
        const unsigned sB = sA + ABYTES;

        #pragma unroll
        for (int ks = 0; ks < 2; ++ks) {
            const int ko = ks * 16;
            unsigned bw[8][2];
            #pragma unroll
            for (int nb = 0; nb < 4; ++nb) {
                const int nrow = wn * 64 + (nb * 2 + b_nt) * 8 + lrow;
                ldsm_x4(&bw[nb*2][0], sB + (unsigned)(nrow * RS + ko + b_kh * 8) * 2);
            }
            #pragma unroll
            for (int mt = 0; mt < 2; ++mt) {
                const int arow = wm * 32 + mt * 16 + a_rh * 8 + lrow;
                unsigned af[4];
                ldsm_x4(af, sA + (unsigned)(arow * RS + ko + a_kh * 8) * 2);
                #pragma unroll
                for (int nt = 0; nt < 8; ++nt) mma16816(acc[mt][nt], af, bw[nt]);
            }
        }
        __syncthreads();
    }
}

// ---------------------------------------------------------------------------
// Fused QKV projection. Q pre-scaled 1/8; V transposed.
// ---------------------------------------------------------------------------
__global__ __launch_bounds__(256, 2) void proj_qkv(
    const __half* __restrict__ X,
    const float* __restrict__ bq, const float* __restrict__ bk,
    const float* __restrict__ bv)
{
    extern __shared__ char smc[];
    const int tid  = threadIdx.x;
    const int wid  = tid >> 5, lane = tid & 31;
    const int g    = lane >> 2, q = lane & 3;
    const int wm   = wid >> 1, wn = wid & 1;
    const int wsel = blockIdx.x >> 3;
    const int bn   = (blockIdx.x & 7) * 128;
    const int bm   = blockIdx.y * 128;
    const unsigned sb = smem_u32(smc);

    const __half* Bw = (wsel == 0) ? g_wq : (wsel == 1) ? g_wk : g_wv;
    const float* bias = (wsel == 0) ? bq : (wsel == 1) ? bk : bv;
    const float oscale = (wsel == 0) ? 0.125f : 1.0f;

    float acc[2][8][4] = {};
    gemm_mainloop(X, Bw, bm, bn, sb, tid, lane, wm, wn, acc);

    #pragma unroll
    for (int mt = 0; mt < 2; ++mt) {
        #pragma unroll
        for (int nt = 0; nt < 8; ++nt) {
            const int col = bn + wn * 64 + nt * 8 + q * 2;
            const float b0 = bias[col], b1 = bias[col + 1];
            #pragma unroll
            for (int hrow = 0; hrow < 2; ++hrow) {
                const int row = bm + wm * 32 + mt * 16 + g + hrow * 8;
                const float v0 = (acc[mt][nt][hrow * 2 + 0] + b0) * oscale;
                const float v1 = (acc[mt][nt][hrow * 2 + 1] + b1) * oscale;
                const int bb = row >> 11, t = row & 2047;
                const int hh = col >> 6,  d = col & 63;
                if (wsel < 2) {
                    const size_t idx = (((size_t)(bb * H_ + hh)) * T_ + t) * HD_ + d;
                    __half* dst = (wsel == 0) ? g_q : g_k;
                    *(unsigned*)(dst + idx) = pack_h(v0, v1);
                } else {
                    const size_t idx = (((size_t)(bb * H_ + hh)) * HD_ + d) * T_ + t;
                    g_vt[idx]      = __float2half_rn(v0);
                    g_vt[idx + T_] = __float2half_rn(v1);
                }
            }
        }
    }
}

// ---------------------------------------------------------------------------
// Output projection: y(f16) @ Wp(f16)^T + bp -> f32 out
// ---------------------------------------------------------------------------
__global__ __launch_bounds__(256, 2) void proj_out(
    const float* __restrict__ bias, float* __restrict__ outp)
{
    extern __shared__ char smc[];
    const int tid  = threadIdx.x;
    const int wid  = tid >> 5, lane = tid & 31;
    const int g    = lane >> 2, q = lane & 3;
    const int wm   = wid >> 1, wn = wid & 1;
    const int bn   = blockIdx.x * 128;
    const int bm   = blockIdx.y * 128;
    const unsigned sb = smem_u32(smc);

    float acc[2][8][4] = {};
    gemm_mainloop(g_y, g_wp, bm, bn, sb, tid, lane, wm, wn, acc);

    #pragma unroll
    for (int mt = 0; mt < 2; ++mt) {
        #pragma unroll
        for (int nt = 0; nt < 8; ++nt) {
            const int col = bn + wn * 64 + nt * 8 + q * 2;
            const float b0 = bias[col], b1 = bias[col + 1];
            #pragma unroll
            for (int hrow = 0; hrow < 2; ++hrow) {
                const int row = bm + wm * 32 + mt * 16 + g + hrow * 8;
                outp[(size_t)row * C_ + col]     = acc[mt][nt][hrow * 2 + 0] + b0;
                outp[(size_t)row * C_ + col + 1] = acc[mt][nt][hrow * 2 + 1] + b1;
            }
        }
    }
}

// ---------------------------------------------------------------------------
// Flash attention, single f16, 1-pass QK and PV.
// ---------------------------------------------------------------------------
#define RS2   72
#define ARR2B (64*RS2*2)      // 9216
#define TBUF  (2*ARR2B)       // 18432 (K, V)
#define ATTN_SMEM (2*TBUF)    // 36864  (x2 CTAs = 74KB/SM)

__global__ __launch_bounds__(256, 2) void attn_mma()
{
    extern __shared__ char smc[];
    const int tid = threadIdx.x;
    const int w = tid >> 5, lane = tid & 31;
    const int g = lane >> 2, q = lane & 3;
    const int lrow = lane & 7;
    const int tsel = lane >> 3;
    const int b_nt = tsel >> 1, b_kh = tsel & 1;
    const int blk = (int)gridDim.x - 1 - (int)blockIdx.x;   // heavy blocks first
    const int bh = blockIdx.y;
    const int qbase = blk * 128;
    const unsigned sb = smem_u32(smc);

    const __half* Qg = g_q  + (size_t)bh * T_ * HD_ + (size_t)(qbase + w * 16) * HD_;
    const __half* Kg = g_k  + (size_t)bh * T_ * HD_;
    const __half* Vg = g_vt + (size_t)bh * HD_ * T_;

    unsigned qf[4][4];
    #pragma unroll
    for (int s = 0; s < 4; ++s) {
        const int c0 = s * 16 + 2 * q;
        qf[s][0] = *(const unsigned*)(Qg + (g    ) * HD_ + c0);
        qf[s][1] = *(const unsigned*)(Qg + (g + 8) * HD_ + c0);
        qf[s][2] = *(const unsigned*)(Qg + (g    ) * HD_ + c0 + 8);
        qf[s][3] = *(const unsigned*)(Qg + (g + 8) * HD_ + c0 + 8);
    }

    float oacc[8][4] = {};
    float m[2] = {-1e30f, -1e30f}, l[2] = {0.f, 0.f};

    auto load_tile = [&](int jt, int buf) {
        const int jb = jt * 64;
        const unsigned boff = (unsigned)buf * TBUF;
        #pragma unroll
        for (int it = 0; it < 4; ++it) {
            const int u = it * 256 + tid;        // 0..1023
            const int arr = u >> 9;              // 0: K, 1: V
            const int r   = (u >> 3) & 63;
            const int seg = u & 7;
            const void* gp = (arr == 0)
                ? (const void*)(Kg + ((size_t)(jb + r)) * HD_ + seg * 8)
                : (const void*)(Vg + ((size_t)r) * T_ + jb + seg * 8);
            const unsigned sp = sb + boff + (unsigned)arr * ARR2B
                              + (unsigned)(r * RS2 + seg * 8) * 2;
            cpa16(sp, gp);
        }
        cpa_commit();
    };

    const int ntiles = 2 * blk + 2;
    load_tile(0, 0);

    for (int jt = 0; jt < ntiles; ++jt) {
        if (jt < ntiles - 1) load_tile(jt + 1, (jt + 1) & 1);
        if (jt < ntiles - 1) cpa_wait1(); else cpa_wait0();
        __syncthreads();

        const int jb = jt * 64;
        if (jb <= qbase + w * 16 + 15) {
            const unsigned bufo = sb + (unsigned)(jt & 1) * TBUF;
            const unsigned sK = bufo, sV = bufo + ARR2B;

            // ---- S = Q K^T (1 pass) ----
            float sacc[8][4] = {};
            #pragma unroll
            for (int s = 0; s < 4; ++s) {
                const int ko = s * 16;
                unsigned kb[8][2];
                #pragma unroll
                for (int p = 0; p < 4; ++p) {
                    const int nr = (p * 2 + b_nt) * 8 + lrow;
                    ldsm_x4(&kb[p*2][0], sK + (unsigned)(nr * RS2 + ko + b_kh * 8) * 2);
                }
                #pragma unroll
                for (int j = 0; j < 8; ++j) mma16816(sacc[j], qf[s], kb[j]);
            }

            // ---- causal mask (diagonal tiles only; warp-uniform branch) ----
            if (jb + 63 > qbase + w * 16) {
                #pragma unroll
                for (int nt = 0; nt < 8; ++nt) {
                    #pragma unroll
                    for (int e = 0; e < 4; ++e) {
                        const int col = jb + nt * 8 + 2 * q + (e & 1);
                        const int row = qbase + w * 16 + g + (e >> 1) * 8;
                        if (col > row) sacc[nt][e] = -1e30f;
                    }
                }
            }

            // ---- online softmax ----
            float mn[2];
            #pragma unroll
            for (int i = 0; i < 2; ++i) {
                float rm = sacc[0][i*2];
                #pragma unroll
                for (int nt = 0; nt < 8; ++nt) {
                    rm = fmaxf(rm, sacc[nt][i*2]);
                    rm = fmaxf(rm, sacc[nt][i*2+1]);
                }
                rm = fmaxf(rm, __shfl_xor_sync(0xffffffffu, rm, 1));
                rm = fmaxf(rm, __shfl_xor_sync(0xffffffffu, rm, 2));
                mn[i] = fmaxf(m[i], rm);
            }
            const float al0 = __expf(m[0] - mn[0]);
            const float al1 = __expf(m[1] - mn[1]);
            float rs[2] = {0.f, 0.f};
            #pragma unroll
            for (int nt = 0; nt < 8; ++nt) {
                #pragma unroll
                for (int e = 0; e < 4; ++e) {
                    const float p = __expf(sacc[nt][e] - mn[e >> 1]);
                    sacc[nt][e] = p;
                    rs[e >> 1] += p;
                }
            }
            #pragma unroll
            for (int i = 0; i < 2; ++i) {
                rs[i] += __shfl_xor_sync(0xffffffffu, rs[i], 1);
                rs[i] += __shfl_xor_sync(0xffffffffu, rs[i], 2);
            }
            l[0] = al0 * l[0] + rs[0];  m[0] = mn[0];
            l[1] = al1 * l[1] + rs[1];  m[1] = mn[1];
            #pragma unroll
            for (int nt = 0; nt < 8; ++nt) {
                oacc[nt][0] *= al0; oacc[nt][1] *= al0;
                oacc[nt][2] *= al1; oacc[nt][3] *= al1;
            }

            // ---- pack P (C-frag -> A-frag), single f16 ----
            unsigned pp[4][4];
            #pragma unroll
            for (int s = 0; s < 4; ++s) {
                pp[s][0] = pack_h(sacc[2*s  ][0], sacc[2*s  ][1]);
                pp[s][1] = pack_h(sacc[2*s  ][2], sacc[2*s  ][3]);
                pp[s][2] = pack_h(sacc[2*s+1][0], sacc[2*s+1][1]);
                pp[s][3] = pack_h(sacc[2*s+1][2], sacc[2*s+1][3]);
            }

            // ---- O += P V (1 pass) ----
            #pragma unroll
            for (int s = 0; s < 4; ++s) {
                const int ko = s * 16;
                unsigned vb[8][2];
                #pragma unroll
                for (int p = 0; p < 4; ++p) {
                    const int nr = (p * 2 + b_nt) * 8 + lrow;
                    ldsm_x4(&vb[p*2][0], sV + (unsigned)(nr * RS2 + ko + b_kh * 8) * 2);
                }
                #pragma unroll
                for (int j = 0; j < 8; ++j) mma16816(oacc[j], pp[s], vb[j]);
            }
        }
        __syncthreads();
    }

    const int b = bh >> 4, h = bh & 15;
    #pragma unroll
    for (int i = 0; i < 2; ++i) {
        const int t = qbase + w * 16 + g + i * 8;
        const float inv = 1.f / l[i];
        const size_t base = ((size_t)(b * T_ + t)) * C_ + h * HD_;
        #pragma unroll
        for (int nt = 0; nt < 8; ++nt) {
            const float v0 = oacc[nt][i*2]     * inv;
            const float v1 = oacc[nt][i*2 + 1] * inv;
            const int col = nt * 8 + 2 * q;
            *(unsigned*)(g_y + base + col) = pack_h(v0, v1);
        }
    }
}

// ---------------------------------------------------------------------------
extern "C" void kernel_launch(void* const* d_in, const int* in_sizes, int n_in,
                              void* d_out, int out_size)
{
    const float* query = (const float*)d_in[0];
    const float* Wq = (const float*)d_in[1];  const float* bq = (const float*)d_in[2];
    const float* Wk = (const float*)d_in[3];  const float* bk = (const float*)d_in[4];
    const float* Wv = (const float*)d_in[5];  const float* bv = (const float*)d_in[6];
    const float* Wp = (const float*)d_in[7];  const float* bp = (const float*)d_in[8];

    __half *x, *wq, *wk, *wv, *wp;
    cudaGetSymbolAddress((void**)&x, g_x);
    cudaGetSymbolAddress((void**)&wq, g_wq);   cudaGetSymbolAddress((void**)&wk, g_wk);
    cudaGetSymbolAddress((void**)&wv, g_wv);   cudaGetSymbolAddress((void**)&wp, g_wp);

    cudaFuncSetAttribute(proj_qkv, cudaFuncAttributeMaxDynamicSharedMemorySize, PROJ_SMEM);
    cudaFuncSetAttribute(proj_out, cudaFuncAttributeMaxDynamicSharedMemorySize, PROJ_SMEM);
    cudaFuncSetAttribute(attn_mma, cudaFuncAttributeMaxDynamicSharedMemorySize, ATTN_SMEM);

    // fused f16 convert
    conv_all_kernel<<<1184, 256>>>(
        (const float4*)query,
        (const float4*)Wq, (const float4*)Wk, (const float4*)Wv, (const float4*)Wp,
        (uint2*)x, (uint2*)wq, (uint2*)wk, (uint2*)wv, (uint2*)wp);

    // fused QKV projection (Q pre-scaled by 1/8)
    proj_qkv<<<dim3(24, M_/128), 256, PROJ_SMEM>>>(x, bq, bk, bv);

    // tensor-core flash attention
    attn_mma<<<dim3(T_/128, B_*H_), 256, ATTN_SMEM>>>();

    // output projection
    proj_out<<<dim3(C_/128, M_/128), 256, PROJ_SMEM>>>(bp, (float*)d_out);
}